// round 1
// baseline (speedup 1.0000x reference)
#include <cuda_runtime.h>
#include <math.h>

#define NPATHS 15
#define CG_TOTAL 615
#define GEO_TOTAL 51

// path tables: (l1,l2,l3) enumerated as in the reference (l1 outer, l2 mid, l3 inner)
__device__ constexpr int PL1[NPATHS]  = {0,0,0,1,1,1,1,1,1,2,2,2,2,2,2};
__device__ constexpr int PL2[NPATHS]  = {0,1,2,0,1,1,1,2,2,0,1,1,2,2,2};
__device__ constexpr int PL3[NPATHS]  = {0,1,2,1,0,1,2,1,2,2,1,2,0,1,2};
__device__ constexpr int CGO[NPATHS]  = {0,1,10,35,44,53,80,125,170,245,270,315,390,415,490};
__device__ constexpr int GEOO[NPATHS] = {0,1,4,9,12,13,16,21,24,29,34,37,42,43,46};
__device__ constexpr int LOFF[3] = {0,1,4};

__device__ float g_cg[CG_TOTAL];
__device__ float g_Ai[65536 * 8];

// ---------------------------------------------------------------------------
// CG init: replicate the reference complex-basis construction in double.
// ---------------------------------------------------------------------------
__device__ double dfact(int n) {
    double r = 1.0;
    for (int i = 2; i <= n; ++i) r *= (double)i;
    return r;
}

__device__ double cgc(int j1, int j2, int j3, int m1, int m2, int m3) {
    if (m1 + m2 != m3) return 0.0;
    double pre = sqrt((double)(2 * j3 + 1) * dfact(j3 + j1 - j2) * dfact(j3 - j1 + j2) *
                      dfact(j1 + j2 - j3) / dfact(j1 + j2 + j3 + 1));
    pre *= sqrt(dfact(j3 + m3) * dfact(j3 - m3) * dfact(j1 - m1) * dfact(j1 + m1) *
                dfact(j2 - m2) * dfact(j2 + m2));
    double s = 0.0;
    for (int k = 0; k <= j1 + j2 - j3; ++k) {
        int d1 = j1 + j2 - j3 - k, d2 = j1 - m1 - k, d3 = j2 + m2 - k;
        int d4 = j3 - j2 + m1 + k, d5 = j3 - j1 - m2 + k;
        if (d1 < 0 || d2 < 0 || d3 < 0 || d4 < 0 || d5 < 0) continue;
        double t = 1.0 / (dfact(k) * dfact(d1) * dfact(d2) * dfact(d3) * dfact(d4) * dfact(d5));
        s += (k & 1) ? -t : t;
    }
    return pre * s;
}

__device__ void buildq(int l, double qr[5][5], double qi[5][5]) {
    for (int a = 0; a < 5; a++)
        for (int b = 0; b < 5; b++) { qr[a][b] = 0.0; qi[a][b] = 0.0; }
    const double isq = sqrt(0.5);
    for (int m = -l; m < 0; m++) {
        qr[l + m][l - m] = isq;       // q[l+m, l+|m|] = 2^-0.5
        qi[l + m][l + m] = -isq;      // q[l+m, l-|m|] = -1j*2^-0.5
    }
    qr[l][l] = 1.0;
    for (int m = 1; m <= l; m++) {
        double sg = (m & 1) ? -1.0 : 1.0;
        qr[l + m][l + m] = sg * isq;  // (-1)^m * 2^-0.5
        qi[l + m][l - m] = sg * isq;  // 1j*(-1)^m * 2^-0.5
    }
    // multiply by (-i)^l
    if (l == 1) {
        for (int a = 0; a < 5; a++)
            for (int b = 0; b < 5; b++) {
                double r = qr[a][b], i0 = qi[a][b];
                qr[a][b] = i0;   // (r + i*im)*(-i) = im - i*r
                qi[a][b] = -r;
            }
    } else if (l == 2) {
        for (int a = 0; a < 5; a++)
            for (int b = 0; b < 5; b++) { qr[a][b] = -qr[a][b]; qi[a][b] = -qi[a][b]; }
    }
}

__global__ void init_cg_kernel() {
    int p = threadIdx.x;
    if (p >= NPATHS) return;
    int l1 = PL1[p], l2 = PL2[p], l3 = PL3[p];
    double q1r[5][5], q1i[5][5], q2r[5][5], q2i[5][5], q3r[5][5], q3i[5][5];
    buildq(l1, q1r, q1i);
    buildq(l2, q2r, q2i);
    buildq(l3, q3r, q3i);
    int n1 = 2 * l1 + 1, n2 = 2 * l2 + 1, n3 = 2 * l3 + 1;
    double bufr[125], bufi[125];
    double sr = 0.0, si = 0.0;
    for (int i = 0; i < n1; i++)
        for (int j = 0; j < n2; j++)
            for (int k = 0; k < n3; k++) {
                double ar = 0.0, ai = 0.0;
                for (int a = 0; a < n1; a++)
                    for (int b = 0; b < n2; b++) {
                        double t12r = q1r[a][i] * q2r[b][j] - q1i[a][i] * q2i[b][j];
                        double t12i = q1r[a][i] * q2i[b][j] + q1i[a][i] * q2r[b][j];
                        if (t12r == 0.0 && t12i == 0.0) continue;
                        for (int c = 0; c < n3; c++) {
                            double C = cgc(l1, l2, l3, a - l1, b - l2, c - l3);
                            if (C == 0.0) continue;
                            double t3r = q3r[c][k], t3i = -q3i[c][k];  // conj
                            ar += (t12r * t3r - t12i * t3i) * C;
                            ai += (t12r * t3i + t12i * t3r) * C;
                        }
                    }
                int idx = (i * n2 + j) * n3 + k;
                bufr[idx] = ar;
                bufi[idx] = ai;
                sr += fabs(ar);
                si += fabs(ai);
            }
    int base = CGO[p];
    bool useRe = (sr >= si);
    int tot = n1 * n2 * n3;
    for (int idx = 0; idx < tot; idx++)
        g_cg[base + idx] = (float)(useRe ? bufr[idx] : bufi[idx]);
}

// ---------------------------------------------------------------------------
// Node kernel: Ai = silu(emb_table[A] @ mlp_w1 + b1) @ mlp_w2 + b2
// ---------------------------------------------------------------------------
__global__ void __launch_bounds__(256) node_kernel(
    const float* __restrict__ emb_table, const int* __restrict__ A,
    const float* __restrict__ w1, const float* __restrict__ b1,
    const float* __restrict__ w2, const float* __restrict__ b2, int N)
{
    __shared__ float sW1[16 * 64], sB1[64], sW2[64 * 8], sB2[8], sEmb[10 * 16];
    int tid = threadIdx.x, bs = blockDim.x;
    for (int i = tid; i < 16 * 64; i += bs) sW1[i] = w1[i];
    for (int i = tid; i < 64; i += bs) sB1[i] = b1[i];
    for (int i = tid; i < 64 * 8; i += bs) sW2[i] = w2[i];
    for (int i = tid; i < 8; i += bs) sB2[i] = b2[i];
    for (int i = tid; i < 10 * 16; i += bs) sEmb[i] = emb_table[i];
    __syncthreads();

    int n = blockIdx.x * bs + tid;
    if (n >= N) return;
    int a = A[n];
    float x[16];
#pragma unroll
    for (int i = 0; i < 16; i++) x[i] = sEmb[a * 16 + i];
    float h[64];
#pragma unroll
    for (int j = 0; j < 64; j++) {
        float t = sB1[j];
#pragma unroll
        for (int i = 0; i < 16; i++) t += x[i] * sW1[i * 64 + j];
        h[j] = t / (1.0f + __expf(-t));
    }
#pragma unroll
    for (int o = 0; o < 8; o++) {
        float t = sB2[o];
#pragma unroll
        for (int j = 0; j < 64; j++) t += h[j] * sW2[j * 8 + o];
        g_Ai[n * 8 + o] = t;
    }
}

// ---------------------------------------------------------------------------
// Edge kernel: one thread per edge, full pipeline + 144 atomic adds
// ---------------------------------------------------------------------------
__global__ void __launch_bounds__(256) edge_kernel(
    const float* __restrict__ pos, const int* __restrict__ batch,
    const int* __restrict__ esrc, const int* __restrict__ edst,
    const float* __restrict__ eshift, const float* __restrict__ cell,
    const float* __restrict__ fw1, const float* __restrict__ fb1,
    const float* __restrict__ fw2, const float* __restrict__ fb2,
    const float* __restrict__ fw3, const float* __restrict__ fb3,
    const float* __restrict__ tpw,
    float* __restrict__ out, int E, float inv_avg)
{
    __shared__ float sW1[8 * 64], sB1[64], sW2[64 * 64], sB2[64];
    __shared__ float sW3[64 * NPATHS], sB3[NPATHS], sTP[NPATHS * 8 * 16], sCG[CG_TOTAL];
    int tid = threadIdx.x, bs = blockDim.x;
    for (int i = tid; i < 8 * 64; i += bs) sW1[i] = fw1[i];
    for (int i = tid; i < 64; i += bs) { sB1[i] = fb1[i]; sB2[i] = fb2[i]; }
    for (int i = tid; i < 64 * 64; i += bs) sW2[i] = fw2[i];
    for (int i = tid; i < 64 * NPATHS; i += bs) sW3[i] = fw3[i];
    for (int i = tid; i < NPATHS; i += bs) sB3[i] = fb3[i];
    for (int i = tid; i < NPATHS * 8 * 16; i += bs) sTP[i] = tpw[i];
    for (int i = tid; i < CG_TOTAL; i += bs) sCG[i] = g_cg[i];
    __syncthreads();

    int e = blockIdx.x * bs + tid;
    if (e >= E) return;

    int s = esrc[e], d = edst[e];
    int b = batch[s];
    const float* cl = cell + b * 9;
    float sx = eshift[e * 3 + 0], sy = eshift[e * 3 + 1], sz = eshift[e * 3 + 2];
    float shx = sx * cl[0] + sy * cl[3] + sz * cl[6];
    float shy = sx * cl[1] + sy * cl[4] + sz * cl[7];
    float shz = sx * cl[2] + sy * cl[5] + sz * cl[8];
    float vx = pos[d * 3 + 0] - pos[s * 3 + 0] + shx;
    float vy = pos[d * 3 + 1] - pos[s * 3 + 1] + shy;
    float vz = pos[d * 3 + 2] - pos[s * 3 + 2] + shz;
    float len = sqrtf(vx * vx + vy * vy + vz * vz);
    float il = 1.0f / fmaxf(len, 1e-8f);
    float nx = vx * il, ny = vy * il, nz = vz * il;

    // spherical harmonics, m = -l..l per l
    float Yv[9];
    const float s3 = 1.7320508075688772f;
    const float s15 = 3.872983346207417f;
    const float s5 = 2.23606797749979f;
    Yv[0] = 1.0f;
    Yv[1] = s3 * ny; Yv[2] = s3 * nz; Yv[3] = s3 * nx;
    Yv[4] = s15 * nx * ny;
    Yv[5] = s15 * ny * nz;
    Yv[6] = 0.5f * s5 * (3.0f * nz * nz - 1.0f);
    Yv[7] = s15 * nx * nz;
    Yv[8] = 0.5f * s15 * (nx * nx - ny * ny);

    // radial basis (soft one-hot * sqrt(8))
    float emb[8];
    const float step = 2.0f / 9.0f;
    const float istep = 4.5f;
    const float cemb = 2.8284271247461903f / 1.12f;
#pragma unroll
    for (int i = 0; i < 8; i++) {
        float t = (len - (float)(i + 1) * step) * istep;
        emb[i] = __expf(-t * t) * cemb;
    }

    // MLP 8 -> 64 -> 64 -> 15
    float h[64];
#pragma unroll
    for (int j = 0; j < 64; j++) {
        float t = sB1[j];
#pragma unroll
        for (int i = 0; i < 8; i++) t += emb[i] * sW1[i * 64 + j];
        h[j] = t / (1.0f + __expf(-t));
    }
    float h2[64];
#pragma unroll
    for (int j = 0; j < 64; j++) {
        float t = sB2[j];
#pragma unroll
        for (int i = 0; i < 64; i++) t += h[i] * sW2[i * 64 + j];
        h2[j] = t / (1.0f + __expf(-t));
    }
    const float ALP0 = 0.20412414523193154f;  // 1/sqrt(8*3)
    const float ALP1 = 0.14433756729740643f;  // 1/sqrt(8*6)
    float gp[NPATHS];
#pragma unroll
    for (int p = 0; p < NPATHS; p++) {
        float t = sB3[p];
#pragma unroll
        for (int j = 0; j < 64; j++) t += h2[j] * sW3[j * NPATHS + p];
        float alpha = (PL3[p] == 0) ? ALP0 : ALP1;
        gp[p] = t * alpha * inv_avg;
    }

    // geometry contraction per path
    float geo[GEO_TOTAL];
#pragma unroll
    for (int p = 0; p < NPATHS; p++) {
        const int l1 = PL1[p], l2 = PL2[p], l3 = PL3[p];
        const int o1 = LOFF[l1], o2 = LOFF[l2];
        const int n2d = 2 * l2 + 1, n3d = 2 * l3 + 1;
#pragma unroll
        for (int k = 0; k < 2 * l3 + 1; k++) {
            float acc = 0.0f;
#pragma unroll
            for (int m = 0; m < 2 * l1 + 1; m++) {
#pragma unroll
                for (int n = 0; n < 2 * l2 + 1; n++) {
                    acc += Yv[o1 + m] * Yv[o2 + n] * sCG[CGO[p] + (m * n2d + n) * n3d + k];
                }
            }
            geo[GEOO[p] + k] = acc;
        }
    }

    // channel mixing + scatter
    float Ai[8];
#pragma unroll
    for (int m = 0; m < 8; m++) Ai[m] = g_Ai[s * 8 + m];

    float* orow = out + (size_t)d * 144;
    for (int c = 0; c < 16; c++) {
        float a0 = 0.0f;
        float a10 = 0.0f, a11 = 0.0f, a12 = 0.0f;
        float a20 = 0.0f, a21 = 0.0f, a22 = 0.0f, a23 = 0.0f, a24 = 0.0f;
#pragma unroll
        for (int p = 0; p < NPATHS; p++) {
            float cw = 0.0f;
#pragma unroll
            for (int m = 0; m < 8; m++) cw += Ai[m] * sTP[(p * 8 + m) * 16 + c];
            cw *= gp[p];
            if (PL3[p] == 0) {
                a0 += cw * geo[GEOO[p]];
            } else if (PL3[p] == 1) {
                a10 += cw * geo[GEOO[p] + 0];
                a11 += cw * geo[GEOO[p] + 1];
                a12 += cw * geo[GEOO[p] + 2];
            } else {
                a20 += cw * geo[GEOO[p] + 0];
                a21 += cw * geo[GEOO[p] + 1];
                a22 += cw * geo[GEOO[p] + 2];
                a23 += cw * geo[GEOO[p] + 3];
                a24 += cw * geo[GEOO[p] + 4];
            }
        }
        atomicAdd(orow + c, a0);
        atomicAdd(orow + 16 + 3 * c + 0, a10);
        atomicAdd(orow + 16 + 3 * c + 1, a11);
        atomicAdd(orow + 16 + 3 * c + 2, a12);
        atomicAdd(orow + 64 + 5 * c + 0, a20);
        atomicAdd(orow + 64 + 5 * c + 1, a21);
        atomicAdd(orow + 64 + 5 * c + 2, a22);
        atomicAdd(orow + 64 + 5 * c + 3, a23);
        atomicAdd(orow + 64 + 5 * c + 4, a24);
    }
}

// ---------------------------------------------------------------------------
extern "C" void kernel_launch(void* const* d_in, const int* in_sizes, int n_in,
                              void* d_out, int out_size)
{
    const float* pos    = (const float*)d_in[0];
    const int*   A      = (const int*)d_in[1];
    const int*   batch  = (const int*)d_in[2];
    const int*   esrc   = (const int*)d_in[3];
    const int*   edst   = (const int*)d_in[4];
    const float* eshift = (const float*)d_in[5];
    const float* cell   = (const float*)d_in[6];
    const float* embt   = (const float*)d_in[7];
    const float* mw1    = (const float*)d_in[8];
    const float* mb1    = (const float*)d_in[9];
    const float* mw2    = (const float*)d_in[10];
    const float* mb2    = (const float*)d_in[11];
    const float* fw1    = (const float*)d_in[12];
    const float* fb1    = (const float*)d_in[13];
    const float* fw2    = (const float*)d_in[14];
    const float* fb2    = (const float*)d_in[15];
    const float* fw3    = (const float*)d_in[16];
    const float* fb3    = (const float*)d_in[17];
    const float* tpw    = (const float*)d_in[18];
    float* out = (float*)d_out;

    int N = in_sizes[1];
    int E = in_sizes[3];
    float avg = (float)E / (float)N;
    float inv_avg = 1.0f / fmaxf(avg, 1e-8f);

    cudaMemsetAsync(d_out, 0, (size_t)out_size * sizeof(float));
    init_cg_kernel<<<1, 32>>>();
    node_kernel<<<(N + 255) / 256, 256>>>(embt, A, mw1, mb1, mw2, mb2, N);
    edge_kernel<<<(E + 255) / 256, 256>>>(pos, batch, esrc, edst, eshift, cell,
                                          fw1, fb1, fw2, fb2, fw3, fb3, tpw,
                                          out, E, inv_avg);
}

// round 2
// speedup vs baseline: 1.1040x; 1.1040x over previous
#include <cuda_runtime.h>
#include <math.h>

#define NPATHS 15
#define CG_TOTAL 615
#define GEO_TOTAL 51
#define MAXE 1000000
#define MAXN 50048

// path tables: (l1,l2,l3) enumerated as in the reference (l1 outer, l2 mid, l3 inner)
__device__ constexpr int PL1[NPATHS]  = {0,0,0,1,1,1,1,1,1,2,2,2,2,2,2};
__device__ constexpr int PL2[NPATHS]  = {0,1,2,0,1,1,1,2,2,0,1,1,2,2,2};
__device__ constexpr int PL3[NPATHS]  = {0,1,2,1,0,1,2,1,2,2,1,2,0,1,2};
__device__ constexpr int CGO[NPATHS]  = {0,1,10,35,44,53,80,125,170,245,270,315,390,415,490};
__device__ constexpr int GEOO[NPATHS] = {0,1,4,9,12,13,16,21,24,29,34,37,42,43,46};
__device__ constexpr int LOFF[3] = {0,1,4};

__device__ float g_cg[CG_TOTAL];
__device__ float g_chan[MAXN * 256];            // [node][c(16)][p(pad 16)]
__device__ float g_geoS[GEO_TOTAL * MAXE];      // [j][e]  (gates folded in)

// ---------------------------------------------------------------------------
// CG init: replicate the reference complex-basis construction in double.
// ---------------------------------------------------------------------------
__device__ double dfact(int n) {
    double r = 1.0;
    for (int i = 2; i <= n; ++i) r *= (double)i;
    return r;
}

__device__ double cgc(int j1, int j2, int j3, int m1, int m2, int m3) {
    if (m1 + m2 != m3) return 0.0;
    double pre = sqrt((double)(2 * j3 + 1) * dfact(j3 + j1 - j2) * dfact(j3 - j1 + j2) *
                      dfact(j1 + j2 - j3) / dfact(j1 + j2 + j3 + 1));
    pre *= sqrt(dfact(j3 + m3) * dfact(j3 - m3) * dfact(j1 - m1) * dfact(j1 + m1) *
                dfact(j2 - m2) * dfact(j2 + m2));
    double s = 0.0;
    for (int k = 0; k <= j1 + j2 - j3; ++k) {
        int d1 = j1 + j2 - j3 - k, d2 = j1 - m1 - k, d3 = j2 + m2 - k;
        int d4 = j3 - j2 + m1 + k, d5 = j3 - j1 - m2 + k;
        if (d1 < 0 || d2 < 0 || d3 < 0 || d4 < 0 || d5 < 0) continue;
        double t = 1.0 / (dfact(k) * dfact(d1) * dfact(d2) * dfact(d3) * dfact(d4) * dfact(d5));
        s += (k & 1) ? -t : t;
    }
    return pre * s;
}

__device__ void buildq(int l, double qr[5][5], double qi[5][5]) {
    for (int a = 0; a < 5; a++)
        for (int b = 0; b < 5; b++) { qr[a][b] = 0.0; qi[a][b] = 0.0; }
    const double isq = sqrt(0.5);
    for (int m = -l; m < 0; m++) {
        qr[l + m][l - m] = isq;
        qi[l + m][l + m] = -isq;
    }
    qr[l][l] = 1.0;
    for (int m = 1; m <= l; m++) {
        double sg = (m & 1) ? -1.0 : 1.0;
        qr[l + m][l + m] = sg * isq;
        qi[l + m][l - m] = sg * isq;
    }
    if (l == 1) {
        for (int a = 0; a < 5; a++)
            for (int b = 0; b < 5; b++) {
                double r = qr[a][b], i0 = qi[a][b];
                qr[a][b] = i0;
                qi[a][b] = -r;
            }
    } else if (l == 2) {
        for (int a = 0; a < 5; a++)
            for (int b = 0; b < 5; b++) { qr[a][b] = -qr[a][b]; qi[a][b] = -qi[a][b]; }
    }
}

__global__ void init_cg_kernel() {
    int p = threadIdx.x;
    if (p >= NPATHS) return;
    int l1 = PL1[p], l2 = PL2[p], l3 = PL3[p];
    double q1r[5][5], q1i[5][5], q2r[5][5], q2i[5][5], q3r[5][5], q3i[5][5];
    buildq(l1, q1r, q1i);
    buildq(l2, q2r, q2i);
    buildq(l3, q3r, q3i);
    int n1 = 2 * l1 + 1, n2 = 2 * l2 + 1, n3 = 2 * l3 + 1;
    double bufr[125], bufi[125];
    double sr = 0.0, si = 0.0;
    for (int i = 0; i < n1; i++)
        for (int j = 0; j < n2; j++)
            for (int k = 0; k < n3; k++) {
                double ar = 0.0, ai = 0.0;
                for (int a = 0; a < n1; a++)
                    for (int b = 0; b < n2; b++) {
                        double t12r = q1r[a][i] * q2r[b][j] - q1i[a][i] * q2i[b][j];
                        double t12i = q1r[a][i] * q2i[b][j] + q1i[a][i] * q2r[b][j];
                        if (t12r == 0.0 && t12i == 0.0) continue;
                        for (int c = 0; c < n3; c++) {
                            double C = cgc(l1, l2, l3, a - l1, b - l2, c - l3);
                            if (C == 0.0) continue;
                            double t3r = q3r[c][k], t3i = -q3i[c][k];
                            ar += (t12r * t3r - t12i * t3i) * C;
                            ai += (t12r * t3i + t12i * t3r) * C;
                        }
                    }
                int idx = (i * n2 + j) * n3 + k;
                bufr[idx] = ar;
                bufi[idx] = ai;
                sr += fabs(ar);
                si += fabs(ai);
            }
    int base = CGO[p];
    bool useRe = (sr >= si);
    int tot = n1 * n2 * n3;
    for (int idx = 0; idx < tot; idx++)
        g_cg[base + idx] = (float)(useRe ? bufr[idx] : bufi[idx]);
}

// ---------------------------------------------------------------------------
// Node kernel: Ai then chan[n][c][p] = sum_m Ai[m] * tpw[p][m][c]
// ---------------------------------------------------------------------------
__global__ void __launch_bounds__(256) node_kernel(
    const float* __restrict__ emb_table, const int* __restrict__ A,
    const float* __restrict__ w1, const float* __restrict__ b1,
    const float* __restrict__ w2, const float* __restrict__ b2,
    const float* __restrict__ tpw, int N)
{
    __shared__ float sW1[16 * 64], sB1[64], sW2[64 * 8], sB2[8], sEmb[10 * 16];
    __shared__ float sTP[NPATHS * 8 * 16];
    int tid = threadIdx.x, bs = blockDim.x;
    for (int i = tid; i < 16 * 64; i += bs) sW1[i] = w1[i];
    for (int i = tid; i < 64; i += bs) sB1[i] = b1[i];
    for (int i = tid; i < 64 * 8; i += bs) sW2[i] = w2[i];
    for (int i = tid; i < 8; i += bs) sB2[i] = b2[i];
    for (int i = tid; i < 10 * 16; i += bs) sEmb[i] = emb_table[i];
    for (int i = tid; i < NPATHS * 8 * 16; i += bs) sTP[i] = tpw[i];
    __syncthreads();

    int n = blockIdx.x * bs + tid;
    if (n >= N) return;
    int a = A[n];
    float x[16];
#pragma unroll
    for (int i = 0; i < 16; i++) x[i] = sEmb[a * 16 + i];
    float h[64];
#pragma unroll
    for (int j = 0; j < 64; j++) {
        float t = sB1[j];
#pragma unroll
        for (int i = 0; i < 16; i++) t += x[i] * sW1[i * 64 + j];
        h[j] = t / (1.0f + __expf(-t));
    }
    float Ai[8];
#pragma unroll
    for (int o = 0; o < 8; o++) {
        float t = sB2[o];
#pragma unroll
        for (int j = 0; j < 64; j++) t += h[j] * sW2[j * 8 + o];
        Ai[o] = t;
    }
    float* crow = g_chan + (size_t)n * 256;
#pragma unroll
    for (int c = 0; c < 16; c++) {
#pragma unroll
        for (int p = 0; p < NPATHS; p++) {
            float t = 0.0f;
#pragma unroll
            for (int m = 0; m < 8; m++) t += Ai[m] * sTP[(p * 8 + m) * 16 + c];
            crow[c * 16 + p] = t;
        }
        crow[c * 16 + 15] = 0.0f;
    }
}

// ---------------------------------------------------------------------------
// Edge-geo kernel: 2 edges per thread. Computes gates MLP + scaled geometry,
// streams geoS[j][e] = gate[p] * geo[p][k] to global scratch.
// ---------------------------------------------------------------------------
__global__ void __launch_bounds__(256) geo_kernel(
    const float* __restrict__ pos, const int* __restrict__ batch,
    const int* __restrict__ esrc, const int* __restrict__ edst,
    const float* __restrict__ eshift, const float* __restrict__ cell,
    const float* __restrict__ fw1, const float* __restrict__ fb1,
    const float* __restrict__ fw2, const float* __restrict__ fb2,
    const float* __restrict__ fw3, const float* __restrict__ fb3,
    int eStart, int eEnd, int E, float inv_avg)
{
    __shared__ float sW1[8 * 64], sB1[64], sW2[64 * 64], sB2[64];
    __shared__ float sW3[64 * NPATHS], sB3[NPATHS], sCG[CG_TOTAL];
    int tid = threadIdx.x, bs = blockDim.x;
    for (int i = tid; i < 8 * 64; i += bs) sW1[i] = fw1[i];
    for (int i = tid; i < 64; i += bs) { sB1[i] = fb1[i]; sB2[i] = fb2[i]; }
    for (int i = tid; i < 64 * 64; i += bs) sW2[i] = fw2[i];
    for (int i = tid; i < 64 * NPATHS; i += bs) sW3[i] = fw3[i];
    for (int i = tid; i < NPATHS; i += bs) sB3[i] = fb3[i];
    for (int i = tid; i < CG_TOTAL; i += bs) sCG[i] = g_cg[i];
    __syncthreads();

    int eIdx[2];
    eIdx[0] = eStart + blockIdx.x * 512 + tid;
    eIdx[1] = eIdx[0] + 256;
    bool val[2];
    val[0] = eIdx[0] < eEnd;
    val[1] = eIdx[1] < eEnd;

    float Yv[2][9];
    float len[2];
#pragma unroll
    for (int r = 0; r < 2; r++) {
        int e = val[r] ? eIdx[r] : 0;
        int s = esrc[e], d = edst[e];
        int b = batch[s];
        const float* cl = cell + b * 9;
        float sx = eshift[e * 3 + 0], sy = eshift[e * 3 + 1], sz = eshift[e * 3 + 2];
        float shx = sx * cl[0] + sy * cl[3] + sz * cl[6];
        float shy = sx * cl[1] + sy * cl[4] + sz * cl[7];
        float shz = sx * cl[2] + sy * cl[5] + sz * cl[8];
        float vx = pos[d * 3 + 0] - pos[s * 3 + 0] + shx;
        float vy = pos[d * 3 + 1] - pos[s * 3 + 1] + shy;
        float vz = pos[d * 3 + 2] - pos[s * 3 + 2] + shz;
        float L = sqrtf(vx * vx + vy * vy + vz * vz);
        len[r] = L;
        float il = 1.0f / fmaxf(L, 1e-8f);
        float nx = vx * il, ny = vy * il, nz = vz * il;
        const float s3 = 1.7320508075688772f;
        const float s15 = 3.872983346207417f;
        const float s5 = 2.23606797749979f;
        Yv[r][0] = 1.0f;
        Yv[r][1] = s3 * ny; Yv[r][2] = s3 * nz; Yv[r][3] = s3 * nx;
        Yv[r][4] = s15 * nx * ny;
        Yv[r][5] = s15 * ny * nz;
        Yv[r][6] = 0.5f * s5 * (3.0f * nz * nz - 1.0f);
        Yv[r][7] = s15 * nx * nz;
        Yv[r][8] = 0.5f * s15 * (nx * nx - ny * ny);
    }

    // radial basis
    float emb[2][8];
    const float step = 2.0f / 9.0f;
    const float istep = 4.5f;
    const float cemb = 2.8284271247461903f / 1.12f;
#pragma unroll
    for (int r = 0; r < 2; r++)
#pragma unroll
        for (int i = 0; i < 8; i++) {
            float t = (len[r] - (float)(i + 1) * step) * istep;
            emb[r][i] = __expf(-t * t) * cemb;
        }

    // layer 1: 8 -> 64 (shared weight LDS feeds both edges)
    float h1[2][64];
#pragma unroll
    for (int j = 0; j < 64; j++) {
        float ta = sB1[j], tb = ta;
#pragma unroll
        for (int i = 0; i < 8; i++) {
            float w = sW1[i * 64 + j];
            ta += emb[0][i] * w;
            tb += emb[1][i] * w;
        }
        h1[0][j] = ta / (1.0f + __expf(-ta));
        h1[1][j] = tb / (1.0f + __expf(-tb));
    }

    // layers 2+3 fused: h2_j then immediately accumulate gates
    float gp[2][NPATHS];
#pragma unroll
    for (int p = 0; p < NPATHS; p++) { gp[0][p] = sB3[p]; gp[1][p] = sB3[p]; }
#pragma unroll 4
    for (int j = 0; j < 64; j++) {
        float ta = sB2[j], tb = ta;
#pragma unroll
        for (int i = 0; i < 64; i++) {
            float w = sW2[i * 64 + j];
            ta += h1[0][i] * w;
            tb += h1[1][i] * w;
        }
        float sa = ta / (1.0f + __expf(-ta));
        float sb = tb / (1.0f + __expf(-tb));
#pragma unroll
        for (int p = 0; p < NPATHS; p++) {
            float w3 = sW3[j * NPATHS + p];
            gp[0][p] += sa * w3;
            gp[1][p] += sb * w3;
        }
    }
    const float ALP0 = 0.20412414523193154f;  // 1/sqrt(8*3)
    const float ALP1 = 0.14433756729740643f;  // 1/sqrt(8*6)
#pragma unroll
    for (int p = 0; p < NPATHS; p++) {
        float alpha = (PL3[p] == 0) ? ALP0 : ALP1;
#pragma unroll
        for (int r = 0; r < 2; r++) gp[r][p] *= alpha * inv_avg;
    }

    // geometry: stream scaled values straight out (no register array)
#pragma unroll
    for (int p = 0; p < NPATHS; p++) {
        const int l1 = PL1[p], l2 = PL2[p], l3 = PL3[p];
        const int o1 = LOFF[l1], o2 = LOFF[l2];
        const int n2d = 2 * l2 + 1, n3d = 2 * l3 + 1;
#pragma unroll
        for (int k = 0; k < 2 * l3 + 1; k++) {
            float acc0 = 0.0f, acc1 = 0.0f;
#pragma unroll
            for (int m = 0; m < 2 * l1 + 1; m++) {
#pragma unroll
                for (int n = 0; n < 2 * l2 + 1; n++) {
                    float cgv = sCG[CGO[p] + (m * n2d + n) * n3d + k];
                    acc0 += Yv[0][o1 + m] * Yv[0][o2 + n] * cgv;
                    acc1 += Yv[1][o1 + m] * Yv[1][o2 + n] * cgv;
                }
            }
            int j = GEOO[p] + k;
            if (val[0]) g_geoS[(size_t)j * E + eIdx[0]] = acc0 * gp[0][p];
            if (val[1]) g_geoS[(size_t)j * E + eIdx[1]] = acc1 * gp[1][p];
        }
    }
}

// ---------------------------------------------------------------------------
// Mix kernel: 16 threads per edge (one per channel). out[d] += chan * geoS.
// ---------------------------------------------------------------------------
__global__ void __launch_bounds__(256) mix_kernel(
    const int* __restrict__ esrc, const int* __restrict__ edst,
    float* __restrict__ out, int E)
{
    __shared__ float sGeo[16][GEO_TOTAL + 1];
    int tid = threadIdx.x;
    int eBase = blockIdx.x * 16;

    // stage 16 edges x 51 geo values, coalesced over e
    for (int idx = tid; idx < 16 * GEO_TOTAL; idx += 256) {
        int j = idx >> 4;        // 0..50
        int le = idx & 15;
        int e = eBase + le;
        sGeo[le][j] = (e < E) ? g_geoS[(size_t)j * E + e] : 0.0f;
    }
    __syncthreads();

    int le = tid >> 4;
    int c = tid & 15;
    int e = eBase + le;
    if (e >= E) return;
    int s = esrc[e], d = edst[e];

    // chan row for this (node, channel): 16 floats (15 used)
    const float4* cp = (const float4*)(g_chan + (size_t)s * 256 + c * 16);
    float4 c0 = cp[0], c1 = cp[1], c2 = cp[2], c3 = cp[3];
    float ch[16] = {c0.x, c0.y, c0.z, c0.w, c1.x, c1.y, c1.z, c1.w,
                    c2.x, c2.y, c2.z, c2.w, c3.x, c3.y, c3.z, c3.w};

    float a0 = 0.0f;
    float a10 = 0.0f, a11 = 0.0f, a12 = 0.0f;
    float a20 = 0.0f, a21 = 0.0f, a22 = 0.0f, a23 = 0.0f, a24 = 0.0f;
    const float* g = sGeo[le];
#pragma unroll
    for (int p = 0; p < NPATHS; p++) {
        float cw = ch[p];
        int o = GEOO[p];
        if (PL3[p] == 0) {
            a0 += cw * g[o];
        } else if (PL3[p] == 1) {
            a10 += cw * g[o + 0];
            a11 += cw * g[o + 1];
            a12 += cw * g[o + 2];
        } else {
            a20 += cw * g[o + 0];
            a21 += cw * g[o + 1];
            a22 += cw * g[o + 2];
            a23 += cw * g[o + 3];
            a24 += cw * g[o + 4];
        }
    }

    float* orow = out + (size_t)d * 144;
    atomicAdd(orow + c, a0);
    atomicAdd(orow + 16 + 3 * c + 0, a10);
    atomicAdd(orow + 16 + 3 * c + 1, a11);
    atomicAdd(orow + 16 + 3 * c + 2, a12);
    atomicAdd(orow + 64 + 5 * c + 0, a20);
    atomicAdd(orow + 64 + 5 * c + 1, a21);
    atomicAdd(orow + 64 + 5 * c + 2, a22);
    atomicAdd(orow + 64 + 5 * c + 3, a23);
    atomicAdd(orow + 64 + 5 * c + 4, a24);
}

// ---------------------------------------------------------------------------
extern "C" void kernel_launch(void* const* d_in, const int* in_sizes, int n_in,
                              void* d_out, int out_size)
{
    const float* pos    = (const float*)d_in[0];
    const int*   A      = (const int*)d_in[1];
    const int*   batch  = (const int*)d_in[2];
    const int*   esrc   = (const int*)d_in[3];
    const int*   edst   = (const int*)d_in[4];
    const float* eshift = (const float*)d_in[5];
    const float* cell   = (const float*)d_in[6];
    const float* embt   = (const float*)d_in[7];
    const float* mw1    = (const float*)d_in[8];
    const float* mb1    = (const float*)d_in[9];
    const float* mw2    = (const float*)d_in[10];
    const float* mb2    = (const float*)d_in[11];
    const float* fw1    = (const float*)d_in[12];
    const float* fb1    = (const float*)d_in[13];
    const float* fw2    = (const float*)d_in[14];
    const float* fb2    = (const float*)d_in[15];
    const float* fw3    = (const float*)d_in[16];
    const float* fb3    = (const float*)d_in[17];
    const float* tpw    = (const float*)d_in[18];
    float* out = (float*)d_out;

    int N = in_sizes[1];
    int E = in_sizes[3];
    float avg = (float)E / (float)N;
    float inv_avg = 1.0f / fmaxf(avg, 1e-8f);

    cudaMemsetAsync(d_out, 0, (size_t)out_size * sizeof(float));
    init_cg_kernel<<<1, 32>>>();
    node_kernel<<<(N + 255) / 256, 256>>>(embt, A, mw1, mb1, mw2, mb2, tpw, N);

    // geo in 4 chunks (also positions a geo launch at ncu's capture slot)
    int chunk = (E + 3) / 4;
    for (int q = 0; q < 4; q++) {
        int s0 = q * chunk;
        int s1 = min(s0 + chunk, E);
        if (s1 <= s0) continue;
        int nb = (s1 - s0 + 511) / 512;
        geo_kernel<<<nb, 256>>>(pos, batch, esrc, edst, eshift, cell,
                                fw1, fb1, fw2, fb2, fw3, fb3,
                                s0, s1, E, inv_avg);
    }
    mix_kernel<<<(E + 15) / 16, 256>>>(esrc, edst, out, E);
}

// round 3
// speedup vs baseline: 1.1099x; 1.0053x over previous
#include <cuda_runtime.h>
#include <math.h>

#define NPATHS 15
#define CG_TOTAL 615
#define MAXE 1000000
#define NPAD 50176            // 1024 * 49
#define SCAN_T 1024
#define SCAN_CHUNK 49

// path tables: (l1,l2,l3) enumerated as in the reference (l1 outer, l2 mid, l3 inner)
__device__ constexpr int PL1[NPATHS]  = {0,0,0,1,1,1,1,1,1,2,2,2,2,2,2};
__device__ constexpr int PL2[NPATHS]  = {0,1,2,0,1,1,1,2,2,0,1,1,2,2,2};
__device__ constexpr int PL3[NPATHS]  = {0,1,2,1,0,1,2,1,2,2,1,2,0,1,2};
__device__ constexpr int CGO[NPATHS]  = {0,1,10,35,44,53,80,125,170,245,270,315,390,415,490};
__device__ constexpr int GEOO[NPATHS] = {0,1,4,9,12,13,16,21,24,29,34,37,42,43,46};
__device__ constexpr int LOFF[3] = {0,1,4};

__device__ float g_cg[CG_TOTAL];
__device__ float g_chan[NPAD * 256];             // [node][c(16)][p(pad16)]
__device__ float g_geoS[(size_t)MAXE * 52];      // [slot][52]  (gates folded in)
__device__ int   g_count[NPAD];
__device__ int   g_off[NPAD + 1];
__device__ int   g_cursor[NPAD];
__device__ int   g_eperm[MAXE];
__device__ int   g_srcS[MAXE];

// ---------------------------------------------------------------------------
// CG init (device-side, double precision, replicates the reference)
// ---------------------------------------------------------------------------
__device__ double dfact(int n) {
    double r = 1.0;
    for (int i = 2; i <= n; ++i) r *= (double)i;
    return r;
}

__device__ double cgc(int j1, int j2, int j3, int m1, int m2, int m3) {
    if (m1 + m2 != m3) return 0.0;
    double pre = sqrt((double)(2 * j3 + 1) * dfact(j3 + j1 - j2) * dfact(j3 - j1 + j2) *
                      dfact(j1 + j2 - j3) / dfact(j1 + j2 + j3 + 1));
    pre *= sqrt(dfact(j3 + m3) * dfact(j3 - m3) * dfact(j1 - m1) * dfact(j1 + m1) *
                dfact(j2 - m2) * dfact(j2 + m2));
    double s = 0.0;
    for (int k = 0; k <= j1 + j2 - j3; ++k) {
        int d1 = j1 + j2 - j3 - k, d2 = j1 - m1 - k, d3 = j2 + m2 - k;
        int d4 = j3 - j2 + m1 + k, d5 = j3 - j1 - m2 + k;
        if (d1 < 0 || d2 < 0 || d3 < 0 || d4 < 0 || d5 < 0) continue;
        double t = 1.0 / (dfact(k) * dfact(d1) * dfact(d2) * dfact(d3) * dfact(d4) * dfact(d5));
        s += (k & 1) ? -t : t;
    }
    return pre * s;
}

__device__ void buildq(int l, double qr[5][5], double qi[5][5]) {
    for (int a = 0; a < 5; a++)
        for (int b = 0; b < 5; b++) { qr[a][b] = 0.0; qi[a][b] = 0.0; }
    const double isq = sqrt(0.5);
    for (int m = -l; m < 0; m++) {
        qr[l + m][l - m] = isq;
        qi[l + m][l + m] = -isq;
    }
    qr[l][l] = 1.0;
    for (int m = 1; m <= l; m++) {
        double sg = (m & 1) ? -1.0 : 1.0;
        qr[l + m][l + m] = sg * isq;
        qi[l + m][l - m] = sg * isq;
    }
    if (l == 1) {
        for (int a = 0; a < 5; a++)
            for (int b = 0; b < 5; b++) {
                double r = qr[a][b], i0 = qi[a][b];
                qr[a][b] = i0;
                qi[a][b] = -r;
            }
    } else if (l == 2) {
        for (int a = 0; a < 5; a++)
            for (int b = 0; b < 5; b++) { qr[a][b] = -qr[a][b]; qi[a][b] = -qi[a][b]; }
    }
}

__global__ void init_cg_kernel() {
    int p = threadIdx.x;
    if (p >= NPATHS) return;
    int l1 = PL1[p], l2 = PL2[p], l3 = PL3[p];
    double q1r[5][5], q1i[5][5], q2r[5][5], q2i[5][5], q3r[5][5], q3i[5][5];
    buildq(l1, q1r, q1i);
    buildq(l2, q2r, q2i);
    buildq(l3, q3r, q3i);
    int n1 = 2 * l1 + 1, n2 = 2 * l2 + 1, n3 = 2 * l3 + 1;
    double bufr[125], bufi[125];
    double sr = 0.0, si = 0.0;
    for (int i = 0; i < n1; i++)
        for (int j = 0; j < n2; j++)
            for (int k = 0; k < n3; k++) {
                double ar = 0.0, ai = 0.0;
                for (int a = 0; a < n1; a++)
                    for (int b = 0; b < n2; b++) {
                        double t12r = q1r[a][i] * q2r[b][j] - q1i[a][i] * q2i[b][j];
                        double t12i = q1r[a][i] * q2i[b][j] + q1i[a][i] * q2r[b][j];
                        if (t12r == 0.0 && t12i == 0.0) continue;
                        for (int c = 0; c < n3; c++) {
                            double C = cgc(l1, l2, l3, a - l1, b - l2, c - l3);
                            if (C == 0.0) continue;
                            double t3r = q3r[c][k], t3i = -q3i[c][k];
                            ar += (t12r * t3r - t12i * t3i) * C;
                            ai += (t12r * t3i + t12i * t3r) * C;
                        }
                    }
                int idx = (i * n2 + j) * n3 + k;
                bufr[idx] = ar;
                bufi[idx] = ai;
                sr += fabs(ar);
                si += fabs(ai);
            }
    int base = CGO[p];
    bool useRe = (sr >= si);
    int tot = n1 * n2 * n3;
    for (int idx = 0; idx < tot; idx++)
        g_cg[base + idx] = (float)(useRe ? bufr[idx] : bufi[idx]);
}

// ---------------------------------------------------------------------------
// Sorting machinery: zero -> hist -> scan -> scatter
// ---------------------------------------------------------------------------
__global__ void zero_count_kernel() {
    int i = blockIdx.x * blockDim.x + threadIdx.x;
    if (i < NPAD) g_count[i] = 0;
}

__global__ void hist_kernel(const int* __restrict__ edst, int E) {
    int e = blockIdx.x * blockDim.x + threadIdx.x;
    if (e < E) atomicAdd(&g_count[edst[e]], 1);
}

__global__ void __launch_bounds__(SCAN_T) scan_kernel() {
    __shared__ int ssum[SCAN_T];
    int t = threadIdx.x;
    int lo = t * SCAN_CHUNK;
    int hi = lo + SCAN_CHUNK;
    int s = 0;
    for (int i = lo; i < hi; i++) s += g_count[i];
    ssum[t] = s;
    __syncthreads();
    for (int d = 1; d < SCAN_T; d <<= 1) {
        int v = 0;
        if (t >= d) v = ssum[t - d];
        __syncthreads();
        if (t >= d) ssum[t] += v;
        __syncthreads();
    }
    int pre = (t == 0) ? 0 : ssum[t - 1];
    for (int i = lo; i < hi; i++) {
        g_off[i] = pre;
        g_cursor[i] = pre;
        pre += g_count[i];
    }
    if (t == SCAN_T - 1) g_off[NPAD] = pre;
}

__global__ void scatter_kernel(const int* __restrict__ edst, int E) {
    int e = blockIdx.x * blockDim.x + threadIdx.x;
    if (e >= E) return;
    int d = edst[e];
    int p = atomicAdd(&g_cursor[d], 1);
    g_eperm[p] = e;
}

// ---------------------------------------------------------------------------
// Node kernel: Ai, then chan[n][c][p] = sum_m Ai[m] * tpw[p][m][c]
// ---------------------------------------------------------------------------
__global__ void __launch_bounds__(256) node_kernel(
    const float* __restrict__ emb_table, const int* __restrict__ A,
    const float* __restrict__ w1, const float* __restrict__ b1,
    const float* __restrict__ w2, const float* __restrict__ b2,
    const float* __restrict__ tpw, int N)
{
    __shared__ float sW1[16 * 64], sB1[64], sW2[64 * 8], sB2[8], sEmb[10 * 16];
    __shared__ float sTP[NPATHS * 8 * 16];
    int tid = threadIdx.x, bs = blockDim.x;
    for (int i = tid; i < 16 * 64; i += bs) sW1[i] = w1[i];
    for (int i = tid; i < 64; i += bs) sB1[i] = b1[i];
    for (int i = tid; i < 64 * 8; i += bs) sW2[i] = w2[i];
    for (int i = tid; i < 8; i += bs) sB2[i] = b2[i];
    for (int i = tid; i < 10 * 16; i += bs) sEmb[i] = emb_table[i];
    for (int i = tid; i < NPATHS * 8 * 16; i += bs) sTP[i] = tpw[i];
    __syncthreads();

    int n = blockIdx.x * bs + tid;
    if (n >= N) return;
    int a = A[n];
    float x[16];
#pragma unroll
    for (int i = 0; i < 16; i++) x[i] = sEmb[a * 16 + i];
    float h[64];
#pragma unroll
    for (int j = 0; j < 64; j++) {
        float t = sB1[j];
#pragma unroll
        for (int i = 0; i < 16; i++) t += x[i] * sW1[i * 64 + j];
        h[j] = t / (1.0f + __expf(-t));
    }
    float Ai[8];
#pragma unroll
    for (int o = 0; o < 8; o++) {
        float t = sB2[o];
#pragma unroll
        for (int j = 0; j < 64; j++) t += h[j] * sW2[j * 8 + o];
        Ai[o] = t;
    }
    float* crow = g_chan + (size_t)n * 256;
#pragma unroll
    for (int c = 0; c < 16; c++) {
#pragma unroll
        for (int p = 0; p < NPATHS; p++) {
            float t = 0.0f;
#pragma unroll
            for (int m = 0; m < 8; m++) t += Ai[m] * sTP[(p * 8 + m) * 16 + c];
            crow[c * 16 + p] = t;
        }
        crow[c * 16 + 15] = 0.0f;
    }
}

// ---------------------------------------------------------------------------
// Geo kernel: processes SORTED slots (2 per thread). Gates MLP + scaled
// geometry; writes geoS[slot][j] = gate[p]*geo[p][k], srcS[slot] = src node.
// Transposed float4 weights in smem -> 4x fewer LDS.
// ---------------------------------------------------------------------------
__global__ void __launch_bounds__(256) geo_kernel(
    const float* __restrict__ pos, const int* __restrict__ batch,
    const int* __restrict__ esrc, const int* __restrict__ edst,
    const float* __restrict__ eshift, const float* __restrict__ cell,
    const float* __restrict__ fw1, const float* __restrict__ fb1,
    const float* __restrict__ fw2, const float* __restrict__ fb2,
    const float* __restrict__ fw3, const float* __restrict__ fb3,
    int E, float inv_avg)
{
    __shared__ float4 sW1t[64][2];    // [j][i4]  (8 -> 64 layer, transposed)
    __shared__ float4 sW2t[64][16];   // [j][i4]  (64 -> 64 layer, transposed)
    __shared__ float4 sW3p[64][4];    // [j][p4]  (64 -> 15, padded to 16)
    __shared__ float sB1[64], sB2[64], sB3[16], sCG[CG_TOTAL];
    int tid = threadIdx.x, bs = blockDim.x;
    for (int i = tid; i < 8 * 64; i += bs) {
        int r = i / 64, j = i % 64;
        ((float*)&sW1t[j][0])[r] = fw1[i];
    }
    for (int i = tid; i < 64 * 64; i += bs) {
        int r = i / 64, j = i % 64;
        ((float*)&sW2t[j][0])[r] = fw2[i];
    }
    for (int i = tid; i < 64 * 16; i += bs) {
        int j = i >> 4, p = i & 15;
        ((float*)&sW3p[j][0])[p] = (p < NPATHS) ? fw3[j * NPATHS + p] : 0.0f;
    }
    for (int i = tid; i < 64; i += bs) { sB1[i] = fb1[i]; sB2[i] = fb2[i]; }
    for (int i = tid; i < 16; i += bs) sB3[i] = (i < NPATHS) ? fb3[i] : 0.0f;
    for (int i = tid; i < CG_TOTAL; i += bs) sCG[i] = g_cg[i];
    __syncthreads();

    int slot[2];
    slot[0] = blockIdx.x * 512 + tid;
    slot[1] = slot[0] + 256;
    bool val[2];
    val[0] = slot[0] < E;
    val[1] = slot[1] < E;

    float Yv[2][9];
    float len[2];
#pragma unroll
    for (int r = 0; r < 2; r++) {
        int e = val[r] ? g_eperm[slot[r]] : 0;
        int s = esrc[e], d = edst[e];
        if (val[r]) g_srcS[slot[r]] = s;
        int b = batch[s];
        const float* cl = cell + b * 9;
        float sx = eshift[e * 3 + 0], sy = eshift[e * 3 + 1], sz = eshift[e * 3 + 2];
        float shx = sx * cl[0] + sy * cl[3] + sz * cl[6];
        float shy = sx * cl[1] + sy * cl[4] + sz * cl[7];
        float shz = sx * cl[2] + sy * cl[5] + sz * cl[8];
        float vx = pos[d * 3 + 0] - pos[s * 3 + 0] + shx;
        float vy = pos[d * 3 + 1] - pos[s * 3 + 1] + shy;
        float vz = pos[d * 3 + 2] - pos[s * 3 + 2] + shz;
        float L = sqrtf(vx * vx + vy * vy + vz * vz);
        len[r] = L;
        float il = 1.0f / fmaxf(L, 1e-8f);
        float nx = vx * il, ny = vy * il, nz = vz * il;
        const float s3 = 1.7320508075688772f;
        const float s15 = 3.872983346207417f;
        const float s5 = 2.23606797749979f;
        Yv[r][0] = 1.0f;
        Yv[r][1] = s3 * ny; Yv[r][2] = s3 * nz; Yv[r][3] = s3 * nx;
        Yv[r][4] = s15 * nx * ny;
        Yv[r][5] = s15 * ny * nz;
        Yv[r][6] = 0.5f * s5 * (3.0f * nz * nz - 1.0f);
        Yv[r][7] = s15 * nx * nz;
        Yv[r][8] = 0.5f * s15 * (nx * nx - ny * ny);
    }

    // radial basis
    float emb[2][8];
    const float step = 2.0f / 9.0f;
    const float istep = 4.5f;
    const float cemb = 2.8284271247461903f / 1.12f;
#pragma unroll
    for (int r = 0; r < 2; r++)
#pragma unroll
        for (int i = 0; i < 8; i++) {
            float t = (len[r] - (float)(i + 1) * step) * istep;
            emb[r][i] = __expf(-t * t) * cemb;
        }

    // layer 1: 8 -> 64 (float4 transposed weights)
    float h1[2][64];
#pragma unroll
    for (int j = 0; j < 64; j++) {
        float4 w0 = sW1t[j][0], w1v = sW1t[j][1];
        float ta = sB1[j], tb = ta;
        ta += emb[0][0] * w0.x + emb[0][1] * w0.y + emb[0][2] * w0.z + emb[0][3] * w0.w;
        ta += emb[0][4] * w1v.x + emb[0][5] * w1v.y + emb[0][6] * w1v.z + emb[0][7] * w1v.w;
        tb += emb[1][0] * w0.x + emb[1][1] * w0.y + emb[1][2] * w0.z + emb[1][3] * w0.w;
        tb += emb[1][4] * w1v.x + emb[1][5] * w1v.y + emb[1][6] * w1v.z + emb[1][7] * w1v.w;
        h1[0][j] = ta / (1.0f + __expf(-ta));
        h1[1][j] = tb / (1.0f + __expf(-tb));
    }

    // layers 2+3 fused
    float gp[2][16];
#pragma unroll
    for (int p = 0; p < 16; p++) { gp[0][p] = sB3[p]; gp[1][p] = sB3[p]; }
#pragma unroll 4
    for (int j = 0; j < 64; j++) {
        float ta = sB2[j], tb = ta;
#pragma unroll
        for (int i4 = 0; i4 < 16; i4++) {
            float4 w = sW2t[j][i4];
            ta += h1[0][i4 * 4 + 0] * w.x + h1[0][i4 * 4 + 1] * w.y +
                  h1[0][i4 * 4 + 2] * w.z + h1[0][i4 * 4 + 3] * w.w;
            tb += h1[1][i4 * 4 + 0] * w.x + h1[1][i4 * 4 + 1] * w.y +
                  h1[1][i4 * 4 + 2] * w.z + h1[1][i4 * 4 + 3] * w.w;
        }
        float sa = ta / (1.0f + __expf(-ta));
        float sb = tb / (1.0f + __expf(-tb));
#pragma unroll
        for (int p4 = 0; p4 < 4; p4++) {
            float4 w3 = sW3p[j][p4];
            gp[0][p4 * 4 + 0] += sa * w3.x;
            gp[0][p4 * 4 + 1] += sa * w3.y;
            gp[0][p4 * 4 + 2] += sa * w3.z;
            gp[0][p4 * 4 + 3] += sa * w3.w;
            gp[1][p4 * 4 + 0] += sb * w3.x;
            gp[1][p4 * 4 + 1] += sb * w3.y;
            gp[1][p4 * 4 + 2] += sb * w3.z;
            gp[1][p4 * 4 + 3] += sb * w3.w;
        }
    }
    const float ALP0 = 0.20412414523193154f;  // 1/sqrt(8*3)
    const float ALP1 = 0.14433756729740643f;  // 1/sqrt(8*6)
#pragma unroll
    for (int p = 0; p < NPATHS; p++) {
        float alpha = (PL3[p] == 0) ? ALP0 : ALP1;
        gp[0][p] *= alpha * inv_avg;
        gp[1][p] *= alpha * inv_avg;
    }

    // geometry: stream scaled values out (geoS[slot][j])
    float* out0 = g_geoS + (size_t)slot[0] * 52;
    float* out1 = g_geoS + (size_t)slot[1] * 52;
#pragma unroll
    for (int p = 0; p < NPATHS; p++) {
        const int l1 = PL1[p], l2 = PL2[p], l3 = PL3[p];
        const int o1 = LOFF[l1], o2 = LOFF[l2];
        const int n2d = 2 * l2 + 1, n3d = 2 * l3 + 1;
#pragma unroll
        for (int k = 0; k < 2 * l3 + 1; k++) {
            float acc0 = 0.0f, acc1 = 0.0f;
#pragma unroll
            for (int m = 0; m < 2 * l1 + 1; m++) {
#pragma unroll
                for (int n = 0; n < 2 * l2 + 1; n++) {
                    float cgv = sCG[CGO[p] + (m * n2d + n) * n3d + k];
                    acc0 += Yv[0][o1 + m] * Yv[0][o2 + n] * cgv;
                    acc1 += Yv[1][o1 + m] * Yv[1][o2 + n] * cgv;
                }
            }
            int j = GEOO[p] + k;
            if (val[0]) out0[j] = acc0 * gp[0][p];
            if (val[1]) out1[j] = acc1 * gp[1][p];
        }
    }
}

// ---------------------------------------------------------------------------
// Mix/gather kernel: 16 threads per node (thread = channel). Loops over the
// node's sorted slot range; NO atomics, plain stores at the end.
// ---------------------------------------------------------------------------
__global__ void __launch_bounds__(256) mix_kernel(float* __restrict__ out, int N)
{
    int tid = threadIdx.x;
    int half = tid >> 4;       // 0..15 (node within block)
    int c = tid & 15;          // channel
    int n = blockIdx.x * 16 + half;
    if (n >= N) return;
    int lo = g_off[n], hi = g_off[n + 1];

    float a0 = 0.0f;
    float a10 = 0.0f, a11 = 0.0f, a12 = 0.0f;
    float a20 = 0.0f, a21 = 0.0f, a22 = 0.0f, a23 = 0.0f, a24 = 0.0f;

    for (int i = lo; i < hi; i++) {
        int s = g_srcS[i];
        const float4* cp = (const float4*)(g_chan + (size_t)s * 256 + c * 16);
        float4 c0 = cp[0], c1 = cp[1], c2 = cp[2], c3 = cp[3];
        float ch[16] = {c0.x, c0.y, c0.z, c0.w, c1.x, c1.y, c1.z, c1.w,
                        c2.x, c2.y, c2.z, c2.w, c3.x, c3.y, c3.z, c3.w};

        const float4* gp4 = (const float4*)(g_geoS + (size_t)i * 52);
        float g[52];
#pragma unroll
        for (int q = 0; q < 13; q++) {
            float4 v = gp4[q];
            g[q * 4 + 0] = v.x; g[q * 4 + 1] = v.y;
            g[q * 4 + 2] = v.z; g[q * 4 + 3] = v.w;
        }

#pragma unroll
        for (int p = 0; p < NPATHS; p++) {
            float cw = ch[p];
            int o = GEOO[p];
            if (PL3[p] == 0) {
                a0 += cw * g[o];
            } else if (PL3[p] == 1) {
                a10 += cw * g[o + 0];
                a11 += cw * g[o + 1];
                a12 += cw * g[o + 2];
            } else {
                a20 += cw * g[o + 0];
                a21 += cw * g[o + 1];
                a22 += cw * g[o + 2];
                a23 += cw * g[o + 3];
                a24 += cw * g[o + 4];
            }
        }
    }

    float* orow = out + (size_t)n * 144;
    orow[c] = a0;
    orow[16 + 3 * c + 0] = a10;
    orow[16 + 3 * c + 1] = a11;
    orow[16 + 3 * c + 2] = a12;
    orow[64 + 5 * c + 0] = a20;
    orow[64 + 5 * c + 1] = a21;
    orow[64 + 5 * c + 2] = a22;
    orow[64 + 5 * c + 3] = a23;
    orow[64 + 5 * c + 4] = a24;
}

// ---------------------------------------------------------------------------
extern "C" void kernel_launch(void* const* d_in, const int* in_sizes, int n_in,
                              void* d_out, int out_size)
{
    const float* pos    = (const float*)d_in[0];
    const int*   A      = (const int*)d_in[1];
    const int*   batch  = (const int*)d_in[2];
    const int*   esrc   = (const int*)d_in[3];
    const int*   edst   = (const int*)d_in[4];
    const float* eshift = (const float*)d_in[5];
    const float* cell   = (const float*)d_in[6];
    const float* embt   = (const float*)d_in[7];
    const float* mw1    = (const float*)d_in[8];
    const float* mb1    = (const float*)d_in[9];
    const float* mw2    = (const float*)d_in[10];
    const float* mb2    = (const float*)d_in[11];
    const float* fw1    = (const float*)d_in[12];
    const float* fb1    = (const float*)d_in[13];
    const float* fw2    = (const float*)d_in[14];
    const float* fb2    = (const float*)d_in[15];
    const float* fw3    = (const float*)d_in[16];
    const float* fb3    = (const float*)d_in[17];
    const float* tpw    = (const float*)d_in[18];
    float* out = (float*)d_out;

    int N = in_sizes[1];
    int E = in_sizes[3];
    float avg = (float)E / (float)N;
    float inv_avg = 1.0f / fmaxf(avg, 1e-8f);

    init_cg_kernel<<<1, 32>>>();
    zero_count_kernel<<<(NPAD + 255) / 256, 256>>>();
    node_kernel<<<(N + 255) / 256, 256>>>(embt, A, mw1, mb1, mw2, mb2, tpw, N);
    hist_kernel<<<(E + 255) / 256, 256>>>(edst, E);
    scan_kernel<<<1, SCAN_T>>>();
    scatter_kernel<<<(E + 255) / 256, 256>>>(edst, E);
    geo_kernel<<<(E + 511) / 512, 256>>>(pos, batch, esrc, edst, eshift, cell,
                                         fw1, fb1, fw2, fb2, fw3, fb3,
                                         E, inv_avg);
    mix_kernel<<<(N + 15) / 16, 256>>>(out, N);
}

// round 4
// speedup vs baseline: 1.1332x; 1.0210x over previous
#include <cuda_runtime.h>
#include <math.h>

#define NPATHS 15
#define CG_TOTAL 615
#define MAXE 1000000
#define NPAD 50176            // 1024 * 49
#define SCAN_T 1024
#define SCAN_CHUNK 49

// path tables: (l1,l2,l3) enumerated as in the reference (l1 outer, l2 mid, l3 inner)
__device__ constexpr int PL1[NPATHS]  = {0,0,0,1,1,1,1,1,1,2,2,2,2,2,2};
__device__ constexpr int PL2[NPATHS]  = {0,1,2,0,1,1,1,2,2,0,1,1,2,2,2};
__device__ constexpr int PL3[NPATHS]  = {0,1,2,1,0,1,2,1,2,2,1,2,0,1,2};
__device__ constexpr int CGO[NPATHS]  = {0,1,10,35,44,53,80,125,170,245,270,315,390,415,490};
__device__ constexpr int GEOO[NPATHS] = {0,1,4,9,12,13,16,21,24,29,34,37,42,43,46};
__device__ constexpr int LOFF[3] = {0,1,4};

__device__ float g_cg[CG_TOTAL];
__device__ __align__(16) float g_Ai[NPAD * 8];
__device__ __align__(16) float g_AiS[MAXE * 8];          // per sorted slot: Ai of src
__device__ float g_geoS[(size_t)52 * MAXE];              // [pj][slot]; row 51 stays 0
__device__ __align__(16) float g_S[(size_t)NPAD * 416];  // [node][m*52+pj]
__device__ int   g_count[NPAD];
__device__ int   g_off[NPAD + 1];
__device__ int   g_cursor[NPAD];
__device__ int   g_eperm[MAXE];

// ---------------------------------------------------------------------------
// CG init (device-side, double precision, replicates the reference)
// ---------------------------------------------------------------------------
__device__ double dfact(int n) {
    double r = 1.0;
    for (int i = 2; i <= n; ++i) r *= (double)i;
    return r;
}

__device__ double cgc(int j1, int j2, int j3, int m1, int m2, int m3) {
    if (m1 + m2 != m3) return 0.0;
    double pre = sqrt((double)(2 * j3 + 1) * dfact(j3 + j1 - j2) * dfact(j3 - j1 + j2) *
                      dfact(j1 + j2 - j3) / dfact(j1 + j2 + j3 + 1));
    pre *= sqrt(dfact(j3 + m3) * dfact(j3 - m3) * dfact(j1 - m1) * dfact(j1 + m1) *
                dfact(j2 - m2) * dfact(j2 + m2));
    double s = 0.0;
    for (int k = 0; k <= j1 + j2 - j3; ++k) {
        int d1 = j1 + j2 - j3 - k, d2 = j1 - m1 - k, d3 = j2 + m2 - k;
        int d4 = j3 - j2 + m1 + k, d5 = j3 - j1 - m2 + k;
        if (d1 < 0 || d2 < 0 || d3 < 0 || d4 < 0 || d5 < 0) continue;
        double t = 1.0 / (dfact(k) * dfact(d1) * dfact(d2) * dfact(d3) * dfact(d4) * dfact(d5));
        s += (k & 1) ? -t : t;
    }
    return pre * s;
}

__device__ void buildq(int l, double qr[5][5], double qi[5][5]) {
    for (int a = 0; a < 5; a++)
        for (int b = 0; b < 5; b++) { qr[a][b] = 0.0; qi[a][b] = 0.0; }
    const double isq = sqrt(0.5);
    for (int m = -l; m < 0; m++) {
        qr[l + m][l - m] = isq;
        qi[l + m][l + m] = -isq;
    }
    qr[l][l] = 1.0;
    for (int m = 1; m <= l; m++) {
        double sg = (m & 1) ? -1.0 : 1.0;
        qr[l + m][l + m] = sg * isq;
        qi[l + m][l - m] = sg * isq;
    }
    if (l == 1) {
        for (int a = 0; a < 5; a++)
            for (int b = 0; b < 5; b++) {
                double r = qr[a][b], i0 = qi[a][b];
                qr[a][b] = i0;
                qi[a][b] = -r;
            }
    } else if (l == 2) {
        for (int a = 0; a < 5; a++)
            for (int b = 0; b < 5; b++) { qr[a][b] = -qr[a][b]; qi[a][b] = -qi[a][b]; }
    }
}

__global__ void init_cg_kernel() {
    int p = threadIdx.x;
    if (p >= NPATHS) return;
    int l1 = PL1[p], l2 = PL2[p], l3 = PL3[p];
    double q1r[5][5], q1i[5][5], q2r[5][5], q2i[5][5], q3r[5][5], q3i[5][5];
    buildq(l1, q1r, q1i);
    buildq(l2, q2r, q2i);
    buildq(l3, q3r, q3i);
    int n1 = 2 * l1 + 1, n2 = 2 * l2 + 1, n3 = 2 * l3 + 1;
    double bufr[125], bufi[125];
    double sr = 0.0, si = 0.0;
    for (int i = 0; i < n1; i++)
        for (int j = 0; j < n2; j++)
            for (int k = 0; k < n3; k++) {
                double ar = 0.0, ai = 0.0;
                for (int a = 0; a < n1; a++)
                    for (int b = 0; b < n2; b++) {
                        double t12r = q1r[a][i] * q2r[b][j] - q1i[a][i] * q2i[b][j];
                        double t12i = q1r[a][i] * q2i[b][j] + q1i[a][i] * q2r[b][j];
                        if (t12r == 0.0 && t12i == 0.0) continue;
                        for (int c = 0; c < n3; c++) {
                            double C = cgc(l1, l2, l3, a - l1, b - l2, c - l3);
                            if (C == 0.0) continue;
                            double t3r = q3r[c][k], t3i = -q3i[c][k];
                            ar += (t12r * t3r - t12i * t3i) * C;
                            ai += (t12r * t3i + t12i * t3r) * C;
                        }
                    }
                int idx = (i * n2 + j) * n3 + k;
                bufr[idx] = ar;
                bufi[idx] = ai;
                sr += fabs(ar);
                si += fabs(ai);
            }
    int base = CGO[p];
    bool useRe = (sr >= si);
    int tot = n1 * n2 * n3;
    for (int idx = 0; idx < tot; idx++)
        g_cg[base + idx] = (float)(useRe ? bufr[idx] : bufi[idx]);
}

// ---------------------------------------------------------------------------
// Sorting machinery: zero -> hist -> scan -> scatter
// ---------------------------------------------------------------------------
__global__ void zero_count_kernel() {
    int i = blockIdx.x * blockDim.x + threadIdx.x;
    if (i < NPAD) g_count[i] = 0;
}

__global__ void hist_kernel(const int* __restrict__ edst, int E) {
    int e = blockIdx.x * blockDim.x + threadIdx.x;
    if (e < E) atomicAdd(&g_count[edst[e]], 1);
}

__global__ void __launch_bounds__(SCAN_T) scan_kernel() {
    __shared__ int ssum[SCAN_T];
    int t = threadIdx.x;
    int lo = t * SCAN_CHUNK;
    int hi = lo + SCAN_CHUNK;
    int s = 0;
    for (int i = lo; i < hi; i++) s += g_count[i];
    ssum[t] = s;
    __syncthreads();
    for (int d = 1; d < SCAN_T; d <<= 1) {
        int v = 0;
        if (t >= d) v = ssum[t - d];
        __syncthreads();
        if (t >= d) ssum[t] += v;
        __syncthreads();
    }
    int pre = (t == 0) ? 0 : ssum[t - 1];
    for (int i = lo; i < hi; i++) {
        g_off[i] = pre;
        g_cursor[i] = pre;
        pre += g_count[i];
    }
    if (t == SCAN_T - 1) g_off[NPAD] = pre;
}

__global__ void scatter_kernel(const int* __restrict__ edst, int E) {
    int e = blockIdx.x * blockDim.x + threadIdx.x;
    if (e >= E) return;
    int d = edst[e];
    int p = atomicAdd(&g_cursor[d], 1);
    g_eperm[p] = e;
}

// ---------------------------------------------------------------------------
// Node kernel: Ai only
// ---------------------------------------------------------------------------
__global__ void __launch_bounds__(256) node_kernel(
    const float* __restrict__ emb_table, const int* __restrict__ A,
    const float* __restrict__ w1, const float* __restrict__ b1,
    const float* __restrict__ w2, const float* __restrict__ b2, int N)
{
    __shared__ float sW1[16 * 64], sB1[64], sW2[64 * 8], sB2[8], sEmb[10 * 16];
    int tid = threadIdx.x, bs = blockDim.x;
    for (int i = tid; i < 16 * 64; i += bs) sW1[i] = w1[i];
    for (int i = tid; i < 64; i += bs) sB1[i] = b1[i];
    for (int i = tid; i < 64 * 8; i += bs) sW2[i] = w2[i];
    for (int i = tid; i < 8; i += bs) sB2[i] = b2[i];
    for (int i = tid; i < 10 * 16; i += bs) sEmb[i] = emb_table[i];
    __syncthreads();

    int n = blockIdx.x * bs + tid;
    if (n >= N) return;
    int a = A[n];
    float x[16];
#pragma unroll
    for (int i = 0; i < 16; i++) x[i] = sEmb[a * 16 + i];
    float h[64];
#pragma unroll
    for (int j = 0; j < 64; j++) {
        float t = sB1[j];
#pragma unroll
        for (int i = 0; i < 16; i++) t += x[i] * sW1[i * 64 + j];
        h[j] = t / (1.0f + __expf(-t));
    }
#pragma unroll
    for (int o = 0; o < 8; o++) {
        float t = sB2[o];
#pragma unroll
        for (int j = 0; j < 64; j++) t += h[j] * sW2[j * 8 + o];
        g_Ai[n * 8 + o] = t;
    }
}

// ---------------------------------------------------------------------------
// Geo kernel: sorted slots, 2 per thread. Gates MLP + scaled geometry.
// Writes geoS[pj][slot] (coalesced) and AiS[slot][8].
// ---------------------------------------------------------------------------
__global__ void __launch_bounds__(256) geo_kernel(
    const float* __restrict__ pos, const int* __restrict__ batch,
    const int* __restrict__ esrc, const int* __restrict__ edst,
    const float* __restrict__ eshift, const float* __restrict__ cell,
    const float* __restrict__ fw1, const float* __restrict__ fb1,
    const float* __restrict__ fw2, const float* __restrict__ fb2,
    const float* __restrict__ fw3, const float* __restrict__ fb3,
    int E, float inv_avg)
{
    __shared__ float4 sW1t[64][2];    // [j][i4]  (8 -> 64 layer, transposed)
    __shared__ float4 sW2t[64][16];   // [j][i4]  (64 -> 64 layer, transposed)
    __shared__ float4 sW3p[64][4];    // [j][p4]  (64 -> 15, padded to 16)
    __shared__ float sB1[64], sB2[64], sB3[16], sCG[CG_TOTAL];
    int tid = threadIdx.x, bs = blockDim.x;
    for (int i = tid; i < 8 * 64; i += bs) {
        int r = i / 64, j = i % 64;
        ((float*)&sW1t[j][0])[r] = fw1[i];
    }
    for (int i = tid; i < 64 * 64; i += bs) {
        int r = i / 64, j = i % 64;
        ((float*)&sW2t[j][0])[r] = fw2[i];
    }
    for (int i = tid; i < 64 * 16; i += bs) {
        int j = i >> 4, p = i & 15;
        ((float*)&sW3p[j][0])[p] = (p < NPATHS) ? fw3[j * NPATHS + p] : 0.0f;
    }
    for (int i = tid; i < 64; i += bs) { sB1[i] = fb1[i]; sB2[i] = fb2[i]; }
    for (int i = tid; i < 16; i += bs) sB3[i] = (i < NPATHS) ? fb3[i] : 0.0f;
    for (int i = tid; i < CG_TOTAL; i += bs) sCG[i] = g_cg[i];
    __syncthreads();

    int slot[2];
    slot[0] = blockIdx.x * 512 + tid;
    slot[1] = slot[0] + 256;
    bool val[2];
    val[0] = slot[0] < E;
    val[1] = slot[1] < E;

    float Yv[2][9];
    float len[2];
#pragma unroll
    for (int r = 0; r < 2; r++) {
        int e = val[r] ? g_eperm[slot[r]] : 0;
        int s = esrc[e], d = edst[e];
        // copy Ai of source into slot-ordered stream
        const float4* ap = (const float4*)(g_Ai + (size_t)s * 8);
        float4 a0 = ap[0], a1 = ap[1];
        if (val[r]) {
            float4* dst = (float4*)(g_AiS + (size_t)slot[r] * 8);
            dst[0] = a0; dst[1] = a1;
        }
        int b = batch[s];
        const float* cl = cell + b * 9;
        float sx = eshift[e * 3 + 0], sy = eshift[e * 3 + 1], sz = eshift[e * 3 + 2];
        float shx = sx * cl[0] + sy * cl[3] + sz * cl[6];
        float shy = sx * cl[1] + sy * cl[4] + sz * cl[7];
        float shz = sx * cl[2] + sy * cl[5] + sz * cl[8];
        float vx = pos[d * 3 + 0] - pos[s * 3 + 0] + shx;
        float vy = pos[d * 3 + 1] - pos[s * 3 + 1] + shy;
        float vz = pos[d * 3 + 2] - pos[s * 3 + 2] + shz;
        float L = sqrtf(vx * vx + vy * vy + vz * vz);
        len[r] = L;
        float il = 1.0f / fmaxf(L, 1e-8f);
        float nx = vx * il, ny = vy * il, nz = vz * il;
        const float s3 = 1.7320508075688772f;
        const float s15 = 3.872983346207417f;
        const float s5 = 2.23606797749979f;
        Yv[r][0] = 1.0f;
        Yv[r][1] = s3 * ny; Yv[r][2] = s3 * nz; Yv[r][3] = s3 * nx;
        Yv[r][4] = s15 * nx * ny;
        Yv[r][5] = s15 * ny * nz;
        Yv[r][6] = 0.5f * s5 * (3.0f * nz * nz - 1.0f);
        Yv[r][7] = s15 * nx * nz;
        Yv[r][8] = 0.5f * s15 * (nx * nx - ny * ny);
    }

    // radial basis
    float emb[2][8];
    const float step = 2.0f / 9.0f;
    const float istep = 4.5f;
    const float cemb = 2.8284271247461903f / 1.12f;
#pragma unroll
    for (int r = 0; r < 2; r++)
#pragma unroll
        for (int i = 0; i < 8; i++) {
            float t = (len[r] - (float)(i + 1) * step) * istep;
            emb[r][i] = __expf(-t * t) * cemb;
        }

    // layer 1: 8 -> 64 (float4 transposed weights)
    float h1[2][64];
#pragma unroll
    for (int j = 0; j < 64; j++) {
        float4 w0 = sW1t[j][0], w1v = sW1t[j][1];
        float ta = sB1[j], tb = ta;
        ta += emb[0][0] * w0.x + emb[0][1] * w0.y + emb[0][2] * w0.z + emb[0][3] * w0.w;
        ta += emb[0][4] * w1v.x + emb[0][5] * w1v.y + emb[0][6] * w1v.z + emb[0][7] * w1v.w;
        tb += emb[1][0] * w0.x + emb[1][1] * w0.y + emb[1][2] * w0.z + emb[1][3] * w0.w;
        tb += emb[1][4] * w1v.x + emb[1][5] * w1v.y + emb[1][6] * w1v.z + emb[1][7] * w1v.w;
        h1[0][j] = ta / (1.0f + __expf(-ta));
        h1[1][j] = tb / (1.0f + __expf(-tb));
    }

    // layers 2+3 fused
    float gp[2][16];
#pragma unroll
    for (int p = 0; p < 16; p++) { gp[0][p] = sB3[p]; gp[1][p] = sB3[p]; }
#pragma unroll 4
    for (int j = 0; j < 64; j++) {
        float ta = sB2[j], tb = ta;
#pragma unroll
        for (int i4 = 0; i4 < 16; i4++) {
            float4 w = sW2t[j][i4];
            ta += h1[0][i4 * 4 + 0] * w.x + h1[0][i4 * 4 + 1] * w.y +
                  h1[0][i4 * 4 + 2] * w.z + h1[0][i4 * 4 + 3] * w.w;
            tb += h1[1][i4 * 4 + 0] * w.x + h1[1][i4 * 4 + 1] * w.y +
                  h1[1][i4 * 4 + 2] * w.z + h1[1][i4 * 4 + 3] * w.w;
        }
        float sa = ta / (1.0f + __expf(-ta));
        float sb = tb / (1.0f + __expf(-tb));
#pragma unroll
        for (int p4 = 0; p4 < 4; p4++) {
            float4 w3 = sW3p[j][p4];
            gp[0][p4 * 4 + 0] += sa * w3.x;
            gp[0][p4 * 4 + 1] += sa * w3.y;
            gp[0][p4 * 4 + 2] += sa * w3.z;
            gp[0][p4 * 4 + 3] += sa * w3.w;
            gp[1][p4 * 4 + 0] += sb * w3.x;
            gp[1][p4 * 4 + 1] += sb * w3.y;
            gp[1][p4 * 4 + 2] += sb * w3.z;
            gp[1][p4 * 4 + 3] += sb * w3.w;
        }
    }
    const float ALP0 = 0.20412414523193154f;  // 1/sqrt(8*3)
    const float ALP1 = 0.14433756729740643f;  // 1/sqrt(8*6)
#pragma unroll
    for (int p = 0; p < NPATHS; p++) {
        float alpha = (PL3[p] == 0) ? ALP0 : ALP1;
        gp[0][p] *= alpha * inv_avg;
        gp[1][p] *= alpha * inv_avg;
    }

    // geometry: stream scaled values out, coalesced (geoS[pj][slot])
#pragma unroll
    for (int p = 0; p < NPATHS; p++) {
        const int l1 = PL1[p], l2 = PL2[p], l3 = PL3[p];
        const int o1 = LOFF[l1], o2 = LOFF[l2];
        const int n2d = 2 * l2 + 1, n3d = 2 * l3 + 1;
#pragma unroll
        for (int k = 0; k < 2 * l3 + 1; k++) {
            float acc0 = 0.0f, acc1 = 0.0f;
#pragma unroll
            for (int m = 0; m < 2 * l1 + 1; m++) {
#pragma unroll
                for (int n = 0; n < 2 * l2 + 1; n++) {
                    float cgv = sCG[CGO[p] + (m * n2d + n) * n3d + k];
                    acc0 += Yv[0][o1 + m] * Yv[0][o2 + n] * cgv;
                    acc1 += Yv[1][o1 + m] * Yv[1][o2 + n] * cgv;
                }
            }
            int j = GEOO[p] + k;
            if (val[0]) g_geoS[(size_t)j * E + slot[0]] = acc0 * gp[0][p];
            if (val[1]) g_geoS[(size_t)j * E + slot[1]] = acc1 * gp[1][p];
        }
    }
}

// ---------------------------------------------------------------------------
// Accumulate kernel: warp per node. Streams AiS + geoS over the node's slot
// range; builds S[n][m][pj] = sum_e Ai[m]*geoScaled[pj]. Purely sequential IO.
// ---------------------------------------------------------------------------
__global__ void __launch_bounds__(256) accum_kernel(int E, int N)
{
    int n = (blockIdx.x * blockDim.x + threadIdx.x) >> 5;
    int lane = threadIdx.x & 31;
    if (n >= N) return;
    int m = lane & 7;
    int q = lane >> 3;           // 0..3
    int base_pj = q * 13;        // pj 51 is a zero row (padding)
    int lo = g_off[n], hi = g_off[n + 1];

    float acc[13];
#pragma unroll
    for (int r = 0; r < 13; r++) acc[r] = 0.0f;

    int i = lo;
    for (; i + 1 < hi; i += 2) {
        float ai0 = g_AiS[(size_t)i * 8 + m];
        float ai1 = g_AiS[(size_t)(i + 1) * 8 + m];
#pragma unroll
        for (int r = 0; r < 13; r++) {
            const float* row = g_geoS + (size_t)(base_pj + r) * E;
            acc[r] += ai0 * row[i] + ai1 * row[i + 1];
        }
    }
    if (i < hi) {
        float ai0 = g_AiS[(size_t)i * 8 + m];
#pragma unroll
        for (int r = 0; r < 13; r++)
            acc[r] += ai0 * g_geoS[(size_t)(base_pj + r) * E + i];
    }

    float* srow = g_S + (size_t)n * 416 + m * 52 + base_pj;
#pragma unroll
    for (int r = 0; r < 13; r++) srow[r] = acc[r];
}

// ---------------------------------------------------------------------------
// Finalize kernel: thread per (node, channel). out[c][j] from S and tpw.
// ---------------------------------------------------------------------------
__global__ void __launch_bounds__(256) finalize_kernel(
    const float* __restrict__ tpw, float* __restrict__ out, int N)
{
    __shared__ float sTP[NPATHS * 8 * 16];
    __shared__ float sS[16][416];
    int tid = threadIdx.x;
    for (int i = tid; i < NPATHS * 8 * 16; i += 256) sTP[i] = tpw[i];
    int nodeBase = blockIdx.x * 16;
    for (int i = tid; i < 16 * 416; i += 256) {
        int le = i / 416, o = i - le * 416;
        int n = nodeBase + le;
        sS[le][o] = (n < N) ? g_S[(size_t)n * 416 + o] : 0.0f;
    }
    __syncthreads();

    int le = tid >> 4, c = tid & 15;
    int n = nodeBase + le;
    if (n >= N) return;
    const float* S = sS[le];
    float* orow = out + (size_t)n * 144;

    const int P0[3] = {0, 4, 12};
    const int G0[3] = {0, 12, 42};
    const int P1[6] = {1, 3, 5, 7, 10, 13};
    const int G1[6] = {1, 9, 13, 21, 34, 43};
    const int P2[6] = {2, 6, 8, 9, 11, 14};
    const int G2[6] = {4, 16, 24, 29, 37, 46};

    // l3 = 0
    {
        float a = 0.0f;
#pragma unroll
        for (int i = 0; i < 3; i++) {
            int p = P0[i], g = G0[i];
#pragma unroll
            for (int m = 0; m < 8; m++)
                a += sTP[(p * 8 + m) * 16 + c] * S[m * 52 + g];
        }
        orow[c] = a;
    }
    // l3 = 1
#pragma unroll
    for (int k = 0; k < 3; k++) {
        float a = 0.0f;
#pragma unroll
        for (int i = 0; i < 6; i++) {
            int p = P1[i], g = G1[i] + k;
#pragma unroll
            for (int m = 0; m < 8; m++)
                a += sTP[(p * 8 + m) * 16 + c] * S[m * 52 + g];
        }
        orow[16 + 3 * c + k] = a;
    }
    // l3 = 2
#pragma unroll
    for (int k = 0; k < 5; k++) {
        float a = 0.0f;
#pragma unroll
        for (int i = 0; i < 6; i++) {
            int p = P2[i], g = G2[i] + k;
#pragma unroll
            for (int m = 0; m < 8; m++)
                a += sTP[(p * 8 + m) * 16 + c] * S[m * 52 + g];
        }
        orow[64 + 5 * c + k] = a;
    }
}

// ---------------------------------------------------------------------------
extern "C" void kernel_launch(void* const* d_in, const int* in_sizes, int n_in,
                              void* d_out, int out_size)
{
    const float* pos    = (const float*)d_in[0];
    const int*   A      = (const int*)d_in[1];
    const int*   batch  = (const int*)d_in[2];
    const int*   esrc   = (const int*)d_in[3];
    const int*   edst   = (const int*)d_in[4];
    const float* eshift = (const float*)d_in[5];
    const float* cell   = (const float*)d_in[6];
    const float* embt   = (const float*)d_in[7];
    const float* mw1    = (const float*)d_in[8];
    const float* mb1    = (const float*)d_in[9];
    const float* mw2    = (const float*)d_in[10];
    const float* mb2    = (const float*)d_in[11];
    const float* fw1    = (const float*)d_in[12];
    const float* fb1    = (const float*)d_in[13];
    const float* fw2    = (const float*)d_in[14];
    const float* fb2    = (const float*)d_in[15];
    const float* fw3    = (const float*)d_in[16];
    const float* fb3    = (const float*)d_in[17];
    const float* tpw    = (const float*)d_in[18];
    float* out = (float*)d_out;

    int N = in_sizes[1];
    int E = in_sizes[3];
    float avg = (float)E / (float)N;
    float inv_avg = 1.0f / fmaxf(avg, 1e-8f);

    init_cg_kernel<<<1, 32>>>();
    zero_count_kernel<<<(NPAD + 255) / 256, 256>>>();
    node_kernel<<<(N + 255) / 256, 256>>>(embt, A, mw1, mb1, mw2, mb2, N);
    hist_kernel<<<(E + 255) / 256, 256>>>(edst, E);
    scan_kernel<<<1, SCAN_T>>>();
    scatter_kernel<<<(E + 255) / 256, 256>>>(edst, E);
    geo_kernel<<<(E + 511) / 512, 256>>>(pos, batch, esrc, edst, eshift, cell,
                                         fw1, fb1, fw2, fb2, fw3, fb3,
                                         E, inv_avg);
    accum_kernel<<<(N * 32 + 255) / 256, 256>>>(E, N);
    finalize_kernel<<<(N + 15) / 16, 256>>>(tpw, out, N);
}

// round 5
// speedup vs baseline: 5.2898x; 4.6681x over previous
#include <cuda_runtime.h>
#include <math.h>

#define NPATHS 15
#define CG_TOTAL 615
#define MAXE 1000000
#define NPAD 50176            // 1024 * 49
#define SCAN_T 1024
#define SCAN_CHUNK 49

// path tables: (l1,l2,l3) enumerated as in the reference (l1 outer, l2 mid, l3 inner)
__device__ constexpr int PL1[NPATHS]  = {0,0,0,1,1,1,1,1,1,2,2,2,2,2,2};
__device__ constexpr int PL2[NPATHS]  = {0,1,2,0,1,1,1,2,2,0,1,1,2,2,2};
__device__ constexpr int PL3[NPATHS]  = {0,1,2,1,0,1,2,1,2,2,1,2,0,1,2};
__device__ constexpr int CGO[NPATHS]  = {0,1,10,35,44,53,80,125,170,245,270,315,390,415,490};
__device__ constexpr int GEOO[NPATHS] = {0,1,4,9,12,13,16,21,24,29,34,37,42,43,46};
__device__ constexpr int LOFF[3] = {0,1,4};

__device__ float g_cg[CG_TOTAL];
__device__ __align__(16) float g_Ai[NPAD * 8];
__device__ __align__(16) float g_AiS[MAXE * 8];          // per sorted slot: Ai of src
__device__ float g_geoS[(size_t)52 * MAXE];              // [pj][slot]; row 51 stays 0
__device__ __align__(16) float g_S[(size_t)NPAD * 416];  // [node][m*52+pj]
__device__ int   g_count[NPAD];
__device__ int   g_off[NPAD + 1];
__device__ int   g_cursor[NPAD];
__device__ int   g_eperm[MAXE];

// ---------------------------------------------------------------------------
// CG init (device-side, double precision, replicates the reference)
// PARALLELIZED: 15 blocks (one per path) x 128 threads (one per element).
// ---------------------------------------------------------------------------
__device__ double dfact(int n) {
    double r = 1.0;
    for (int i = 2; i <= n; ++i) r *= (double)i;
    return r;
}

__device__ double cgc(int j1, int j2, int j3, int m1, int m2, int m3) {
    if (m1 + m2 != m3) return 0.0;
    double pre = sqrt((double)(2 * j3 + 1) * dfact(j3 + j1 - j2) * dfact(j3 - j1 + j2) *
                      dfact(j1 + j2 - j3) / dfact(j1 + j2 + j3 + 1));
    pre *= sqrt(dfact(j3 + m3) * dfact(j3 - m3) * dfact(j1 - m1) * dfact(j1 + m1) *
                dfact(j2 - m2) * dfact(j2 + m2));
    double s = 0.0;
    for (int k = 0; k <= j1 + j2 - j3; ++k) {
        int d1 = j1 + j2 - j3 - k, d2 = j1 - m1 - k, d3 = j2 + m2 - k;
        int d4 = j3 - j2 + m1 + k, d5 = j3 - j1 - m2 + k;
        if (d1 < 0 || d2 < 0 || d3 < 0 || d4 < 0 || d5 < 0) continue;
        double t = 1.0 / (dfact(k) * dfact(d1) * dfact(d2) * dfact(d3) * dfact(d4) * dfact(d5));
        s += (k & 1) ? -t : t;
    }
    return pre * s;
}

__device__ void buildq(int l, double qr[5][5], double qi[5][5]) {
    for (int a = 0; a < 5; a++)
        for (int b = 0; b < 5; b++) { qr[a][b] = 0.0; qi[a][b] = 0.0; }
    const double isq = sqrt(0.5);
    for (int m = -l; m < 0; m++) {
        qr[l + m][l - m] = isq;
        qi[l + m][l + m] = -isq;
    }
    qr[l][l] = 1.0;
    for (int m = 1; m <= l; m++) {
        double sg = (m & 1) ? -1.0 : 1.0;
        qr[l + m][l + m] = sg * isq;
        qi[l + m][l - m] = sg * isq;
    }
    if (l == 1) {
        for (int a = 0; a < 5; a++)
            for (int b = 0; b < 5; b++) {
                double r = qr[a][b], i0 = qi[a][b];
                qr[a][b] = i0;
                qi[a][b] = -r;
            }
    } else if (l == 2) {
        for (int a = 0; a < 5; a++)
            for (int b = 0; b < 5; b++) { qr[a][b] = -qr[a][b]; qi[a][b] = -qi[a][b]; }
    }
}

__global__ void __launch_bounds__(128) init_cg_kernel() {
    __shared__ double sq1r[5][5], sq1i[5][5];
    __shared__ double sq2r[5][5], sq2i[5][5];
    __shared__ double sq3r[5][5], sq3i[5][5];
    __shared__ float sAr[128], sAi[128];
    __shared__ int sUseRe;

    int p = blockIdx.x;
    int t = threadIdx.x;
    int l1 = PL1[p], l2 = PL2[p], l3 = PL3[p];
    int n1 = 2 * l1 + 1, n2 = 2 * l2 + 1, n3 = 2 * l3 + 1;
    int tot = n1 * n2 * n3;

    // threads 0..2 build the three q matrices into shared
    if (t < 3) {
        double qr[5][5], qi[5][5];
        int l = (t == 0) ? l1 : (t == 1) ? l2 : l3;
        buildq(l, qr, qi);
        double (*dr)[5] = (t == 0) ? sq1r : (t == 1) ? sq2r : sq3r;
        double (*di)[5] = (t == 0) ? sq1i : (t == 1) ? sq2i : sq3i;
        for (int a = 0; a < 5; a++)
            for (int b = 0; b < 5; b++) { dr[a][b] = qr[a][b]; di[a][b] = qi[a][b]; }
    }
    __syncthreads();

    double ar = 0.0, ai = 0.0;
    if (t < tot) {
        int i = t / (n2 * n3);
        int rem = t - i * (n2 * n3);
        int j = rem / n3;
        int k = rem - j * n3;
        for (int a = 0; a < n1; a++)
            for (int b = 0; b < n2; b++) {
                double t12r = sq1r[a][i] * sq2r[b][j] - sq1i[a][i] * sq2i[b][j];
                double t12i = sq1r[a][i] * sq2i[b][j] + sq1i[a][i] * sq2r[b][j];
                if (t12r == 0.0 && t12i == 0.0) continue;
                for (int c = 0; c < n3; c++) {
                    double C = cgc(l1, l2, l3, a - l1, b - l2, c - l3);
                    if (C == 0.0) continue;
                    double t3r = sq3r[c][k], t3i = -sq3i[c][k];  // conj
                    ar += (t12r * t3r - t12i * t3i) * C;
                    ai += (t12r * t3i + t12i * t3r) * C;
                }
            }
    }
    sAr[t] = (t < tot) ? (float)fabs(ar) : 0.0f;
    sAi[t] = (t < tot) ? (float)fabs(ai) : 0.0f;
    __syncthreads();
    if (t == 0) {
        float sr = 0.0f, si = 0.0f;
        for (int q = 0; q < tot; q++) { sr += sAr[q]; si += sAi[q]; }
        sUseRe = (sr >= si) ? 1 : 0;
    }
    __syncthreads();
    if (t < tot)
        g_cg[CGO[p] + t] = (float)(sUseRe ? ar : ai);
}

// ---------------------------------------------------------------------------
// Sorting machinery: zero -> hist -> scan -> scatter
// ---------------------------------------------------------------------------
__global__ void zero_count_kernel() {
    int i = blockIdx.x * blockDim.x + threadIdx.x;
    if (i < NPAD) g_count[i] = 0;
}

__global__ void hist_kernel(const int* __restrict__ edst, int E) {
    int e = blockIdx.x * blockDim.x + threadIdx.x;
    if (e < E) atomicAdd(&g_count[edst[e]], 1);
}

__global__ void __launch_bounds__(SCAN_T) scan_kernel() {
    __shared__ int ssum[SCAN_T];
    int t = threadIdx.x;
    int lo = t * SCAN_CHUNK;
    int hi = lo + SCAN_CHUNK;
    int s = 0;
    for (int i = lo; i < hi; i++) s += g_count[i];
    ssum[t] = s;
    __syncthreads();
    for (int d = 1; d < SCAN_T; d <<= 1) {
        int v = 0;
        if (t >= d) v = ssum[t - d];
        __syncthreads();
        if (t >= d) ssum[t] += v;
        __syncthreads();
    }
    int pre = (t == 0) ? 0 : ssum[t - 1];
    for (int i = lo; i < hi; i++) {
        g_off[i] = pre;
        g_cursor[i] = pre;
        pre += g_count[i];
    }
    if (t == SCAN_T - 1) g_off[NPAD] = pre;
}

__global__ void scatter_kernel(const int* __restrict__ edst, int E) {
    int e = blockIdx.x * blockDim.x + threadIdx.x;
    if (e >= E) return;
    int d = edst[e];
    int p = atomicAdd(&g_cursor[d], 1);
    g_eperm[p] = e;
}

// ---------------------------------------------------------------------------
// Node kernel: Ai only
// ---------------------------------------------------------------------------
__global__ void __launch_bounds__(256) node_kernel(
    const float* __restrict__ emb_table, const int* __restrict__ A,
    const float* __restrict__ w1, const float* __restrict__ b1,
    const float* __restrict__ w2, const float* __restrict__ b2, int N)
{
    __shared__ float sW1[16 * 64], sB1[64], sW2[64 * 8], sB2[8], sEmb[10 * 16];
    int tid = threadIdx.x, bs = blockDim.x;
    for (int i = tid; i < 16 * 64; i += bs) sW1[i] = w1[i];
    for (int i = tid; i < 64; i += bs) sB1[i] = b1[i];
    for (int i = tid; i < 64 * 8; i += bs) sW2[i] = w2[i];
    for (int i = tid; i < 8; i += bs) sB2[i] = b2[i];
    for (int i = tid; i < 10 * 16; i += bs) sEmb[i] = emb_table[i];
    __syncthreads();

    int n = blockIdx.x * bs + tid;
    if (n >= N) return;
    int a = A[n];
    float x[16];
#pragma unroll
    for (int i = 0; i < 16; i++) x[i] = sEmb[a * 16 + i];
    float h[64];
#pragma unroll
    for (int j = 0; j < 64; j++) {
        float t = sB1[j];
#pragma unroll
        for (int i = 0; i < 16; i++) t += x[i] * sW1[i * 64 + j];
        h[j] = t / (1.0f + __expf(-t));
    }
#pragma unroll
    for (int o = 0; o < 8; o++) {
        float t = sB2[o];
#pragma unroll
        for (int j = 0; j < 64; j++) t += h[j] * sW2[j * 8 + o];
        g_Ai[n * 8 + o] = t;
    }
}

// ---------------------------------------------------------------------------
// Geo kernel: sorted slots, 2 per thread. Gates MLP + scaled geometry.
// Writes geoS[pj][slot] (coalesced) and AiS[slot][8].
// ---------------------------------------------------------------------------
__global__ void __launch_bounds__(256) geo_kernel(
    const float* __restrict__ pos, const int* __restrict__ batch,
    const int* __restrict__ esrc, const int* __restrict__ edst,
    const float* __restrict__ eshift, const float* __restrict__ cell,
    const float* __restrict__ fw1, const float* __restrict__ fb1,
    const float* __restrict__ fw2, const float* __restrict__ fb2,
    const float* __restrict__ fw3, const float* __restrict__ fb3,
    int E, float inv_avg)
{
    __shared__ float4 sW1t[64][2];    // [j][i4]  (8 -> 64 layer, transposed)
    __shared__ float4 sW2t[64][16];   // [j][i4]  (64 -> 64 layer, transposed)
    __shared__ float4 sW3p[64][4];    // [j][p4]  (64 -> 15, padded to 16)
    __shared__ float sB1[64], sB2[64], sB3[16], sCG[CG_TOTAL];
    int tid = threadIdx.x, bs = blockDim.x;
    for (int i = tid; i < 8 * 64; i += bs) {
        int r = i / 64, j = i % 64;
        ((float*)&sW1t[j][0])[r] = fw1[i];
    }
    for (int i = tid; i < 64 * 64; i += bs) {
        int r = i / 64, j = i % 64;
        ((float*)&sW2t[j][0])[r] = fw2[i];
    }
    for (int i = tid; i < 64 * 16; i += bs) {
        int j = i >> 4, p = i & 15;
        ((float*)&sW3p[j][0])[p] = (p < NPATHS) ? fw3[j * NPATHS + p] : 0.0f;
    }
    for (int i = tid; i < 64; i += bs) { sB1[i] = fb1[i]; sB2[i] = fb2[i]; }
    for (int i = tid; i < 16; i += bs) sB3[i] = (i < NPATHS) ? fb3[i] : 0.0f;
    for (int i = tid; i < CG_TOTAL; i += bs) sCG[i] = g_cg[i];
    __syncthreads();

    int slot[2];
    slot[0] = blockIdx.x * 512 + tid;
    slot[1] = slot[0] + 256;
    bool val[2];
    val[0] = slot[0] < E;
    val[1] = slot[1] < E;

    float Yv[2][9];
    float len[2];
#pragma unroll
    for (int r = 0; r < 2; r++) {
        int e = val[r] ? g_eperm[slot[r]] : 0;
        int s = esrc[e], d = edst[e];
        // copy Ai of source into slot-ordered stream
        const float4* ap = (const float4*)(g_Ai + (size_t)s * 8);
        float4 a0 = ap[0], a1 = ap[1];
        if (val[r]) {
            float4* dst = (float4*)(g_AiS + (size_t)slot[r] * 8);
            dst[0] = a0; dst[1] = a1;
        }
        int b = batch[s];
        const float* cl = cell + b * 9;
        float sx = eshift[e * 3 + 0], sy = eshift[e * 3 + 1], sz = eshift[e * 3 + 2];
        float shx = sx * cl[0] + sy * cl[3] + sz * cl[6];
        float shy = sx * cl[1] + sy * cl[4] + sz * cl[7];
        float shz = sx * cl[2] + sy * cl[5] + sz * cl[8];
        float vx = pos[d * 3 + 0] - pos[s * 3 + 0] + shx;
        float vy = pos[d * 3 + 1] - pos[s * 3 + 1] + shy;
        float vz = pos[d * 3 + 2] - pos[s * 3 + 2] + shz;
        float L = sqrtf(vx * vx + vy * vy + vz * vz);
        len[r] = L;
        float il = 1.0f / fmaxf(L, 1e-8f);
        float nx = vx * il, ny = vy * il, nz = vz * il;
        const float s3 = 1.7320508075688772f;
        const float s15 = 3.872983346207417f;
        const float s5 = 2.23606797749979f;
        Yv[r][0] = 1.0f;
        Yv[r][1] = s3 * ny; Yv[r][2] = s3 * nz; Yv[r][3] = s3 * nx;
        Yv[r][4] = s15 * nx * ny;
        Yv[r][5] = s15 * ny * nz;
        Yv[r][6] = 0.5f * s5 * (3.0f * nz * nz - 1.0f);
        Yv[r][7] = s15 * nx * nz;
        Yv[r][8] = 0.5f * s15 * (nx * nx - ny * ny);
    }

    // radial basis
    float emb[2][8];
    const float step = 2.0f / 9.0f;
    const float istep = 4.5f;
    const float cemb = 2.8284271247461903f / 1.12f;
#pragma unroll
    for (int r = 0; r < 2; r++)
#pragma unroll
        for (int i = 0; i < 8; i++) {
            float t = (len[r] - (float)(i + 1) * step) * istep;
            emb[r][i] = __expf(-t * t) * cemb;
        }

    // layer 1: 8 -> 64 (float4 transposed weights)
    float h1[2][64];
#pragma unroll
    for (int j = 0; j < 64; j++) {
        float4 w0 = sW1t[j][0], w1v = sW1t[j][1];
        float ta = sB1[j], tb = ta;
        ta += emb[0][0] * w0.x + emb[0][1] * w0.y + emb[0][2] * w0.z + emb[0][3] * w0.w;
        ta += emb[0][4] * w1v.x + emb[0][5] * w1v.y + emb[0][6] * w1v.z + emb[0][7] * w1v.w;
        tb += emb[1][0] * w0.x + emb[1][1] * w0.y + emb[1][2] * w0.z + emb[1][3] * w0.w;
        tb += emb[1][4] * w1v.x + emb[1][5] * w1v.y + emb[1][6] * w1v.z + emb[1][7] * w1v.w;
        h1[0][j] = ta / (1.0f + __expf(-ta));
        h1[1][j] = tb / (1.0f + __expf(-tb));
    }

    // layers 2+3 fused
    float gp[2][16];
#pragma unroll
    for (int p = 0; p < 16; p++) { gp[0][p] = sB3[p]; gp[1][p] = sB3[p]; }
#pragma unroll 4
    for (int j = 0; j < 64; j++) {
        float ta = sB2[j], tb = ta;
#pragma unroll
        for (int i4 = 0; i4 < 16; i4++) {
            float4 w = sW2t[j][i4];
            ta += h1[0][i4 * 4 + 0] * w.x + h1[0][i4 * 4 + 1] * w.y +
                  h1[0][i4 * 4 + 2] * w.z + h1[0][i4 * 4 + 3] * w.w;
            tb += h1[1][i4 * 4 + 0] * w.x + h1[1][i4 * 4 + 1] * w.y +
                  h1[1][i4 * 4 + 2] * w.z + h1[1][i4 * 4 + 3] * w.w;
        }
        float sa = ta / (1.0f + __expf(-ta));
        float sb = tb / (1.0f + __expf(-tb));
#pragma unroll
        for (int p4 = 0; p4 < 4; p4++) {
            float4 w3 = sW3p[j][p4];
            gp[0][p4 * 4 + 0] += sa * w3.x;
            gp[0][p4 * 4 + 1] += sa * w3.y;
            gp[0][p4 * 4 + 2] += sa * w3.z;
            gp[0][p4 * 4 + 3] += sa * w3.w;
            gp[1][p4 * 4 + 0] += sb * w3.x;
            gp[1][p4 * 4 + 1] += sb * w3.y;
            gp[1][p4 * 4 + 2] += sb * w3.z;
            gp[1][p4 * 4 + 3] += sb * w3.w;
        }
    }
    const float ALP0 = 0.20412414523193154f;  // 1/sqrt(8*3)
    const float ALP1 = 0.14433756729740643f;  // 1/sqrt(8*6)
#pragma unroll
    for (int p = 0; p < NPATHS; p++) {
        float alpha = (PL3[p] == 0) ? ALP0 : ALP1;
        gp[0][p] *= alpha * inv_avg;
        gp[1][p] *= alpha * inv_avg;
    }

    // geometry: stream scaled values out, coalesced (geoS[pj][slot])
#pragma unroll
    for (int p = 0; p < NPATHS; p++) {
        const int l1 = PL1[p], l2 = PL2[p], l3 = PL3[p];
        const int o1 = LOFF[l1], o2 = LOFF[l2];
        const int n2d = 2 * l2 + 1, n3d = 2 * l3 + 1;
#pragma unroll
        for (int k = 0; k < 2 * l3 + 1; k++) {
            float acc0 = 0.0f, acc1 = 0.0f;
#pragma unroll
            for (int m = 0; m < 2 * l1 + 1; m++) {
#pragma unroll
                for (int n = 0; n < 2 * l2 + 1; n++) {
                    float cgv = sCG[CGO[p] + (m * n2d + n) * n3d + k];
                    acc0 += Yv[0][o1 + m] * Yv[0][o2 + n] * cgv;
                    acc1 += Yv[1][o1 + m] * Yv[1][o2 + n] * cgv;
                }
            }
            int j = GEOO[p] + k;
            if (val[0]) g_geoS[(size_t)j * E + slot[0]] = acc0 * gp[0][p];
            if (val[1]) g_geoS[(size_t)j * E + slot[1]] = acc1 * gp[1][p];
        }
    }
}

// ---------------------------------------------------------------------------
// Accumulate kernel: warp per node. Streams AiS + geoS over the node's slot
// range; builds S[n][m][pj] = sum_e Ai[m]*geoScaled[pj]. Purely sequential IO.
// ---------------------------------------------------------------------------
__global__ void __launch_bounds__(256) accum_kernel(int E, int N)
{
    int n = (blockIdx.x * blockDim.x + threadIdx.x) >> 5;
    int lane = threadIdx.x & 31;
    if (n >= N) return;
    int m = lane & 7;
    int q = lane >> 3;           // 0..3
    int base_pj = q * 13;        // pj 51 is a zero row (padding)
    int lo = g_off[n], hi = g_off[n + 1];

    float acc[13];
#pragma unroll
    for (int r = 0; r < 13; r++) acc[r] = 0.0f;

    int i = lo;
    for (; i + 1 < hi; i += 2) {
        float ai0 = g_AiS[(size_t)i * 8 + m];
        float ai1 = g_AiS[(size_t)(i + 1) * 8 + m];
#pragma unroll
        for (int r = 0; r < 13; r++) {
            const float* row = g_geoS + (size_t)(base_pj + r) * E;
            acc[r] += ai0 * row[i] + ai1 * row[i + 1];
        }
    }
    if (i < hi) {
        float ai0 = g_AiS[(size_t)i * 8 + m];
#pragma unroll
        for (int r = 0; r < 13; r++)
            acc[r] += ai0 * g_geoS[(size_t)(base_pj + r) * E + i];
    }

    float* srow = g_S + (size_t)n * 416 + m * 52 + base_pj;
#pragma unroll
    for (int r = 0; r < 13; r++) srow[r] = acc[r];
}

// ---------------------------------------------------------------------------
// Finalize kernel: thread per (node, channel). out[c][j] from S and tpw.
// ---------------------------------------------------------------------------
__global__ void __launch_bounds__(256) finalize_kernel(
    const float* __restrict__ tpw, float* __restrict__ out, int N)
{
    __shared__ float sTP[NPATHS * 8 * 16];
    __shared__ float sS[16][416];
    int tid = threadIdx.x;
    for (int i = tid; i < NPATHS * 8 * 16; i += 256) sTP[i] = tpw[i];
    int nodeBase = blockIdx.x * 16;
    for (int i = tid; i < 16 * 416; i += 256) {
        int le = i / 416, o = i - le * 416;
        int n = nodeBase + le;
        sS[le][o] = (n < N) ? g_S[(size_t)n * 416 + o] : 0.0f;
    }
    __syncthreads();

    int le = tid >> 4, c = tid & 15;
    int n = nodeBase + le;
    if (n >= N) return;
    const float* S = sS[le];
    float* orow = out + (size_t)n * 144;

    const int P0[3] = {0, 4, 12};
    const int G0[3] = {0, 12, 42};
    const int P1[6] = {1, 3, 5, 7, 10, 13};
    const int G1[6] = {1, 9, 13, 21, 34, 43};
    const int P2[6] = {2, 6, 8, 9, 11, 14};
    const int G2[6] = {4, 16, 24, 29, 37, 46};

    // l3 = 0
    {
        float a = 0.0f;
#pragma unroll
        for (int i = 0; i < 3; i++) {
            int p = P0[i], g = G0[i];
#pragma unroll
            for (int m = 0; m < 8; m++)
                a += sTP[(p * 8 + m) * 16 + c] * S[m * 52 + g];
        }
        orow[c] = a;
    }
    // l3 = 1
#pragma unroll
    for (int k = 0; k < 3; k++) {
        float a = 0.0f;
#pragma unroll
        for (int i = 0; i < 6; i++) {
            int p = P1[i], g = G1[i] + k;
#pragma unroll
            for (int m = 0; m < 8; m++)
                a += sTP[(p * 8 + m) * 16 + c] * S[m * 52 + g];
        }
        orow[16 + 3 * c + k] = a;
    }
    // l3 = 2
#pragma unroll
    for (int k = 0; k < 5; k++) {
        float a = 0.0f;
#pragma unroll
        for (int i = 0; i < 6; i++) {
            int p = P2[i], g = G2[i] + k;
#pragma unroll
            for (int m = 0; m < 8; m++)
                a += sTP[(p * 8 + m) * 16 + c] * S[m * 52 + g];
        }
        orow[64 + 5 * c + k] = a;
    }
}

// ---------------------------------------------------------------------------
extern "C" void kernel_launch(void* const* d_in, const int* in_sizes, int n_in,
                              void* d_out, int out_size)
{
    const float* pos    = (const float*)d_in[0];
    const int*   A      = (const int*)d_in[1];
    const int*   batch  = (const int*)d_in[2];
    const int*   esrc   = (const int*)d_in[3];
    const int*   edst   = (const int*)d_in[4];
    const float* eshift = (const float*)d_in[5];
    const float* cell   = (const float*)d_in[6];
    const float* embt   = (const float*)d_in[7];
    const float* mw1    = (const float*)d_in[8];
    const float* mb1    = (const float*)d_in[9];
    const float* mw2    = (const float*)d_in[10];
    const float* mb2    = (const float*)d_in[11];
    const float* fw1    = (const float*)d_in[12];
    const float* fb1    = (const float*)d_in[13];
    const float* fw2    = (const float*)d_in[14];
    const float* fb2    = (const float*)d_in[15];
    const float* fw3    = (const float*)d_in[16];
    const float* fb3    = (const float*)d_in[17];
    const float* tpw    = (const float*)d_in[18];
    float* out = (float*)d_out;

    int N = in_sizes[1];
    int E = in_sizes[3];
    float avg = (float)E / (float)N;
    float inv_avg = 1.0f / fmaxf(avg, 1e-8f);

    init_cg_kernel<<<NPATHS, 128>>>();
    zero_count_kernel<<<(NPAD + 255) / 256, 256>>>();
    node_kernel<<<(N + 255) / 256, 256>>>(embt, A, mw1, mb1, mw2, mb2, N);
    hist_kernel<<<(E + 255) / 256, 256>>>(edst, E);
    scan_kernel<<<1, SCAN_T>>>();
    scatter_kernel<<<(E + 255) / 256, 256>>>(edst, E);
    geo_kernel<<<(E + 511) / 512, 256>>>(pos, batch, esrc, edst, eshift, cell,
                                         fw1, fb1, fw2, fb2, fw3, fb3,
                                         E, inv_avg);
    accum_kernel<<<(N * 32 + 255) / 256, 256>>>(E, N);
    finalize_kernel<<<(N + 15) / 16, 256>>>(tpw, out, N);
}

// round 6
// speedup vs baseline: 8.7954x; 1.6627x over previous
#include <cuda_runtime.h>
#include <math.h>

#define NPATHS 15
#define CG_TOTAL 615
#define MAXE 1000000
#define NPAD 50176            // 1024 * 49
#define SCAN_T 1024
#define SCAN_CHUNK 49
#define TABN 16384            // gate table intervals over [0, 2]

// path tables: (l1,l2,l3) enumerated as in the reference (l1 outer, l2 mid, l3 inner)
__device__ constexpr int PL1[NPATHS]  = {0,0,0,1,1,1,1,1,1,2,2,2,2,2,2};
__device__ constexpr int PL2[NPATHS]  = {0,1,2,0,1,1,1,2,2,0,1,1,2,2,2};
__device__ constexpr int PL3[NPATHS]  = {0,1,2,1,0,1,2,1,2,2,1,2,0,1,2};
__device__ constexpr int CGO[NPATHS]  = {0,1,10,35,44,53,80,125,170,245,270,315,390,415,490};
__device__ constexpr int GEOO[NPATHS] = {0,1,4,9,12,13,16,21,24,29,34,37,42,43,46};
__device__ constexpr int LOFF[3] = {0,1,4};

__device__ float g_cg[CG_TOTAL];
__device__ __align__(16) float g_Ai[NPAD * 8];
__device__ __align__(16) float g_AiS[MAXE * 8];          // per sorted slot: Ai of src
__device__ float g_geoS[(size_t)52 * MAXE];              // [pj][slot]; row 51 stays 0
__device__ __align__(16) float g_S[(size_t)NPAD * 416];  // [node][m*52+pj]
__device__ __align__(16) float g_tab[(TABN + 1) * 16];   // gate table (alpha*inv_avg baked)
__device__ int   g_count[NPAD];
__device__ int   g_off[NPAD + 1];
__device__ int   g_cursor[NPAD];
__device__ int   g_eperm[MAXE];

// ---------------------------------------------------------------------------
// CG init (device-side, double precision, replicates the reference)
// 15 blocks (one per path) x 128 threads (one per element).
// ---------------------------------------------------------------------------
__device__ double dfact(int n) {
    double r = 1.0;
    for (int i = 2; i <= n; ++i) r *= (double)i;
    return r;
}

__device__ double cgc(int j1, int j2, int j3, int m1, int m2, int m3) {
    if (m1 + m2 != m3) return 0.0;
    double pre = sqrt((double)(2 * j3 + 1) * dfact(j3 + j1 - j2) * dfact(j3 - j1 + j2) *
                      dfact(j1 + j2 - j3) / dfact(j1 + j2 + j3 + 1));
    pre *= sqrt(dfact(j3 + m3) * dfact(j3 - m3) * dfact(j1 - m1) * dfact(j1 + m1) *
                dfact(j2 - m2) * dfact(j2 + m2));
    double s = 0.0;
    for (int k = 0; k <= j1 + j2 - j3; ++k) {
        int d1 = j1 + j2 - j3 - k, d2 = j1 - m1 - k, d3 = j2 + m2 - k;
        int d4 = j3 - j2 + m1 + k, d5 = j3 - j1 - m2 + k;
        if (d1 < 0 || d2 < 0 || d3 < 0 || d4 < 0 || d5 < 0) continue;
        double t = 1.0 / (dfact(k) * dfact(d1) * dfact(d2) * dfact(d3) * dfact(d4) * dfact(d5));
        s += (k & 1) ? -t : t;
    }
    return pre * s;
}

__device__ void buildq(int l, double qr[5][5], double qi[5][5]) {
    for (int a = 0; a < 5; a++)
        for (int b = 0; b < 5; b++) { qr[a][b] = 0.0; qi[a][b] = 0.0; }
    const double isq = sqrt(0.5);
    for (int m = -l; m < 0; m++) {
        qr[l + m][l - m] = isq;
        qi[l + m][l + m] = -isq;
    }
    qr[l][l] = 1.0;
    for (int m = 1; m <= l; m++) {
        double sg = (m & 1) ? -1.0 : 1.0;
        qr[l + m][l + m] = sg * isq;
        qi[l + m][l - m] = sg * isq;
    }
    if (l == 1) {
        for (int a = 0; a < 5; a++)
            for (int b = 0; b < 5; b++) {
                double r = qr[a][b], i0 = qi[a][b];
                qr[a][b] = i0;
                qi[a][b] = -r;
            }
    } else if (l == 2) {
        for (int a = 0; a < 5; a++)
            for (int b = 0; b < 5; b++) { qr[a][b] = -qr[a][b]; qi[a][b] = -qi[a][b]; }
    }
}

__global__ void __launch_bounds__(128) init_cg_kernel() {
    __shared__ double sq1r[5][5], sq1i[5][5];
    __shared__ double sq2r[5][5], sq2i[5][5];
    __shared__ double sq3r[5][5], sq3i[5][5];
    __shared__ float sAr[128], sAi[128];
    __shared__ int sUseRe;

    int p = blockIdx.x;
    int t = threadIdx.x;
    int l1 = PL1[p], l2 = PL2[p], l3 = PL3[p];
    int n1 = 2 * l1 + 1, n2 = 2 * l2 + 1, n3 = 2 * l3 + 1;
    int tot = n1 * n2 * n3;

    if (t < 3) {
        double qr[5][5], qi[5][5];
        int l = (t == 0) ? l1 : (t == 1) ? l2 : l3;
        buildq(l, qr, qi);
        double (*dr)[5] = (t == 0) ? sq1r : (t == 1) ? sq2r : sq3r;
        double (*di)[5] = (t == 0) ? sq1i : (t == 1) ? sq2i : sq3i;
        for (int a = 0; a < 5; a++)
            for (int b = 0; b < 5; b++) { dr[a][b] = qr[a][b]; di[a][b] = qi[a][b]; }
    }
    __syncthreads();

    double ar = 0.0, ai = 0.0;
    if (t < tot) {
        int i = t / (n2 * n3);
        int rem = t - i * (n2 * n3);
        int j = rem / n3;
        int k = rem - j * n3;
        for (int a = 0; a < n1; a++)
            for (int b = 0; b < n2; b++) {
                double t12r = sq1r[a][i] * sq2r[b][j] - sq1i[a][i] * sq2i[b][j];
                double t12i = sq1r[a][i] * sq2i[b][j] + sq1i[a][i] * sq2r[b][j];
                if (t12r == 0.0 && t12i == 0.0) continue;
                for (int c = 0; c < n3; c++) {
                    double C = cgc(l1, l2, l3, a - l1, b - l2, c - l3);
                    if (C == 0.0) continue;
                    double t3r = sq3r[c][k], t3i = -sq3i[c][k];  // conj
                    ar += (t12r * t3r - t12i * t3i) * C;
                    ai += (t12r * t3i + t12i * t3r) * C;
                }
            }
    }
    sAr[t] = (t < tot) ? (float)fabs(ar) : 0.0f;
    sAi[t] = (t < tot) ? (float)fabs(ai) : 0.0f;
    __syncthreads();
    if (t == 0) {
        float sr = 0.0f, si = 0.0f;
        for (int q = 0; q < tot; q++) { sr += sAr[q]; si += sAi[q]; }
        sUseRe = (sr >= si) ? 1 : 0;
    }
    __syncthreads();
    if (t < tot)
        g_cg[CGO[p] + t] = (float)(sUseRe ? ar : ai);
}

// ---------------------------------------------------------------------------
// Gate table: evaluate the radial MLP exactly at TABN+1 nodes over [0,2].
// alpha * inv_avg baked in.
// ---------------------------------------------------------------------------
__global__ void __launch_bounds__(256) gate_table_kernel(
    const float* __restrict__ fw1, const float* __restrict__ fb1,
    const float* __restrict__ fw2, const float* __restrict__ fb2,
    const float* __restrict__ fw3, const float* __restrict__ fb3,
    float inv_avg)
{
    __shared__ float sW1[8 * 64], sB1[64], sW2[64 * 64], sB2[64];
    __shared__ float sW3[64 * NPATHS], sB3[NPATHS];
    int tid = threadIdx.x, bs = blockDim.x;
    for (int i = tid; i < 8 * 64; i += bs) sW1[i] = fw1[i];
    for (int i = tid; i < 64; i += bs) { sB1[i] = fb1[i]; sB2[i] = fb2[i]; }
    for (int i = tid; i < 64 * 64; i += bs) sW2[i] = fw2[i];
    for (int i = tid; i < 64 * NPATHS; i += bs) sW3[i] = fw3[i];
    for (int i = tid; i < NPATHS; i += bs) sB3[i] = fb3[i];
    __syncthreads();

    int idx = blockIdx.x * bs + tid;
    if (idx > TABN) return;
    float len = (float)idx * (2.0f / (float)TABN);

    float emb[8];
    const float step = 2.0f / 9.0f;
    const float istep = 4.5f;
    const float cemb = 2.8284271247461903f / 1.12f;
#pragma unroll
    for (int i = 0; i < 8; i++) {
        float t = (len - (float)(i + 1) * step) * istep;
        emb[i] = __expf(-t * t) * cemb;
    }

    float h1[64];
#pragma unroll
    for (int j = 0; j < 64; j++) {
        float t = sB1[j];
#pragma unroll
        for (int i = 0; i < 8; i++) t += emb[i] * sW1[i * 64 + j];
        h1[j] = t / (1.0f + __expf(-t));
    }

    float gp[NPATHS];
#pragma unroll
    for (int p = 0; p < NPATHS; p++) gp[p] = sB3[p];
#pragma unroll 4
    for (int j = 0; j < 64; j++) {
        float t = sB2[j];
#pragma unroll
        for (int i = 0; i < 64; i++) t += h1[i] * sW2[i * 64 + j];
        float s = t / (1.0f + __expf(-t));
#pragma unroll
        for (int p = 0; p < NPATHS; p++) gp[p] += s * sW3[j * NPATHS + p];
    }

    const float ALP0 = 0.20412414523193154f;  // 1/sqrt(8*3)
    const float ALP1 = 0.14433756729740643f;  // 1/sqrt(8*6)
    float* row = g_tab + (size_t)idx * 16;
#pragma unroll
    for (int p = 0; p < NPATHS; p++) {
        float alpha = (PL3[p] == 0) ? ALP0 : ALP1;
        row[p] = gp[p] * alpha * inv_avg;
    }
    row[15] = 0.0f;
}

// ---------------------------------------------------------------------------
// Sorting machinery: zero -> hist -> scan -> scatter
// ---------------------------------------------------------------------------
__global__ void zero_count_kernel() {
    int i = blockIdx.x * blockDim.x + threadIdx.x;
    if (i < NPAD) g_count[i] = 0;
}

__global__ void hist_kernel(const int* __restrict__ edst, int E) {
    int e = blockIdx.x * blockDim.x + threadIdx.x;
    if (e < E) atomicAdd(&g_count[edst[e]], 1);
}

__global__ void __launch_bounds__(SCAN_T) scan_kernel() {
    __shared__ int ssum[SCAN_T];
    int t = threadIdx.x;
    int lo = t * SCAN_CHUNK;
    int hi = lo + SCAN_CHUNK;
    int s = 0;
    for (int i = lo; i < hi; i++) s += g_count[i];
    ssum[t] = s;
    __syncthreads();
    for (int d = 1; d < SCAN_T; d <<= 1) {
        int v = 0;
        if (t >= d) v = ssum[t - d];
        __syncthreads();
        if (t >= d) ssum[t] += v;
        __syncthreads();
    }
    int pre = (t == 0) ? 0 : ssum[t - 1];
    for (int i = lo; i < hi; i++) {
        g_off[i] = pre;
        g_cursor[i] = pre;
        pre += g_count[i];
    }
    if (t == SCAN_T - 1) g_off[NPAD] = pre;
}

__global__ void scatter_kernel(const int* __restrict__ edst, int E) {
    int e = blockIdx.x * blockDim.x + threadIdx.x;
    if (e >= E) return;
    int d = edst[e];
    int p = atomicAdd(&g_cursor[d], 1);
    g_eperm[p] = e;
}

// ---------------------------------------------------------------------------
// Node kernel: Ai only
// ---------------------------------------------------------------------------
__global__ void __launch_bounds__(256) node_kernel(
    const float* __restrict__ emb_table, const int* __restrict__ A,
    const float* __restrict__ w1, const float* __restrict__ b1,
    const float* __restrict__ w2, const float* __restrict__ b2, int N)
{
    __shared__ float sW1[16 * 64], sB1[64], sW2[64 * 8], sB2[8], sEmb[10 * 16];
    int tid = threadIdx.x, bs = blockDim.x;
    for (int i = tid; i < 16 * 64; i += bs) sW1[i] = w1[i];
    for (int i = tid; i < 64; i += bs) sB1[i] = b1[i];
    for (int i = tid; i < 64 * 8; i += bs) sW2[i] = w2[i];
    for (int i = tid; i < 8; i += bs) sB2[i] = b2[i];
    for (int i = tid; i < 10 * 16; i += bs) sEmb[i] = emb_table[i];
    __syncthreads();

    int n = blockIdx.x * bs + tid;
    if (n >= N) return;
    int a = A[n];
    float x[16];
#pragma unroll
    for (int i = 0; i < 16; i++) x[i] = sEmb[a * 16 + i];
    float h[64];
#pragma unroll
    for (int j = 0; j < 64; j++) {
        float t = sB1[j];
#pragma unroll
        for (int i = 0; i < 16; i++) t += x[i] * sW1[i * 64 + j];
        h[j] = t / (1.0f + __expf(-t));
    }
#pragma unroll
    for (int o = 0; o < 8; o++) {
        float t = sB2[o];
#pragma unroll
        for (int j = 0; j < 64; j++) t += h[j] * sW2[j * 8 + o];
        g_Ai[n * 8 + o] = t;
    }
}

// ---------------------------------------------------------------------------
// Geo kernel: 1 edge per thread. SH + table-interpolated gates + scaled
// geometry. Writes geoS[pj][slot] (coalesced) and AiS[slot][8].
// ---------------------------------------------------------------------------
__global__ void __launch_bounds__(256) geo_kernel(
    const float* __restrict__ pos, const int* __restrict__ batch,
    const int* __restrict__ esrc, const int* __restrict__ edst,
    const float* __restrict__ eshift, const float* __restrict__ cell,
    int E)
{
    __shared__ float sCG[CG_TOTAL];
    int tid = threadIdx.x;
    for (int i = tid; i < CG_TOTAL; i += 256) sCG[i] = g_cg[i];
    __syncthreads();

    int slot = blockIdx.x * 256 + tid;
    if (slot >= E) return;
    int e = g_eperm[slot];
    int s = esrc[e], d = edst[e];

    // copy Ai of source into slot-ordered stream
    {
        const float4* ap = (const float4*)(g_Ai + (size_t)s * 8);
        float4 a0 = ap[0], a1 = ap[1];
        float4* dst = (float4*)(g_AiS + (size_t)slot * 8);
        dst[0] = a0; dst[1] = a1;
    }

    int b = batch[s];
    const float* cl = cell + b * 9;
    float sx = eshift[e * 3 + 0], sy = eshift[e * 3 + 1], sz = eshift[e * 3 + 2];
    float shx = sx * cl[0] + sy * cl[3] + sz * cl[6];
    float shy = sx * cl[1] + sy * cl[4] + sz * cl[7];
    float shz = sx * cl[2] + sy * cl[5] + sz * cl[8];
    float vx = pos[d * 3 + 0] - pos[s * 3 + 0] + shx;
    float vy = pos[d * 3 + 1] - pos[s * 3 + 1] + shy;
    float vz = pos[d * 3 + 2] - pos[s * 3 + 2] + shz;
    float L = sqrtf(vx * vx + vy * vy + vz * vz);
    float il = 1.0f / fmaxf(L, 1e-8f);
    float nx = vx * il, ny = vy * il, nz = vz * il;

    float Yv[9];
    const float s3 = 1.7320508075688772f;
    const float s15 = 3.872983346207417f;
    const float s5 = 2.23606797749979f;
    Yv[0] = 1.0f;
    Yv[1] = s3 * ny; Yv[2] = s3 * nz; Yv[3] = s3 * nx;
    Yv[4] = s15 * nx * ny;
    Yv[5] = s15 * ny * nz;
    Yv[6] = 0.5f * s5 * (3.0f * nz * nz - 1.0f);
    Yv[7] = s15 * nx * nz;
    Yv[8] = 0.5f * s15 * (nx * nx - ny * ny);

    // gates via table lerp (alpha * inv_avg already baked in)
    float gp[16];
    {
        float t = L * ((float)TABN / 2.0f);
        int i0 = (int)t;
        i0 = min(i0, TABN - 1);
        float f = t - (float)i0;
        const float4* t0 = (const float4*)(g_tab + (size_t)i0 * 16);
        const float4* t1 = (const float4*)(g_tab + (size_t)(i0 + 1) * 16);
#pragma unroll
        for (int q = 0; q < 4; q++) {
            float4 a = t0[q], c = t1[q];
            gp[q * 4 + 0] = a.x + f * (c.x - a.x);
            gp[q * 4 + 1] = a.y + f * (c.y - a.y);
            gp[q * 4 + 2] = a.z + f * (c.z - a.z);
            gp[q * 4 + 3] = a.w + f * (c.w - a.w);
        }
    }

    // geometry: stream scaled values out, coalesced (geoS[pj][slot])
#pragma unroll
    for (int p = 0; p < NPATHS; p++) {
        const int l1 = PL1[p], l2 = PL2[p], l3 = PL3[p];
        const int o1 = LOFF[l1], o2 = LOFF[l2];
        const int n2d = 2 * l2 + 1, n3d = 2 * l3 + 1;
#pragma unroll
        for (int k = 0; k < 2 * l3 + 1; k++) {
            float acc = 0.0f;
#pragma unroll
            for (int m = 0; m < 2 * l1 + 1; m++) {
#pragma unroll
                for (int n = 0; n < 2 * l2 + 1; n++) {
                    acc += Yv[o1 + m] * Yv[o2 + n] * sCG[CGO[p] + (m * n2d + n) * n3d + k];
                }
            }
            int j = GEOO[p] + k;
            g_geoS[(size_t)j * E + slot] = acc * gp[p];
        }
    }
}

// ---------------------------------------------------------------------------
// Accumulate kernel: warp per node. Streams AiS + geoS over the node's slot
// range; builds S[n][m][pj] = sum_e Ai[m]*geoScaled[pj]. Purely sequential IO.
// ---------------------------------------------------------------------------
__global__ void __launch_bounds__(256) accum_kernel(int E, int N)
{
    int n = (blockIdx.x * blockDim.x + threadIdx.x) >> 5;
    int lane = threadIdx.x & 31;
    if (n >= N) return;
    int m = lane & 7;
    int q = lane >> 3;           // 0..3
    int base_pj = q * 13;        // pj 51 is a zero row (padding)
    int lo = g_off[n], hi = g_off[n + 1];

    float acc[13];
#pragma unroll
    for (int r = 0; r < 13; r++) acc[r] = 0.0f;

    int i = lo;
    for (; i + 1 < hi; i += 2) {
        float ai0 = g_AiS[(size_t)i * 8 + m];
        float ai1 = g_AiS[(size_t)(i + 1) * 8 + m];
#pragma unroll
        for (int r = 0; r < 13; r++) {
            const float* row = g_geoS + (size_t)(base_pj + r) * E;
            acc[r] += ai0 * row[i] + ai1 * row[i + 1];
        }
    }
    if (i < hi) {
        float ai0 = g_AiS[(size_t)i * 8 + m];
#pragma unroll
        for (int r = 0; r < 13; r++)
            acc[r] += ai0 * g_geoS[(size_t)(base_pj + r) * E + i];
    }

    float* srow = g_S + (size_t)n * 416 + m * 52 + base_pj;
#pragma unroll
    for (int r = 0; r < 13; r++) srow[r] = acc[r];
}

// ---------------------------------------------------------------------------
// Finalize kernel: thread per (node, channel). out[c][j] from S and tpw.
// ---------------------------------------------------------------------------
__global__ void __launch_bounds__(256) finalize_kernel(
    const float* __restrict__ tpw, float* __restrict__ out, int N)
{
    __shared__ float sTP[NPATHS * 8 * 16];
    __shared__ float sS[16][416];
    int tid = threadIdx.x;
    for (int i = tid; i < NPATHS * 8 * 16; i += 256) sTP[i] = tpw[i];
    int nodeBase = blockIdx.x * 16;
    for (int i = tid; i < 16 * 416; i += 256) {
        int le = i / 416, o = i - le * 416;
        int n = nodeBase + le;
        sS[le][o] = (n < N) ? g_S[(size_t)n * 416 + o] : 0.0f;
    }
    __syncthreads();

    int le = tid >> 4, c = tid & 15;
    int n = nodeBase + le;
    if (n >= N) return;
    const float* S = sS[le];
    float* orow = out + (size_t)n * 144;

    const int P0[3] = {0, 4, 12};
    const int G0[3] = {0, 12, 42};
    const int P1[6] = {1, 3, 5, 7, 10, 13};
    const int G1[6] = {1, 9, 13, 21, 34, 43};
    const int P2[6] = {2, 6, 8, 9, 11, 14};
    const int G2[6] = {4, 16, 24, 29, 37, 46};

    // l3 = 0
    {
        float a = 0.0f;
#pragma unroll
        for (int i = 0; i < 3; i++) {
            int p = P0[i], g = G0[i];
#pragma unroll
            for (int m = 0; m < 8; m++)
                a += sTP[(p * 8 + m) * 16 + c] * S[m * 52 + g];
        }
        orow[c] = a;
    }
    // l3 = 1
#pragma unroll
    for (int k = 0; k < 3; k++) {
        float a = 0.0f;
#pragma unroll
        for (int i = 0; i < 6; i++) {
            int p = P1[i], g = G1[i] + k;
#pragma unroll
            for (int m = 0; m < 8; m++)
                a += sTP[(p * 8 + m) * 16 + c] * S[m * 52 + g];
        }
        orow[16 + 3 * c + k] = a;
    }
    // l3 = 2
#pragma unroll
    for (int k = 0; k < 5; k++) {
        float a = 0.0f;
#pragma unroll
        for (int i = 0; i < 6; i++) {
            int p = P2[i], g = G2[i] + k;
#pragma unroll
            for (int m = 0; m < 8; m++)
                a += sTP[(p * 8 + m) * 16 + c] * S[m * 52 + g];
        }
        orow[64 + 5 * c + k] = a;
    }
}

// ---------------------------------------------------------------------------
extern "C" void kernel_launch(void* const* d_in, const int* in_sizes, int n_in,
                              void* d_out, int out_size)
{
    const float* pos    = (const float*)d_in[0];
    const int*   A      = (const int*)d_in[1];
    const int*   batch  = (const int*)d_in[2];
    const int*   esrc   = (const int*)d_in[3];
    const int*   edst   = (const int*)d_in[4];
    const float* eshift = (const float*)d_in[5];
    const float* cell   = (const float*)d_in[6];
    const float* embt   = (const float*)d_in[7];
    const float* mw1    = (const float*)d_in[8];
    const float* mb1    = (const float*)d_in[9];
    const float* mw2    = (const float*)d_in[10];
    const float* mb2    = (const float*)d_in[11];
    const float* fw1    = (const float*)d_in[12];
    const float* fb1    = (const float*)d_in[13];
    const float* fw2    = (const float*)d_in[14];
    const float* fb2    = (const float*)d_in[15];
    const float* fw3    = (const float*)d_in[16];
    const float* fb3    = (const float*)d_in[17];
    const float* tpw    = (const float*)d_in[18];
    float* out = (float*)d_out;

    int N = in_sizes[1];
    int E = in_sizes[3];
    float avg = (float)E / (float)N;
    float inv_avg = 1.0f / fmaxf(avg, 1e-8f);

    init_cg_kernel<<<NPATHS, 128>>>();
    zero_count_kernel<<<(NPAD + 255) / 256, 256>>>();
    gate_table_kernel<<<(TABN + 256) / 256, 256>>>(fw1, fb1, fw2, fb2, fw3, fb3, inv_avg);
    node_kernel<<<(N + 255) / 256, 256>>>(embt, A, mw1, mb1, mw2, mb2, N);
    hist_kernel<<<(E + 255) / 256, 256>>>(edst, E);
    scan_kernel<<<1, SCAN_T>>>();
    scatter_kernel<<<(E + 255) / 256, 256>>>(edst, E);
    geo_kernel<<<(E + 255) / 256, 256>>>(pos, batch, esrc, edst, eshift, cell, E);
    accum_kernel<<<(N * 32 + 255) / 256, 256>>>(E, N);
    finalize_kernel<<<(N + 15) / 16, 256>>>(tpw, out, N);
}

// round 7
// speedup vs baseline: 9.6132x; 1.0930x over previous
#include <cuda_runtime.h>
#include <math.h>

#define NPATHS 15
#define CG_TOTAL 615
#define MAXE 1000000
#define NPAD 50176            // 1024 * 49
#define SCAN_T 1024
#define SCAN_CHUNK 49
#define TABN 16384            // gate table intervals over [0, 2]

// path tables: (l1,l2,l3) enumerated as in the reference (l1 outer, l2 mid, l3 inner)
__device__ constexpr int PL1[NPATHS]  = {0,0,0,1,1,1,1,1,1,2,2,2,2,2,2};
__device__ constexpr int PL2[NPATHS]  = {0,1,2,0,1,1,1,2,2,0,1,1,2,2,2};
__device__ constexpr int PL3[NPATHS]  = {0,1,2,1,0,1,2,1,2,2,1,2,0,1,2};
__device__ constexpr int CGO[NPATHS]  = {0,1,10,35,44,53,80,125,170,245,270,315,390,415,490};
__device__ constexpr int GEOO[NPATHS] = {0,1,4,9,12,13,16,21,24,29,34,37,42,43,46};
__device__ constexpr int LOFF[3] = {0,1,4};

__device__ float g_cg[CG_TOTAL];
__device__ __align__(16) float g_Ai[NPAD * 8];
__device__ __align__(16) float g_AiSt[(size_t)8 * MAXE];   // [m][slot]
__device__ __align__(16) float g_geoS[(size_t)52 * MAXE];  // [pj][slot]; row 51 stays 0
__device__ __align__(16) float g_S[(size_t)NPAD * 416];    // [node][m*52+pj]
__device__ __align__(16) float g_tab[(TABN + 1) * 16];     // gate table (alpha*inv_avg baked)
__device__ int   g_count[NPAD];
__device__ int   g_off[NPAD + 1];
__device__ int   g_cursor[NPAD];
__device__ int   g_eperm[MAXE];

// ---------------------------------------------------------------------------
// CG init (device-side, double precision, replicates the reference)
// 15 blocks (one per path) x 128 threads (one per element).
// ---------------------------------------------------------------------------
__device__ double dfact(int n) {
    double r = 1.0;
    for (int i = 2; i <= n; ++i) r *= (double)i;
    return r;
}

__device__ double cgc(int j1, int j2, int j3, int m1, int m2, int m3) {
    if (m1 + m2 != m3) return 0.0;
    double pre = sqrt((double)(2 * j3 + 1) * dfact(j3 + j1 - j2) * dfact(j3 - j1 + j2) *
                      dfact(j1 + j2 - j3) / dfact(j1 + j2 + j3 + 1));
    pre *= sqrt(dfact(j3 + m3) * dfact(j3 - m3) * dfact(j1 - m1) * dfact(j1 + m1) *
                dfact(j2 - m2) * dfact(j2 + m2));
    double s = 0.0;
    for (int k = 0; k <= j1 + j2 - j3; ++k) {
        int d1 = j1 + j2 - j3 - k, d2 = j1 - m1 - k, d3 = j2 + m2 - k;
        int d4 = j3 - j2 + m1 + k, d5 = j3 - j1 - m2 + k;
        if (d1 < 0 || d2 < 0 || d3 < 0 || d4 < 0 || d5 < 0) continue;
        double t = 1.0 / (dfact(k) * dfact(d1) * dfact(d2) * dfact(d3) * dfact(d4) * dfact(d5));
        s += (k & 1) ? -t : t;
    }
    return pre * s;
}

__device__ void buildq(int l, double qr[5][5], double qi[5][5]) {
    for (int a = 0; a < 5; a++)
        for (int b = 0; b < 5; b++) { qr[a][b] = 0.0; qi[a][b] = 0.0; }
    const double isq = sqrt(0.5);
    for (int m = -l; m < 0; m++) {
        qr[l + m][l - m] = isq;
        qi[l + m][l + m] = -isq;
    }
    qr[l][l] = 1.0;
    for (int m = 1; m <= l; m++) {
        double sg = (m & 1) ? -1.0 : 1.0;
        qr[l + m][l + m] = sg * isq;
        qi[l + m][l - m] = sg * isq;
    }
    if (l == 1) {
        for (int a = 0; a < 5; a++)
            for (int b = 0; b < 5; b++) {
                double r = qr[a][b], i0 = qi[a][b];
                qr[a][b] = i0;
                qi[a][b] = -r;
            }
    } else if (l == 2) {
        for (int a = 0; a < 5; a++)
            for (int b = 0; b < 5; b++) { qr[a][b] = -qr[a][b]; qi[a][b] = -qi[a][b]; }
    }
}

__global__ void __launch_bounds__(128) init_cg_kernel() {
    __shared__ double sq1r[5][5], sq1i[5][5];
    __shared__ double sq2r[5][5], sq2i[5][5];
    __shared__ double sq3r[5][5], sq3i[5][5];
    __shared__ float sAr[128], sAi[128];
    __shared__ int sUseRe;

    int p = blockIdx.x;
    int t = threadIdx.x;
    int l1 = PL1[p], l2 = PL2[p], l3 = PL3[p];
    int n1 = 2 * l1 + 1, n2 = 2 * l2 + 1, n3 = 2 * l3 + 1;
    int tot = n1 * n2 * n3;

    if (t < 3) {
        double qr[5][5], qi[5][5];
        int l = (t == 0) ? l1 : (t == 1) ? l2 : l3;
        buildq(l, qr, qi);
        double (*dr)[5] = (t == 0) ? sq1r : (t == 1) ? sq2r : sq3r;
        double (*di)[5] = (t == 0) ? sq1i : (t == 1) ? sq2i : sq3i;
        for (int a = 0; a < 5; a++)
            for (int b = 0; b < 5; b++) { dr[a][b] = qr[a][b]; di[a][b] = qi[a][b]; }
    }
    __syncthreads();

    double ar = 0.0, ai = 0.0;
    if (t < tot) {
        int i = t / (n2 * n3);
        int rem = t - i * (n2 * n3);
        int j = rem / n3;
        int k = rem - j * n3;
        for (int a = 0; a < n1; a++)
            for (int b = 0; b < n2; b++) {
                double t12r = sq1r[a][i] * sq2r[b][j] - sq1i[a][i] * sq2i[b][j];
                double t12i = sq1r[a][i] * sq2i[b][j] + sq1i[a][i] * sq2r[b][j];
                if (t12r == 0.0 && t12i == 0.0) continue;
                for (int c = 0; c < n3; c++) {
                    double C = cgc(l1, l2, l3, a - l1, b - l2, c - l3);
                    if (C == 0.0) continue;
                    double t3r = sq3r[c][k], t3i = -sq3i[c][k];  // conj
                    ar += (t12r * t3r - t12i * t3i) * C;
                    ai += (t12r * t3i + t12i * t3r) * C;
                }
            }
    }
    sAr[t] = (t < tot) ? (float)fabs(ar) : 0.0f;
    sAi[t] = (t < tot) ? (float)fabs(ai) : 0.0f;
    __syncthreads();
    if (t == 0) {
        float sr = 0.0f, si = 0.0f;
        for (int q = 0; q < tot; q++) { sr += sAr[q]; si += sAi[q]; }
        sUseRe = (sr >= si) ? 1 : 0;
    }
    __syncthreads();
    if (t < tot)
        g_cg[CGO[p] + t] = (float)(sUseRe ? ar : ai);
}

// ---------------------------------------------------------------------------
// Gate table: evaluate the radial MLP exactly at TABN+1 nodes over [0,2].
// alpha * inv_avg baked in.
// ---------------------------------------------------------------------------
__global__ void __launch_bounds__(256) gate_table_kernel(
    const float* __restrict__ fw1, const float* __restrict__ fb1,
    const float* __restrict__ fw2, const float* __restrict__ fb2,
    const float* __restrict__ fw3, const float* __restrict__ fb3,
    float inv_avg)
{
    __shared__ float sW1[8 * 64], sB1[64], sW2[64 * 64], sB2[64];
    __shared__ float sW3[64 * NPATHS], sB3[NPATHS];
    int tid = threadIdx.x, bs = blockDim.x;
    for (int i = tid; i < 8 * 64; i += bs) sW1[i] = fw1[i];
    for (int i = tid; i < 64; i += bs) { sB1[i] = fb1[i]; sB2[i] = fb2[i]; }
    for (int i = tid; i < 64 * 64; i += bs) sW2[i] = fw2[i];
    for (int i = tid; i < 64 * NPATHS; i += bs) sW3[i] = fw3[i];
    for (int i = tid; i < NPATHS; i += bs) sB3[i] = fb3[i];
    __syncthreads();

    int idx = blockIdx.x * bs + tid;
    if (idx > TABN) return;
    float len = (float)idx * (2.0f / (float)TABN);

    float emb[8];
    const float step = 2.0f / 9.0f;
    const float istep = 4.5f;
    const float cemb = 2.8284271247461903f / 1.12f;
#pragma unroll
    for (int i = 0; i < 8; i++) {
        float t = (len - (float)(i + 1) * step) * istep;
        emb[i] = __expf(-t * t) * cemb;
    }

    float h1[64];
#pragma unroll
    for (int j = 0; j < 64; j++) {
        float t = sB1[j];
#pragma unroll
        for (int i = 0; i < 8; i++) t += emb[i] * sW1[i * 64 + j];
        h1[j] = t / (1.0f + __expf(-t));
    }

    float gp[NPATHS];
#pragma unroll
    for (int p = 0; p < NPATHS; p++) gp[p] = sB3[p];
#pragma unroll 4
    for (int j = 0; j < 64; j++) {
        float t = sB2[j];
#pragma unroll
        for (int i = 0; i < 64; i++) t += h1[i] * sW2[i * 64 + j];
        float s = t / (1.0f + __expf(-t));
#pragma unroll
        for (int p = 0; p < NPATHS; p++) gp[p] += s * sW3[j * NPATHS + p];
    }

    const float ALP0 = 0.20412414523193154f;  // 1/sqrt(8*3)
    const float ALP1 = 0.14433756729740643f;  // 1/sqrt(8*6)
    float* row = g_tab + (size_t)idx * 16;
#pragma unroll
    for (int p = 0; p < NPATHS; p++) {
        float alpha = (PL3[p] == 0) ? ALP0 : ALP1;
        row[p] = gp[p] * alpha * inv_avg;
    }
    row[15] = 0.0f;
}

// ---------------------------------------------------------------------------
// Sorting machinery: zero -> hist -> scan -> scatter
// ---------------------------------------------------------------------------
__global__ void zero_count_kernel() {
    int i = blockIdx.x * blockDim.x + threadIdx.x;
    if (i < NPAD) g_count[i] = 0;
}

__global__ void hist_kernel(const int* __restrict__ edst, int E) {
    int e = blockIdx.x * blockDim.x + threadIdx.x;
    if (e < E) atomicAdd(&g_count[edst[e]], 1);
}

__global__ void __launch_bounds__(SCAN_T) scan_kernel() {
    __shared__ int ssum[SCAN_T];
    int t = threadIdx.x;
    int lo = t * SCAN_CHUNK;
    int hi = lo + SCAN_CHUNK;
    int s = 0;
    for (int i = lo; i < hi; i++) s += g_count[i];
    ssum[t] = s;
    __syncthreads();
    for (int d = 1; d < SCAN_T; d <<= 1) {
        int v = 0;
        if (t >= d) v = ssum[t - d];
        __syncthreads();
        if (t >= d) ssum[t] += v;
        __syncthreads();
    }
    int pre = (t == 0) ? 0 : ssum[t - 1];
    for (int i = lo; i < hi; i++) {
        g_off[i] = pre;
        g_cursor[i] = pre;
        pre += g_count[i];
    }
    if (t == SCAN_T - 1) g_off[NPAD] = pre;
}

__global__ void scatter_kernel(const int* __restrict__ edst, int E) {
    int e = blockIdx.x * blockDim.x + threadIdx.x;
    if (e >= E) return;
    int d = edst[e];
    int p = atomicAdd(&g_cursor[d], 1);
    g_eperm[p] = e;
}

// ---------------------------------------------------------------------------
// Node kernel: Ai only
// ---------------------------------------------------------------------------
__global__ void __launch_bounds__(256) node_kernel(
    const float* __restrict__ emb_table, const int* __restrict__ A,
    const float* __restrict__ w1, const float* __restrict__ b1,
    const float* __restrict__ w2, const float* __restrict__ b2, int N)
{
    __shared__ float sW1[16 * 64], sB1[64], sW2[64 * 8], sB2[8], sEmb[10 * 16];
    int tid = threadIdx.x, bs = blockDim.x;
    for (int i = tid; i < 16 * 64; i += bs) sW1[i] = w1[i];
    for (int i = tid; i < 64; i += bs) sB1[i] = b1[i];
    for (int i = tid; i < 64 * 8; i += bs) sW2[i] = w2[i];
    for (int i = tid; i < 8; i += bs) sB2[i] = b2[i];
    for (int i = tid; i < 10 * 16; i += bs) sEmb[i] = emb_table[i];
    __syncthreads();

    int n = blockIdx.x * bs + tid;
    if (n >= N) return;
    int a = A[n];
    float x[16];
#pragma unroll
    for (int i = 0; i < 16; i++) x[i] = sEmb[a * 16 + i];
    float h[64];
#pragma unroll
    for (int j = 0; j < 64; j++) {
        float t = sB1[j];
#pragma unroll
        for (int i = 0; i < 16; i++) t += x[i] * sW1[i * 64 + j];
        h[j] = t / (1.0f + __expf(-t));
    }
#pragma unroll
    for (int o = 0; o < 8; o++) {
        float t = sB2[o];
#pragma unroll
        for (int j = 0; j < 64; j++) t += h[j] * sW2[j * 8 + o];
        g_Ai[n * 8 + o] = t;
    }
}

// ---------------------------------------------------------------------------
// Geo kernel: 1 edge per thread. SH + table-interpolated gates + scaled
// geometry. Writes geoS[pj][slot] (coalesced) and AiSt[m][slot] (coalesced).
// ---------------------------------------------------------------------------
__global__ void __launch_bounds__(256) geo_kernel(
    const float* __restrict__ pos, const int* __restrict__ batch,
    const int* __restrict__ esrc, const int* __restrict__ edst,
    const float* __restrict__ eshift, const float* __restrict__ cell,
    int E)
{
    __shared__ float sCG[CG_TOTAL];
    int tid = threadIdx.x;
    for (int i = tid; i < CG_TOTAL; i += 256) sCG[i] = g_cg[i];
    __syncthreads();

    int slot = blockIdx.x * 256 + tid;
    if (slot >= E) return;
    int e = g_eperm[slot];
    int s = esrc[e], d = edst[e];

    // copy Ai of source into transposed slot-ordered stream [m][slot]
    {
        const float4* ap = (const float4*)(g_Ai + (size_t)s * 8);
        float4 a0 = ap[0], a1 = ap[1];
        g_AiSt[(size_t)0 * MAXE + slot] = a0.x;
        g_AiSt[(size_t)1 * MAXE + slot] = a0.y;
        g_AiSt[(size_t)2 * MAXE + slot] = a0.z;
        g_AiSt[(size_t)3 * MAXE + slot] = a0.w;
        g_AiSt[(size_t)4 * MAXE + slot] = a1.x;
        g_AiSt[(size_t)5 * MAXE + slot] = a1.y;
        g_AiSt[(size_t)6 * MAXE + slot] = a1.z;
        g_AiSt[(size_t)7 * MAXE + slot] = a1.w;
    }

    int b = batch[s];
    const float* cl = cell + b * 9;
    float sx = eshift[e * 3 + 0], sy = eshift[e * 3 + 1], sz = eshift[e * 3 + 2];
    float shx = sx * cl[0] + sy * cl[3] + sz * cl[6];
    float shy = sx * cl[1] + sy * cl[4] + sz * cl[7];
    float shz = sx * cl[2] + sy * cl[5] + sz * cl[8];
    float vx = pos[d * 3 + 0] - pos[s * 3 + 0] + shx;
    float vy = pos[d * 3 + 1] - pos[s * 3 + 1] + shy;
    float vz = pos[d * 3 + 2] - pos[s * 3 + 2] + shz;
    float L = sqrtf(vx * vx + vy * vy + vz * vz);
    float il = 1.0f / fmaxf(L, 1e-8f);
    float nx = vx * il, ny = vy * il, nz = vz * il;

    float Yv[9];
    const float s3 = 1.7320508075688772f;
    const float s15 = 3.872983346207417f;
    const float s5 = 2.23606797749979f;
    Yv[0] = 1.0f;
    Yv[1] = s3 * ny; Yv[2] = s3 * nz; Yv[3] = s3 * nx;
    Yv[4] = s15 * nx * ny;
    Yv[5] = s15 * ny * nz;
    Yv[6] = 0.5f * s5 * (3.0f * nz * nz - 1.0f);
    Yv[7] = s15 * nx * nz;
    Yv[8] = 0.5f * s15 * (nx * nx - ny * ny);

    // gates via table lerp (alpha * inv_avg already baked in)
    float gp[16];
    {
        float t = L * ((float)TABN / 2.0f);
        int i0 = (int)t;
        i0 = min(i0, TABN - 1);
        float f = t - (float)i0;
        const float4* t0 = (const float4*)(g_tab + (size_t)i0 * 16);
        const float4* t1 = (const float4*)(g_tab + (size_t)(i0 + 1) * 16);
#pragma unroll
        for (int q = 0; q < 4; q++) {
            float4 a = t0[q], c = t1[q];
            gp[q * 4 + 0] = a.x + f * (c.x - a.x);
            gp[q * 4 + 1] = a.y + f * (c.y - a.y);
            gp[q * 4 + 2] = a.z + f * (c.z - a.z);
            gp[q * 4 + 3] = a.w + f * (c.w - a.w);
        }
    }

    // geometry: stream scaled values out, coalesced (geoS[pj][slot])
#pragma unroll
    for (int p = 0; p < NPATHS; p++) {
        const int l1 = PL1[p], l2 = PL2[p], l3 = PL3[p];
        const int o1 = LOFF[l1], o2 = LOFF[l2];
        const int n2d = 2 * l2 + 1, n3d = 2 * l3 + 1;
#pragma unroll
        for (int k = 0; k < 2 * l3 + 1; k++) {
            float acc = 0.0f;
#pragma unroll
            for (int m = 0; m < 2 * l1 + 1; m++) {
#pragma unroll
                for (int n = 0; n < 2 * l2 + 1; n++) {
                    acc += Yv[o1 + m] * Yv[o2 + n] * sCG[CGO[p] + (m * n2d + n) * n3d + k];
                }
            }
            int j = GEOO[p] + k;
            g_geoS[(size_t)j * MAXE + slot] = acc * gp[p];
        }
    }
}

// ---------------------------------------------------------------------------
// Accumulate kernel: warp per node, lane = (m, q). Vectorized: 4 edges per
// iteration via float4 loads from AiSt[m][*] and geoS[pj][*].
// ---------------------------------------------------------------------------
__global__ void __launch_bounds__(256) accum_kernel(int N)
{
    int n = (blockIdx.x * blockDim.x + threadIdx.x) >> 5;
    int lane = threadIdx.x & 31;
    if (n >= N) return;
    int m = lane & 7;
    int q = lane >> 3;           // 0..3
    int base_pj = q * 13;        // pj 51 is a zero row (padding)
    int lo = g_off[n], hi = g_off[n + 1];

    const float* aim = g_AiSt + (size_t)m * MAXE;

    float acc[13];
#pragma unroll
    for (int r = 0; r < 13; r++) acc[r] = 0.0f;

    int i = lo;
    // scalar prologue to 4-alignment
    for (; i < hi && (i & 3); i++) {
        float ai0 = aim[i];
#pragma unroll
        for (int r = 0; r < 13; r++)
            acc[r] += ai0 * g_geoS[(size_t)(base_pj + r) * MAXE + i];
    }
    // vector main loop: 4 edges per iteration
    for (; i + 3 < hi; i += 4) {
        float4 a4 = *(const float4*)(aim + i);
#pragma unroll
        for (int r = 0; r < 13; r++) {
            float4 g4 = *(const float4*)(g_geoS + (size_t)(base_pj + r) * MAXE + i);
            acc[r] += a4.x * g4.x + a4.y * g4.y + a4.z * g4.z + a4.w * g4.w;
        }
    }
    // scalar tail
    for (; i < hi; i++) {
        float ai0 = aim[i];
#pragma unroll
        for (int r = 0; r < 13; r++)
            acc[r] += ai0 * g_geoS[(size_t)(base_pj + r) * MAXE + i];
    }

    float* srow = g_S + (size_t)n * 416 + m * 52 + base_pj;
#pragma unroll
    for (int r = 0; r < 13; r++) srow[r] = acc[r];
}

// ---------------------------------------------------------------------------
// Finalize kernel: thread per (node, channel). out[c][j] from S and tpw.
// ---------------------------------------------------------------------------
__global__ void __launch_bounds__(256) finalize_kernel(
    const float* __restrict__ tpw, float* __restrict__ out, int N)
{
    __shared__ float sTP[NPATHS * 8 * 16];
    __shared__ float sS[16][416];
    int tid = threadIdx.x;
    for (int i = tid; i < NPATHS * 8 * 16; i += 256) sTP[i] = tpw[i];
    int nodeBase = blockIdx.x * 16;
    for (int i = tid; i < 16 * 416; i += 256) {
        int le = i / 416, o = i - le * 416;
        int n = nodeBase + le;
        sS[le][o] = (n < N) ? g_S[(size_t)n * 416 + o] : 0.0f;
    }
    __syncthreads();

    int le = tid >> 4, c = tid & 15;
    int n = nodeBase + le;
    if (n >= N) return;
    const float* S = sS[le];
    float* orow = out + (size_t)n * 144;

    const int P0[3] = {0, 4, 12};
    const int G0[3] = {0, 12, 42};
    const int P1[6] = {1, 3, 5, 7, 10, 13};
    const int G1[6] = {1, 9, 13, 21, 34, 43};
    const int P2[6] = {2, 6, 8, 9, 11, 14};
    const int G2[6] = {4, 16, 24, 29, 37, 46};

    // l3 = 0
    {
        float a = 0.0f;
#pragma unroll
        for (int i = 0; i < 3; i++) {
            int p = P0[i], g = G0[i];
#pragma unroll
            for (int m = 0; m < 8; m++)
                a += sTP[(p * 8 + m) * 16 + c] * S[m * 52 + g];
        }
        orow[c] = a;
    }
    // l3 = 1
#pragma unroll
    for (int k = 0; k < 3; k++) {
        float a = 0.0f;
#pragma unroll
        for (int i = 0; i < 6; i++) {
            int p = P1[i], g = G1[i] + k;
#pragma unroll
            for (int m = 0; m < 8; m++)
                a += sTP[(p * 8 + m) * 16 + c] * S[m * 52 + g];
        }
        orow[16 + 3 * c + k] = a;
    }
    // l3 = 2
#pragma unroll
    for (int k = 0; k < 5; k++) {
        float a = 0.0f;
#pragma unroll
        for (int i = 0; i < 6; i++) {
            int p = P2[i], g = G2[i] + k;
#pragma unroll
            for (int m = 0; m < 8; m++)
                a += sTP[(p * 8 + m) * 16 + c] * S[m * 52 + g];
        }
        orow[64 + 5 * c + k] = a;
    }
}

// ---------------------------------------------------------------------------
extern "C" void kernel_launch(void* const* d_in, const int* in_sizes, int n_in,
                              void* d_out, int out_size)
{
    const float* pos    = (const float*)d_in[0];
    const int*   A      = (const int*)d_in[1];
    const int*   batch  = (const int*)d_in[2];
    const int*   esrc   = (const int*)d_in[3];
    const int*   edst   = (const int*)d_in[4];
    const float* eshift = (const float*)d_in[5];
    const float* cell   = (const float*)d_in[6];
    const float* embt   = (const float*)d_in[7];
    const float* mw1    = (const float*)d_in[8];
    const float* mb1    = (const float*)d_in[9];
    const float* mw2    = (const float*)d_in[10];
    const float* mb2    = (const float*)d_in[11];
    const float* fw1    = (const float*)d_in[12];
    const float* fb1    = (const float*)d_in[13];
    const float* fw2    = (const float*)d_in[14];
    const float* fb2    = (const float*)d_in[15];
    const float* fw3    = (const float*)d_in[16];
    const float* fb3    = (const float*)d_in[17];
    const float* tpw    = (const float*)d_in[18];
    float* out = (float*)d_out;

    int N = in_sizes[1];
    int E = in_sizes[3];
    float avg = (float)E / (float)N;
    float inv_avg = 1.0f / fmaxf(avg, 1e-8f);

    init_cg_kernel<<<NPATHS, 128>>>();
    zero_count_kernel<<<(NPAD + 255) / 256, 256>>>();
    gate_table_kernel<<<(TABN + 256) / 256, 256>>>(fw1, fb1, fw2, fb2, fw3, fb3, inv_avg);
    node_kernel<<<(N + 255) / 256, 256>>>(embt, A, mw1, mb1, mw2, mb2, N);
    hist_kernel<<<(E + 255) / 256, 256>>>(edst, E);
    scan_kernel<<<1, SCAN_T>>>();
    scatter_kernel<<<(E + 255) / 256, 256>>>(edst, E);
    geo_kernel<<<(E + 255) / 256, 256>>>(pos, batch, esrc, edst, eshift, cell, E);
    accum_kernel<<<(N * 32 + 255) / 256, 256>>>(N);
    finalize_kernel<<<(N + 15) / 16, 256>>>(tpw, out, N);
}

// round 8
// speedup vs baseline: 10.7751x; 1.1209x over previous
#include <cuda_runtime.h>
#include <math.h>

#define NPATHS 15
#define CG_TOTAL 615
#define MAXE 1000000
#define NPAD 50176            // 1024 * 49
#define SCAN_T 1024
#define SCAN_CHUNK 49
#define TABN 16384            // gate table intervals over [0, 2]
#define NB_CG 15
#define NB_TAB 65             // covers TABN+1 = 16385 at 256/block
#define NB_ZERO 196           // NPAD / 256

// path tables: (l1,l2,l3) enumerated as in the reference (l1 outer, l2 mid, l3 inner)
__device__ constexpr int PL1[NPATHS]  = {0,0,0,1,1,1,1,1,1,2,2,2,2,2,2};
__device__ constexpr int PL2[NPATHS]  = {0,1,2,0,1,1,1,2,2,0,1,1,2,2,2};
__device__ constexpr int PL3[NPATHS]  = {0,1,2,1,0,1,2,1,2,2,1,2,0,1,2};
__device__ constexpr int CGO[NPATHS]  = {0,1,10,35,44,53,80,125,170,245,270,315,390,415,490};
__device__ constexpr int GEOO[NPATHS] = {0,1,4,9,12,13,16,21,24,29,34,37,42,43,46};
__device__ constexpr int LOFF[3] = {0,1,4};

__device__ float g_cg[CG_TOTAL];
__device__ __align__(16) float g_Ai[NPAD * 8];
__device__ __align__(16) float g_AiSt[(size_t)8 * MAXE];   // [m][slot]
__device__ __align__(16) float g_geoS[(size_t)52 * MAXE];  // [pj][slot]; row 51 stays 0
__device__ __align__(16) float g_tab[(TABN + 1) * 16];     // gate table (alpha*inv_avg baked)
__device__ __align__(16) float4 g_edata[MAXE];             // {sx,sy,sz, bitcast(src)} per slot
__device__ int   g_dstS[MAXE];                             // dst per slot (sorted)
__device__ int   g_count[NPAD];
__device__ int   g_off[NPAD + 1];
__device__ int   g_cursor[NPAD];

// ---------------------------------------------------------------------------
// CG math helpers (double precision, replicates the reference)
// ---------------------------------------------------------------------------
__device__ double dfact(int n) {
    double r = 1.0;
    for (int i = 2; i <= n; ++i) r *= (double)i;
    return r;
}

__device__ double cgc(int j1, int j2, int j3, int m1, int m2, int m3) {
    if (m1 + m2 != m3) return 0.0;
    double pre = sqrt((double)(2 * j3 + 1) * dfact(j3 + j1 - j2) * dfact(j3 - j1 + j2) *
                      dfact(j1 + j2 - j3) / dfact(j1 + j2 + j3 + 1));
    pre *= sqrt(dfact(j3 + m3) * dfact(j3 - m3) * dfact(j1 - m1) * dfact(j1 + m1) *
                dfact(j2 - m2) * dfact(j2 + m2));
    double s = 0.0;
    for (int k = 0; k <= j1 + j2 - j3; ++k) {
        int d1 = j1 + j2 - j3 - k, d2 = j1 - m1 - k, d3 = j2 + m2 - k;
        int d4 = j3 - j2 + m1 + k, d5 = j3 - j1 - m2 + k;
        if (d1 < 0 || d2 < 0 || d3 < 0 || d4 < 0 || d5 < 0) continue;
        double t = 1.0 / (dfact(k) * dfact(d1) * dfact(d2) * dfact(d3) * dfact(d4) * dfact(d5));
        s += (k & 1) ? -t : t;
    }
    return pre * s;
}

__device__ void buildq(int l, double qr[5][5], double qi[5][5]) {
    for (int a = 0; a < 5; a++)
        for (int b = 0; b < 5; b++) { qr[a][b] = 0.0; qi[a][b] = 0.0; }
    const double isq = sqrt(0.5);
    for (int m = -l; m < 0; m++) {
        qr[l + m][l - m] = isq;
        qi[l + m][l + m] = -isq;
    }
    qr[l][l] = 1.0;
    for (int m = 1; m <= l; m++) {
        double sg = (m & 1) ? -1.0 : 1.0;
        qr[l + m][l + m] = sg * isq;
        qi[l + m][l - m] = sg * isq;
    }
    if (l == 1) {
        for (int a = 0; a < 5; a++)
            for (int b = 0; b < 5; b++) {
                double r = qr[a][b], i0 = qi[a][b];
                qr[a][b] = i0;
                qi[a][b] = -r;
            }
    } else if (l == 2) {
        for (int a = 0; a < 5; a++)
            for (int b = 0; b < 5; b++) { qr[a][b] = -qr[a][b]; qi[a][b] = -qi[a][b]; }
    }
}

// ---------------------------------------------------------------------------
// Mega init kernel: blockIdx ranges dispatch to CG init / gate table / node
// MLP / count zeroing. Independent work runs concurrently across SMs.
// ---------------------------------------------------------------------------
__global__ void __launch_bounds__(256) mega_init_kernel(
    // gate table args
    const float* __restrict__ fw1, const float* __restrict__ fb1,
    const float* __restrict__ fw2, const float* __restrict__ fb2,
    const float* __restrict__ fw3, const float* __restrict__ fb3,
    float inv_avg,
    // node args
    const float* __restrict__ emb_table, const int* __restrict__ A,
    const float* __restrict__ mw1, const float* __restrict__ mb1,
    const float* __restrict__ mw2, const float* __restrict__ mb2,
    int N, int nbNode)
{
    __shared__ __align__(16) unsigned char sbuf[23040];
    int b = blockIdx.x;
    int tid = threadIdx.x;

    if (b < NB_CG) {
        // ----- CG init: one block per path -----
        double* q1r = (double*)(sbuf);          // 25 doubles each
        double* q1i = q1r + 25;
        double* q2r = q1i + 25;
        double* q2i = q2r + 25;
        double* q3r = q2i + 25;
        double* q3i = q3r + 25;
        float* sAr = (float*)(q3i + 25);        // 128
        float* sAi = sAr + 128;                 // 128
        int* sUseRe = (int*)(sAi + 128);

        int p = b;
        int l1 = PL1[p], l2 = PL2[p], l3 = PL3[p];
        int n1 = 2 * l1 + 1, n2 = 2 * l2 + 1, n3 = 2 * l3 + 1;
        int tot = n1 * n2 * n3;

        if (tid < 3) {
            double qr[5][5], qi[5][5];
            int l = (tid == 0) ? l1 : (tid == 1) ? l2 : l3;
            buildq(l, qr, qi);
            double* dr = (tid == 0) ? q1r : (tid == 1) ? q2r : q3r;
            double* di = (tid == 0) ? q1i : (tid == 1) ? q2i : q3i;
            for (int a = 0; a < 5; a++)
                for (int c = 0; c < 5; c++) { dr[a * 5 + c] = qr[a][c]; di[a * 5 + c] = qi[a][c]; }
        }
        __syncthreads();

        double ar = 0.0, ai = 0.0;
        if (tid < tot) {
            int i = tid / (n2 * n3);
            int rem = tid - i * (n2 * n3);
            int j = rem / n3;
            int k = rem - j * n3;
            for (int a = 0; a < n1; a++)
                for (int c = 0; c < n2; c++) {
                    double t12r = q1r[a * 5 + i] * q2r[c * 5 + j] - q1i[a * 5 + i] * q2i[c * 5 + j];
                    double t12i = q1r[a * 5 + i] * q2i[c * 5 + j] + q1i[a * 5 + i] * q2r[c * 5 + j];
                    if (t12r == 0.0 && t12i == 0.0) continue;
                    for (int cc = 0; cc < n3; cc++) {
                        double C = cgc(l1, l2, l3, a - l1, c - l2, cc - l3);
                        if (C == 0.0) continue;
                        double t3r = q3r[cc * 5 + k], t3i = -q3i[cc * 5 + k];  // conj
                        ar += (t12r * t3r - t12i * t3i) * C;
                        ai += (t12r * t3i + t12i * t3r) * C;
                    }
                }
        }
        if (tid < 128) {
            sAr[tid] = (tid < tot) ? (float)fabs(ar) : 0.0f;
            sAi[tid] = (tid < tot) ? (float)fabs(ai) : 0.0f;
        }
        __syncthreads();
        if (tid == 0) {
            float sr = 0.0f, si = 0.0f;
            for (int q = 0; q < tot; q++) { sr += sAr[q]; si += sAi[q]; }
            *sUseRe = (sr >= si) ? 1 : 0;
        }
        __syncthreads();
        if (tid < tot)
            g_cg[CGO[p] + tid] = (float)(*sUseRe ? ar : ai);
        return;
    }
    b -= NB_CG;

    if (b < NB_TAB) {
        // ----- gate table -----
        float* F = (float*)sbuf;
        float* sW1 = F;             // 512
        float* sB1 = F + 512;       // 64
        float* sB2 = F + 576;       // 64
        float* sW2 = F + 640;       // 4096
        float* sW3 = F + 4736;      // 960
        float* sB3 = F + 5696;      // 15

        for (int i = tid; i < 8 * 64; i += 256) sW1[i] = fw1[i];
        for (int i = tid; i < 64; i += 256) { sB1[i] = fb1[i]; sB2[i] = fb2[i]; }
        for (int i = tid; i < 64 * 64; i += 256) sW2[i] = fw2[i];
        for (int i = tid; i < 64 * NPATHS; i += 256) sW3[i] = fw3[i];
        for (int i = tid; i < NPATHS; i += 256) sB3[i] = fb3[i];
        __syncthreads();

        int idx = b * 256 + tid;
        if (idx > TABN) return;
        float len = (float)idx * (2.0f / (float)TABN);

        float emb[8];
        const float step = 2.0f / 9.0f;
        const float istep = 4.5f;
        const float cemb = 2.8284271247461903f / 1.12f;
#pragma unroll
        for (int i = 0; i < 8; i++) {
            float t = (len - (float)(i + 1) * step) * istep;
            emb[i] = __expf(-t * t) * cemb;
        }

        float h1[64];
#pragma unroll
        for (int j = 0; j < 64; j++) {
            float t = sB1[j];
#pragma unroll
            for (int i = 0; i < 8; i++) t += emb[i] * sW1[i * 64 + j];
            h1[j] = t / (1.0f + __expf(-t));
        }

        float gp[NPATHS];
#pragma unroll
        for (int p = 0; p < NPATHS; p++) gp[p] = sB3[p];
#pragma unroll 4
        for (int j = 0; j < 64; j++) {
            float t = sB2[j];
#pragma unroll
            for (int i = 0; i < 64; i++) t += h1[i] * sW2[i * 64 + j];
            float s = t / (1.0f + __expf(-t));
#pragma unroll
            for (int p = 0; p < NPATHS; p++) gp[p] += s * sW3[j * NPATHS + p];
        }

        const float ALP0 = 0.20412414523193154f;  // 1/sqrt(8*3)
        const float ALP1 = 0.14433756729740643f;  // 1/sqrt(8*6)
        float* row = g_tab + (size_t)idx * 16;
#pragma unroll
        for (int p = 0; p < NPATHS; p++) {
            float alpha = (PL3[p] == 0) ? ALP0 : ALP1;
            row[p] = gp[p] * alpha * inv_avg;
        }
        row[15] = 0.0f;
        return;
    }
    b -= NB_TAB;

    if (b < nbNode) {
        // ----- node MLP -----
        float* F = (float*)sbuf;
        float* sW1 = F;             // 1024
        float* sB1 = F + 1024;      // 64
        float* sW2 = F + 1088;      // 512
        float* sB2 = F + 1600;      // 8
        float* sEmb = F + 1608;     // 160

        for (int i = tid; i < 16 * 64; i += 256) sW1[i] = mw1[i];
        for (int i = tid; i < 64; i += 256) sB1[i] = mb1[i];
        for (int i = tid; i < 64 * 8; i += 256) sW2[i] = mw2[i];
        for (int i = tid; i < 8; i += 256) sB2[i] = mb2[i];
        for (int i = tid; i < 10 * 16; i += 256) sEmb[i] = emb_table[i];
        __syncthreads();

        int n = b * 256 + tid;
        if (n >= N) return;
        int a = A[n];
        float x[16];
#pragma unroll
        for (int i = 0; i < 16; i++) x[i] = sEmb[a * 16 + i];
        float h[64];
#pragma unroll
        for (int j = 0; j < 64; j++) {
            float t = sB1[j];
#pragma unroll
            for (int i = 0; i < 16; i++) t += x[i] * sW1[i * 64 + j];
            h[j] = t / (1.0f + __expf(-t));
        }
#pragma unroll
        for (int o = 0; o < 8; o++) {
            float t = sB2[o];
#pragma unroll
            for (int j = 0; j < 64; j++) t += h[j] * sW2[j * 8 + o];
            g_Ai[n * 8 + o] = t;
        }
        return;
    }
    b -= nbNode;

    // ----- zero counts -----
    int i = b * 256 + tid;
    if (i < NPAD) g_count[i] = 0;
}

// ---------------------------------------------------------------------------
// Sorting: hist -> scan -> scatter (scatter also packs per-slot edge records)
// ---------------------------------------------------------------------------
__global__ void hist_kernel(const int* __restrict__ edst, int E) {
    int e = blockIdx.x * blockDim.x + threadIdx.x;
    if (e < E) atomicAdd(&g_count[edst[e]], 1);
}

__global__ void __launch_bounds__(SCAN_T) scan_kernel() {
    __shared__ int ssum[SCAN_T];
    int t = threadIdx.x;
    int lo = t * SCAN_CHUNK;
    int hi = lo + SCAN_CHUNK;
    int s = 0;
    for (int i = lo; i < hi; i++) s += g_count[i];
    ssum[t] = s;
    __syncthreads();
    for (int d = 1; d < SCAN_T; d <<= 1) {
        int v = 0;
        if (t >= d) v = ssum[t - d];
        __syncthreads();
        if (t >= d) ssum[t] += v;
        __syncthreads();
    }
    int pre = (t == 0) ? 0 : ssum[t - 1];
    for (int i = lo; i < hi; i++) {
        g_off[i] = pre;
        g_cursor[i] = pre;
        pre += g_count[i];
    }
    if (t == SCAN_T - 1) g_off[NPAD] = pre;
}

__global__ void scatter_kernel(const int* __restrict__ esrc,
                               const int* __restrict__ edst,
                               const float* __restrict__ eshift, int E) {
    int e = blockIdx.x * blockDim.x + threadIdx.x;
    if (e >= E) return;
    int d = edst[e];
    int s = esrc[e];
    float sx = eshift[e * 3 + 0], sy = eshift[e * 3 + 1], sz = eshift[e * 3 + 2];
    int p = atomicAdd(&g_cursor[d], 1);
    g_edata[p] = make_float4(sx, sy, sz, __int_as_float(s));
    g_dstS[p] = d;
}

// ---------------------------------------------------------------------------
// Geo kernel: 1 slot per thread, fully coalesced edge-record reads.
// Writes geoS[pj][slot] and AiSt[m][slot] (both coalesced).
// ---------------------------------------------------------------------------
__global__ void __launch_bounds__(256) geo_kernel(
    const float* __restrict__ pos, const int* __restrict__ batch,
    const float* __restrict__ cell, int E)
{
    __shared__ float sCG[CG_TOTAL];
    int tid = threadIdx.x;
    for (int i = tid; i < CG_TOTAL; i += 256) sCG[i] = g_cg[i];
    __syncthreads();

    int slot = blockIdx.x * 256 + tid;
    if (slot >= E) return;
    float4 rec = g_edata[slot];
    int s = __float_as_int(rec.w);
    int d = g_dstS[slot];

    // copy Ai of source into transposed slot-ordered stream [m][slot]
    {
        const float4* ap = (const float4*)(g_Ai + (size_t)s * 8);
        float4 a0 = ap[0], a1 = ap[1];
        g_AiSt[(size_t)0 * MAXE + slot] = a0.x;
        g_AiSt[(size_t)1 * MAXE + slot] = a0.y;
        g_AiSt[(size_t)2 * MAXE + slot] = a0.z;
        g_AiSt[(size_t)3 * MAXE + slot] = a0.w;
        g_AiSt[(size_t)4 * MAXE + slot] = a1.x;
        g_AiSt[(size_t)5 * MAXE + slot] = a1.y;
        g_AiSt[(size_t)6 * MAXE + slot] = a1.z;
        g_AiSt[(size_t)7 * MAXE + slot] = a1.w;
    }

    int b = batch[s];
    const float* cl = cell + b * 9;
    float shx = rec.x * cl[0] + rec.y * cl[3] + rec.z * cl[6];
    float shy = rec.x * cl[1] + rec.y * cl[4] + rec.z * cl[7];
    float shz = rec.x * cl[2] + rec.y * cl[5] + rec.z * cl[8];
    float vx = pos[d * 3 + 0] - pos[s * 3 + 0] + shx;
    float vy = pos[d * 3 + 1] - pos[s * 3 + 1] + shy;
    float vz = pos[d * 3 + 2] - pos[s * 3 + 2] + shz;
    float L = sqrtf(vx * vx + vy * vy + vz * vz);
    float il = 1.0f / fmaxf(L, 1e-8f);
    float nx = vx * il, ny = vy * il, nz = vz * il;

    float Yv[9];
    const float s3 = 1.7320508075688772f;
    const float s15 = 3.872983346207417f;
    const float s5 = 2.23606797749979f;
    Yv[0] = 1.0f;
    Yv[1] = s3 * ny; Yv[2] = s3 * nz; Yv[3] = s3 * nx;
    Yv[4] = s15 * nx * ny;
    Yv[5] = s15 * ny * nz;
    Yv[6] = 0.5f * s5 * (3.0f * nz * nz - 1.0f);
    Yv[7] = s15 * nx * nz;
    Yv[8] = 0.5f * s15 * (nx * nx - ny * ny);

    // gates via table lerp (alpha * inv_avg already baked in)
    float gp[16];
    {
        float t = L * ((float)TABN / 2.0f);
        int i0 = (int)t;
        i0 = min(i0, TABN - 1);
        float f = t - (float)i0;
        const float4* t0 = (const float4*)(g_tab + (size_t)i0 * 16);
        const float4* t1 = (const float4*)(g_tab + (size_t)(i0 + 1) * 16);
#pragma unroll
        for (int q = 0; q < 4; q++) {
            float4 a = t0[q], c = t1[q];
            gp[q * 4 + 0] = a.x + f * (c.x - a.x);
            gp[q * 4 + 1] = a.y + f * (c.y - a.y);
            gp[q * 4 + 2] = a.z + f * (c.z - a.z);
            gp[q * 4 + 3] = a.w + f * (c.w - a.w);
        }
    }

    // geometry: stream scaled values out, coalesced (geoS[pj][slot])
#pragma unroll
    for (int p = 0; p < NPATHS; p++) {
        const int l1 = PL1[p], l2 = PL2[p], l3 = PL3[p];
        const int o1 = LOFF[l1], o2 = LOFF[l2];
        const int n2d = 2 * l2 + 1, n3d = 2 * l3 + 1;
#pragma unroll
        for (int k = 0; k < 2 * l3 + 1; k++) {
            float acc = 0.0f;
#pragma unroll
            for (int m = 0; m < 2 * l1 + 1; m++) {
#pragma unroll
                for (int n = 0; n < 2 * l2 + 1; n++) {
                    acc += Yv[o1 + m] * Yv[o2 + n] * sCG[CGO[p] + (m * n2d + n) * n3d + k];
                }
            }
            int j = GEOO[p] + k;
            g_geoS[(size_t)j * MAXE + slot] = acc * gp[p];
        }
    }
}

// ---------------------------------------------------------------------------
// Accum+finalize fused: warp per node (8 nodes/block). Accumulates S into
// shared, then applies the tpw transform and writes out[] directly.
// ---------------------------------------------------------------------------
__global__ void __launch_bounds__(256) accum_finalize_kernel(
    const float* __restrict__ tpw, float* __restrict__ out, int N)
{
    __shared__ float sS[8][416];
    __shared__ float sTP[NPATHS * 8 * 16];
    int tid = threadIdx.x;
    for (int i = tid; i < NPATHS * 8 * 16; i += 256) sTP[i] = tpw[i];

    int warp = tid >> 5;
    int lane = tid & 31;
    int n = blockIdx.x * 8 + warp;
    int m = lane & 7;
    int q = lane >> 3;           // 0..3
    int base_pj = q * 13;        // pj 51 is a zero row (padding)

    if (n < N) {
        int lo = g_off[n], hi = g_off[n + 1];
        const float* aim = g_AiSt + (size_t)m * MAXE;

        float acc[13];
#pragma unroll
        for (int r = 0; r < 13; r++) acc[r] = 0.0f;

        int i = lo;
        for (; i < hi && (i & 3); i++) {
            float ai0 = aim[i];
#pragma unroll
            for (int r = 0; r < 13; r++)
                acc[r] += ai0 * g_geoS[(size_t)(base_pj + r) * MAXE + i];
        }
        for (; i + 3 < hi; i += 4) {
            float4 a4 = *(const float4*)(aim + i);
#pragma unroll
            for (int r = 0; r < 13; r++) {
                float4 g4 = *(const float4*)(g_geoS + (size_t)(base_pj + r) * MAXE + i);
                acc[r] += a4.x * g4.x + a4.y * g4.y + a4.z * g4.z + a4.w * g4.w;
            }
        }
        for (; i < hi; i++) {
            float ai0 = aim[i];
#pragma unroll
            for (int r = 0; r < 13; r++)
                acc[r] += ai0 * g_geoS[(size_t)(base_pj + r) * MAXE + i];
        }

        float* srow = &sS[warp][m * 52 + base_pj];
#pragma unroll
        for (int r = 0; r < 13; r++) srow[r] = acc[r];
    }
    __syncthreads();

    if (n >= N || lane >= 16) return;
    int c = lane;
    const float* S = sS[warp];
    float* orow = out + (size_t)n * 144;

    const int P0[3] = {0, 4, 12};
    const int G0[3] = {0, 12, 42};
    const int P1[6] = {1, 3, 5, 7, 10, 13};
    const int G1[6] = {1, 9, 13, 21, 34, 43};
    const int P2[6] = {2, 6, 8, 9, 11, 14};
    const int G2[6] = {4, 16, 24, 29, 37, 46};

    // l3 = 0
    {
        float a = 0.0f;
#pragma unroll
        for (int i = 0; i < 3; i++) {
            int p = P0[i], g = G0[i];
#pragma unroll
            for (int m2 = 0; m2 < 8; m2++)
                a += sTP[(p * 8 + m2) * 16 + c] * S[m2 * 52 + g];
        }
        orow[c] = a;
    }
    // l3 = 1
#pragma unroll
    for (int k = 0; k < 3; k++) {
        float a = 0.0f;
#pragma unroll
        for (int i = 0; i < 6; i++) {
            int p = P1[i], g = G1[i] + k;
#pragma unroll
            for (int m2 = 0; m2 < 8; m2++)
                a += sTP[(p * 8 + m2) * 16 + c] * S[m2 * 52 + g];
        }
        orow[16 + 3 * c + k] = a;
    }
    // l3 = 2
#pragma unroll
    for (int k = 0; k < 5; k++) {
        float a = 0.0f;
#pragma unroll
        for (int i = 0; i < 6; i++) {
            int p = P2[i], g = G2[i] + k;
#pragma unroll
            for (int m2 = 0; m2 < 8; m2++)
                a += sTP[(p * 8 + m2) * 16 + c] * S[m2 * 52 + g];
        }
        orow[64 + 5 * c + k] = a;
    }
}

// ---------------------------------------------------------------------------
extern "C" void kernel_launch(void* const* d_in, const int* in_sizes, int n_in,
                              void* d_out, int out_size)
{
    const float* pos    = (const float*)d_in[0];
    const int*   A      = (const int*)d_in[1];
    const int*   batch  = (const int*)d_in[2];
    const int*   esrc   = (const int*)d_in[3];
    const int*   edst   = (const int*)d_in[4];
    const float* eshift = (const float*)d_in[5];
    const float* cell   = (const float*)d_in[6];
    const float* embt   = (const float*)d_in[7];
    const float* mw1    = (const float*)d_in[8];
    const float* mb1    = (const float*)d_in[9];
    const float* mw2    = (const float*)d_in[10];
    const float* mb2    = (const float*)d_in[11];
    const float* fw1    = (const float*)d_in[12];
    const float* fb1    = (const float*)d_in[13];
    const float* fw2    = (const float*)d_in[14];
    const float* fb2    = (const float*)d_in[15];
    const float* fw3    = (const float*)d_in[16];
    const float* fb3    = (const float*)d_in[17];
    const float* tpw    = (const float*)d_in[18];
    float* out = (float*)d_out;

    int N = in_sizes[1];
    int E = in_sizes[3];
    float avg = (float)E / (float)N;
    float inv_avg = 1.0f / fmaxf(avg, 1e-8f);

    int nbNode = (N + 255) / 256;
    int megaBlocks = NB_CG + NB_TAB + nbNode + NB_ZERO;

    mega_init_kernel<<<megaBlocks, 256>>>(fw1, fb1, fw2, fb2, fw3, fb3, inv_avg,
                                          embt, A, mw1, mb1, mw2, mb2, N, nbNode);
    hist_kernel<<<(E + 255) / 256, 256>>>(edst, E);
    scan_kernel<<<1, SCAN_T>>>();
    scatter_kernel<<<(E + 255) / 256, 256>>>(esrc, edst, eshift, E);
    geo_kernel<<<(E + 255) / 256, 256>>>(pos, batch, cell, E);
    accum_finalize_kernel<<<(N + 7) / 8, 256>>>(tpw, out, N);
}

// round 9
// speedup vs baseline: 10.8844x; 1.0101x over previous
#include <cuda_runtime.h>
#include <cuda_fp16.h>
#include <math.h>

#define NPATHS 15
#define CG_TOTAL 615
#define MAXE 1000000
#define NPAD 50176            // 1024 * 49
#define SCAN_T 1024
#define SCAN_CHUNK 49
#define TABN 16384            // gate table intervals over [0, 2]
#define NB_CG 15
#define NB_TAB 65             // covers TABN+1 = 16385 at 256/block
#define NB_ZERO 196           // NPAD / 256

// path tables: (l1,l2,l3) enumerated as in the reference (l1 outer, l2 mid, l3 inner)
__device__ constexpr int PL1[NPATHS]  = {0,0,0,1,1,1,1,1,1,2,2,2,2,2,2};
__device__ constexpr int PL2[NPATHS]  = {0,1,2,0,1,1,1,2,2,0,1,1,2,2,2};
__device__ constexpr int PL3[NPATHS]  = {0,1,2,1,0,1,2,1,2,2,1,2,0,1,2};
__device__ constexpr int CGO[NPATHS]  = {0,1,10,35,44,53,80,125,170,245,270,315,390,415,490};
__device__ constexpr int GEOO[NPATHS] = {0,1,4,9,12,13,16,21,24,29,34,37,42,43,46};
__device__ constexpr int LOFF[3] = {0,1,4};

__device__ float g_cg[CG_TOTAL];
__device__ __align__(16) float g_Ai[NPAD * 8];
__device__ __align__(16) __half g_AiH[(size_t)8 * MAXE];   // [m][slot], fp16
__device__ __align__(16) __half g_geoH[(size_t)52 * MAXE]; // [pj][slot], fp16; row 51 stays 0
__device__ __align__(16) float g_tab[(TABN + 1) * 16];     // gate table (alpha*inv_avg baked)
__device__ __align__(16) float4 g_edata[MAXE];             // {sx,sy,sz, bitcast(src)} per slot
__device__ int   g_dstS[MAXE];                             // dst per slot (sorted)
__device__ int   g_count[NPAD];
__device__ int   g_off[NPAD + 1];
__device__ int   g_cursor[NPAD];

// ---------------------------------------------------------------------------
// CG math helpers (double precision, replicates the reference)
// ---------------------------------------------------------------------------
__device__ double dfact(int n) {
    double r = 1.0;
    for (int i = 2; i <= n; ++i) r *= (double)i;
    return r;
}

__device__ double cgc(int j1, int j2, int j3, int m1, int m2, int m3) {
    if (m1 + m2 != m3) return 0.0;
    double pre = sqrt((double)(2 * j3 + 1) * dfact(j3 + j1 - j2) * dfact(j3 - j1 + j2) *
                      dfact(j1 + j2 - j3) / dfact(j1 + j2 + j3 + 1));
    pre *= sqrt(dfact(j3 + m3) * dfact(j3 - m3) * dfact(j1 - m1) * dfact(j1 + m1) *
                dfact(j2 - m2) * dfact(j2 + m2));
    double s = 0.0;
    for (int k = 0; k <= j1 + j2 - j3; ++k) {
        int d1 = j1 + j2 - j3 - k, d2 = j1 - m1 - k, d3 = j2 + m2 - k;
        int d4 = j3 - j2 + m1 + k, d5 = j3 - j1 - m2 + k;
        if (d1 < 0 || d2 < 0 || d3 < 0 || d4 < 0 || d5 < 0) continue;
        double t = 1.0 / (dfact(k) * dfact(d1) * dfact(d2) * dfact(d3) * dfact(d4) * dfact(d5));
        s += (k & 1) ? -t : t;
    }
    return pre * s;
}

__device__ void buildq(int l, double qr[5][5], double qi[5][5]) {
    for (int a = 0; a < 5; a++)
        for (int b = 0; b < 5; b++) { qr[a][b] = 0.0; qi[a][b] = 0.0; }
    const double isq = sqrt(0.5);
    for (int m = -l; m < 0; m++) {
        qr[l + m][l - m] = isq;
        qi[l + m][l + m] = -isq;
    }
    qr[l][l] = 1.0;
    for (int m = 1; m <= l; m++) {
        double sg = (m & 1) ? -1.0 : 1.0;
        qr[l + m][l + m] = sg * isq;
        qi[l + m][l - m] = sg * isq;
    }
    if (l == 1) {
        for (int a = 0; a < 5; a++)
            for (int b = 0; b < 5; b++) {
                double r = qr[a][b], i0 = qi[a][b];
                qr[a][b] = i0;
                qi[a][b] = -r;
            }
    } else if (l == 2) {
        for (int a = 0; a < 5; a++)
            for (int b = 0; b < 5; b++) { qr[a][b] = -qr[a][b]; qi[a][b] = -qi[a][b]; }
    }
}

// ---------------------------------------------------------------------------
// Mega init kernel: blockIdx ranges dispatch to CG init / gate table / node
// MLP / count zeroing. Independent work runs concurrently across SMs.
// ---------------------------------------------------------------------------
__global__ void __launch_bounds__(256) mega_init_kernel(
    const float* __restrict__ fw1, const float* __restrict__ fb1,
    const float* __restrict__ fw2, const float* __restrict__ fb2,
    const float* __restrict__ fw3, const float* __restrict__ fb3,
    float inv_avg,
    const float* __restrict__ emb_table, const int* __restrict__ A,
    const float* __restrict__ mw1, const float* __restrict__ mb1,
    const float* __restrict__ mw2, const float* __restrict__ mb2,
    int N, int nbNode)
{
    __shared__ __align__(16) unsigned char sbuf[23040];
    int b = blockIdx.x;
    int tid = threadIdx.x;

    if (b < NB_CG) {
        // ----- CG init: one block per path -----
        double* q1r = (double*)(sbuf);
        double* q1i = q1r + 25;
        double* q2r = q1i + 25;
        double* q2i = q2r + 25;
        double* q3r = q2i + 25;
        double* q3i = q3r + 25;
        float* sAr = (float*)(q3i + 25);
        float* sAi = sAr + 128;
        int* sUseRe = (int*)(sAi + 128);

        int p = b;
        int l1 = PL1[p], l2 = PL2[p], l3 = PL3[p];
        int n1 = 2 * l1 + 1, n2 = 2 * l2 + 1, n3 = 2 * l3 + 1;
        int tot = n1 * n2 * n3;

        if (tid < 3) {
            double qr[5][5], qi[5][5];
            int l = (tid == 0) ? l1 : (tid == 1) ? l2 : l3;
            buildq(l, qr, qi);
            double* dr = (tid == 0) ? q1r : (tid == 1) ? q2r : q3r;
            double* di = (tid == 0) ? q1i : (tid == 1) ? q2i : q3i;
            for (int a = 0; a < 5; a++)
                for (int c = 0; c < 5; c++) { dr[a * 5 + c] = qr[a][c]; di[a * 5 + c] = qi[a][c]; }
        }
        __syncthreads();

        double ar = 0.0, ai = 0.0;
        if (tid < tot) {
            int i = tid / (n2 * n3);
            int rem = tid - i * (n2 * n3);
            int j = rem / n3;
            int k = rem - j * n3;
            for (int a = 0; a < n1; a++)
                for (int c = 0; c < n2; c++) {
                    double t12r = q1r[a * 5 + i] * q2r[c * 5 + j] - q1i[a * 5 + i] * q2i[c * 5 + j];
                    double t12i = q1r[a * 5 + i] * q2i[c * 5 + j] + q1i[a * 5 + i] * q2r[c * 5 + j];
                    if (t12r == 0.0 && t12i == 0.0) continue;
                    for (int cc = 0; cc < n3; cc++) {
                        double C = cgc(l1, l2, l3, a - l1, c - l2, cc - l3);
                        if (C == 0.0) continue;
                        double t3r = q3r[cc * 5 + k], t3i = -q3i[cc * 5 + k];
                        ar += (t12r * t3r - t12i * t3i) * C;
                        ai += (t12r * t3i + t12i * t3r) * C;
                    }
                }
        }
        if (tid < 128) {
            sAr[tid] = (tid < tot) ? (float)fabs(ar) : 0.0f;
            sAi[tid] = (tid < tot) ? (float)fabs(ai) : 0.0f;
        }
        __syncthreads();
        if (tid == 0) {
            float sr = 0.0f, si = 0.0f;
            for (int q = 0; q < tot; q++) { sr += sAr[q]; si += sAi[q]; }
            *sUseRe = (sr >= si) ? 1 : 0;
        }
        __syncthreads();
        if (tid < tot)
            g_cg[CGO[p] + tid] = (float)(*sUseRe ? ar : ai);
        return;
    }
    b -= NB_CG;

    if (b < NB_TAB) {
        // ----- gate table -----
        float* F = (float*)sbuf;
        float* sW1 = F;
        float* sB1 = F + 512;
        float* sB2 = F + 576;
        float* sW2 = F + 640;
        float* sW3 = F + 4736;
        float* sB3 = F + 5696;

        for (int i = tid; i < 8 * 64; i += 256) sW1[i] = fw1[i];
        for (int i = tid; i < 64; i += 256) { sB1[i] = fb1[i]; sB2[i] = fb2[i]; }
        for (int i = tid; i < 64 * 64; i += 256) sW2[i] = fw2[i];
        for (int i = tid; i < 64 * NPATHS; i += 256) sW3[i] = fw3[i];
        for (int i = tid; i < NPATHS; i += 256) sB3[i] = fb3[i];
        __syncthreads();

        int idx = b * 256 + tid;
        if (idx > TABN) return;
        float len = (float)idx * (2.0f / (float)TABN);

        float emb[8];
        const float step = 2.0f / 9.0f;
        const float istep = 4.5f;
        const float cemb = 2.8284271247461903f / 1.12f;
#pragma unroll
        for (int i = 0; i < 8; i++) {
            float t = (len - (float)(i + 1) * step) * istep;
            emb[i] = __expf(-t * t) * cemb;
        }

        float h1[64];
#pragma unroll
        for (int j = 0; j < 64; j++) {
            float t = sB1[j];
#pragma unroll
            for (int i = 0; i < 8; i++) t += emb[i] * sW1[i * 64 + j];
            h1[j] = t / (1.0f + __expf(-t));
        }

        float gp[NPATHS];
#pragma unroll
        for (int p = 0; p < NPATHS; p++) gp[p] = sB3[p];
#pragma unroll 4
        for (int j = 0; j < 64; j++) {
            float t = sB2[j];
#pragma unroll
            for (int i = 0; i < 64; i++) t += h1[i] * sW2[i * 64 + j];
            float s = t / (1.0f + __expf(-t));
#pragma unroll
            for (int p = 0; p < NPATHS; p++) gp[p] += s * sW3[j * NPATHS + p];
        }

        const float ALP0 = 0.20412414523193154f;
        const float ALP1 = 0.14433756729740643f;
        float* row = g_tab + (size_t)idx * 16;
#pragma unroll
        for (int p = 0; p < NPATHS; p++) {
            float alpha = (PL3[p] == 0) ? ALP0 : ALP1;
            row[p] = gp[p] * alpha * inv_avg;
        }
        row[15] = 0.0f;
        return;
    }
    b -= NB_TAB;

    if (b < nbNode) {
        // ----- node MLP -----
        float* F = (float*)sbuf;
        float* sW1 = F;
        float* sB1 = F + 1024;
        float* sW2 = F + 1088;
        float* sB2 = F + 1600;
        float* sEmb = F + 1608;

        for (int i = tid; i < 16 * 64; i += 256) sW1[i] = mw1[i];
        for (int i = tid; i < 64; i += 256) sB1[i] = mb1[i];
        for (int i = tid; i < 64 * 8; i += 256) sW2[i] = mw2[i];
        for (int i = tid; i < 8; i += 256) sB2[i] = mb2[i];
        for (int i = tid; i < 10 * 16; i += 256) sEmb[i] = emb_table[i];
        __syncthreads();

        int n = b * 256 + tid;
        if (n >= N) return;
        int a = A[n];
        float x[16];
#pragma unroll
        for (int i = 0; i < 16; i++) x[i] = sEmb[a * 16 + i];
        float h[64];
#pragma unroll
        for (int j = 0; j < 64; j++) {
            float t = sB1[j];
#pragma unroll
            for (int i = 0; i < 16; i++) t += x[i] * sW1[i * 64 + j];
            h[j] = t / (1.0f + __expf(-t));
        }
#pragma unroll
        for (int o = 0; o < 8; o++) {
            float t = sB2[o];
#pragma unroll
            for (int j = 0; j < 64; j++) t += h[j] * sW2[j * 8 + o];
            g_Ai[n * 8 + o] = t;
        }
        return;
    }
    b -= nbNode;

    // ----- zero counts -----
    int i = b * 256 + tid;
    if (i < NPAD) g_count[i] = 0;
}

// ---------------------------------------------------------------------------
// Sorting: hist -> scan -> scatter (scatter also packs per-slot edge records)
// ---------------------------------------------------------------------------
__global__ void hist_kernel(const int* __restrict__ edst, int E) {
    int e = blockIdx.x * blockDim.x + threadIdx.x;
    if (e < E) atomicAdd(&g_count[edst[e]], 1);
}

__global__ void __launch_bounds__(SCAN_T) scan_kernel() {
    __shared__ int ssum[SCAN_T];
    int t = threadIdx.x;
    int lo = t * SCAN_CHUNK;
    int hi = lo + SCAN_CHUNK;
    int s = 0;
    for (int i = lo; i < hi; i++) s += g_count[i];
    ssum[t] = s;
    __syncthreads();
    for (int d = 1; d < SCAN_T; d <<= 1) {
        int v = 0;
        if (t >= d) v = ssum[t - d];
        __syncthreads();
        if (t >= d) ssum[t] += v;
        __syncthreads();
    }
    int pre = (t == 0) ? 0 : ssum[t - 1];
    for (int i = lo; i < hi; i++) {
        g_off[i] = pre;
        g_cursor[i] = pre;
        pre += g_count[i];
    }
    if (t == SCAN_T - 1) g_off[NPAD] = pre;
}

__global__ void scatter_kernel(const int* __restrict__ esrc,
                               const int* __restrict__ edst,
                               const float* __restrict__ eshift, int E) {
    int e = blockIdx.x * blockDim.x + threadIdx.x;
    if (e >= E) return;
    int d = edst[e];
    int s = esrc[e];
    float sx = eshift[e * 3 + 0], sy = eshift[e * 3 + 1], sz = eshift[e * 3 + 2];
    int p = atomicAdd(&g_cursor[d], 1);
    g_edata[p] = make_float4(sx, sy, sz, __int_as_float(s));
    g_dstS[p] = d;
}

// ---------------------------------------------------------------------------
// Geo kernel: 1 slot per thread, coalesced edge-record reads.
// Writes geoH[pj][slot] (fp16) and AiH[m][slot] (fp16), both coalesced.
// ---------------------------------------------------------------------------
__global__ void __launch_bounds__(256) geo_kernel(
    const float* __restrict__ pos, const int* __restrict__ batch,
    const float* __restrict__ cell, int E)
{
    __shared__ float sCG[CG_TOTAL];
    int tid = threadIdx.x;
    for (int i = tid; i < CG_TOTAL; i += 256) sCG[i] = g_cg[i];
    __syncthreads();

    int slot = blockIdx.x * 256 + tid;
    if (slot >= E) return;
    float4 rec = g_edata[slot];
    int s = __float_as_int(rec.w);
    int d = g_dstS[slot];

    // copy Ai of source into transposed slot-ordered stream [m][slot], fp16
    {
        const float4* ap = (const float4*)(g_Ai + (size_t)s * 8);
        float4 a0 = ap[0], a1 = ap[1];
        g_AiH[(size_t)0 * MAXE + slot] = __float2half_rn(a0.x);
        g_AiH[(size_t)1 * MAXE + slot] = __float2half_rn(a0.y);
        g_AiH[(size_t)2 * MAXE + slot] = __float2half_rn(a0.z);
        g_AiH[(size_t)3 * MAXE + slot] = __float2half_rn(a0.w);
        g_AiH[(size_t)4 * MAXE + slot] = __float2half_rn(a1.x);
        g_AiH[(size_t)5 * MAXE + slot] = __float2half_rn(a1.y);
        g_AiH[(size_t)6 * MAXE + slot] = __float2half_rn(a1.z);
        g_AiH[(size_t)7 * MAXE + slot] = __float2half_rn(a1.w);
    }

    int b = batch[s];
    const float* cl = cell + b * 9;
    float shx = rec.x * cl[0] + rec.y * cl[3] + rec.z * cl[6];
    float shy = rec.x * cl[1] + rec.y * cl[4] + rec.z * cl[7];
    float shz = rec.x * cl[2] + rec.y * cl[5] + rec.z * cl[8];
    float vx = pos[d * 3 + 0] - pos[s * 3 + 0] + shx;
    float vy = pos[d * 3 + 1] - pos[s * 3 + 1] + shy;
    float vz = pos[d * 3 + 2] - pos[s * 3 + 2] + shz;
    float L = sqrtf(vx * vx + vy * vy + vz * vz);
    float il = 1.0f / fmaxf(L, 1e-8f);
    float nx = vx * il, ny = vy * il, nz = vz * il;

    float Yv[9];
    const float s3 = 1.7320508075688772f;
    const float s15 = 3.872983346207417f;
    const float s5 = 2.23606797749979f;
    Yv[0] = 1.0f;
    Yv[1] = s3 * ny; Yv[2] = s3 * nz; Yv[3] = s3 * nx;
    Yv[4] = s15 * nx * ny;
    Yv[5] = s15 * ny * nz;
    Yv[6] = 0.5f * s5 * (3.0f * nz * nz - 1.0f);
    Yv[7] = s15 * nx * nz;
    Yv[8] = 0.5f * s15 * (nx * nx - ny * ny);

    // gates via table lerp (alpha * inv_avg already baked in)
    float gp[16];
    {
        float t = L * ((float)TABN / 2.0f);
        int i0 = (int)t;
        i0 = min(i0, TABN - 1);
        float f = t - (float)i0;
        const float4* t0 = (const float4*)(g_tab + (size_t)i0 * 16);
        const float4* t1 = (const float4*)(g_tab + (size_t)(i0 + 1) * 16);
#pragma unroll
        for (int q = 0; q < 4; q++) {
            float4 a = t0[q], c = t1[q];
            gp[q * 4 + 0] = a.x + f * (c.x - a.x);
            gp[q * 4 + 1] = a.y + f * (c.y - a.y);
            gp[q * 4 + 2] = a.z + f * (c.z - a.z);
            gp[q * 4 + 3] = a.w + f * (c.w - a.w);
        }
    }

    // geometry: stream scaled values out as fp16, coalesced (geoH[pj][slot])
#pragma unroll
    for (int p = 0; p < NPATHS; p++) {
        const int l1 = PL1[p], l2 = PL2[p], l3 = PL3[p];
        const int o1 = LOFF[l1], o2 = LOFF[l2];
        const int n2d = 2 * l2 + 1, n3d = 2 * l3 + 1;
#pragma unroll
        for (int k = 0; k < 2 * l3 + 1; k++) {
            float acc = 0.0f;
#pragma unroll
            for (int m = 0; m < 2 * l1 + 1; m++) {
#pragma unroll
                for (int n = 0; n < 2 * l2 + 1; n++) {
                    acc += Yv[o1 + m] * Yv[o2 + n] * sCG[CGO[p] + (m * n2d + n) * n3d + k];
                }
            }
            int j = GEOO[p] + k;
            g_geoH[(size_t)j * MAXE + slot] = __float2half_rn(acc * gp[p]);
        }
    }
}

// ---------------------------------------------------------------------------
// Accum+finalize fused: warp per node (8 nodes/block). fp16 inputs, fp32
// accumulation; 8 edges per vector iteration via float4-of-half2 loads.
// ---------------------------------------------------------------------------
__global__ void __launch_bounds__(256) accum_finalize_kernel(
    const float* __restrict__ tpw, float* __restrict__ out, int N)
{
    __shared__ float sS[8][416];
    __shared__ float sTP[NPATHS * 8 * 16];
    int tid = threadIdx.x;
    for (int i = tid; i < NPATHS * 8 * 16; i += 256) sTP[i] = tpw[i];

    int warp = tid >> 5;
    int lane = tid & 31;
    int n = blockIdx.x * 8 + warp;
    int m = lane & 7;
    int q = lane >> 3;           // 0..3
    int base_pj = q * 13;        // pj 51 is a zero row (padding)

    if (n < N) {
        int lo = g_off[n], hi = g_off[n + 1];
        const __half* aim = g_AiH + (size_t)m * MAXE;

        float acc[13];
#pragma unroll
        for (int r = 0; r < 13; r++) acc[r] = 0.0f;

        int i = lo;
        // scalar prologue to 8-alignment
        for (; i < hi && (i & 7); i++) {
            float ai0 = __half2float(aim[i]);
#pragma unroll
            for (int r = 0; r < 13; r++)
                acc[r] += ai0 * __half2float(g_geoH[(size_t)(base_pj + r) * MAXE + i]);
        }
        // vector main loop: 8 edges per iteration
        for (; i + 7 < hi; i += 8) {
            float4 av = *(const float4*)(aim + i);
            const __half2* ah = (const __half2*)&av;
            float af[8];
#pragma unroll
            for (int k = 0; k < 4; k++) {
                float2 f = __half22float2(ah[k]);
                af[2 * k] = f.x;
                af[2 * k + 1] = f.y;
            }
#pragma unroll
            for (int r = 0; r < 13; r++) {
                float4 gv = *(const float4*)(g_geoH + (size_t)(base_pj + r) * MAXE + i);
                const __half2* gh = (const __half2*)&gv;
#pragma unroll
                for (int k = 0; k < 4; k++) {
                    float2 gf = __half22float2(gh[k]);
                    acc[r] += af[2 * k] * gf.x + af[2 * k + 1] * gf.y;
                }
            }
        }
        // scalar tail
        for (; i < hi; i++) {
            float ai0 = __half2float(aim[i]);
#pragma unroll
            for (int r = 0; r < 13; r++)
                acc[r] += ai0 * __half2float(g_geoH[(size_t)(base_pj + r) * MAXE + i]);
        }

        float* srow = &sS[warp][m * 52 + base_pj];
#pragma unroll
        for (int r = 0; r < 13; r++) srow[r] = acc[r];
    }
    __syncthreads();

    if (n >= N || lane >= 16) return;
    int c = lane;
    const float* S = sS[warp];
    float* orow = out + (size_t)n * 144;

    const int P0[3] = {0, 4, 12};
    const int G0[3] = {0, 12, 42};
    const int P1[6] = {1, 3, 5, 7, 10, 13};
    const int G1[6] = {1, 9, 13, 21, 34, 43};
    const int P2[6] = {2, 6, 8, 9, 11, 14};
    const int G2[6] = {4, 16, 24, 29, 37, 46};

    // l3 = 0
    {
        float a = 0.0f;
#pragma unroll
        for (int i = 0; i < 3; i++) {
            int p = P0[i], g = G0[i];
#pragma unroll
            for (int m2 = 0; m2 < 8; m2++)
                a += sTP[(p * 8 + m2) * 16 + c] * S[m2 * 52 + g];
        }
        orow[c] = a;
    }
    // l3 = 1
#pragma unroll
    for (int k = 0; k < 3; k++) {
        float a = 0.0f;
#pragma unroll
        for (int i = 0; i < 6; i++) {
            int p = P1[i], g = G1[i] + k;
#pragma unroll
            for (int m2 = 0; m2 < 8; m2++)
                a += sTP[(p * 8 + m2) * 16 + c] * S[m2 * 52 + g];
        }
        orow[16 + 3 * c + k] = a;
    }
    // l3 = 2
#pragma unroll
    for (int k = 0; k < 5; k++) {
        float a = 0.0f;
#pragma unroll
        for (int i = 0; i < 6; i++) {
            int p = P2[i], g = G2[i] + k;
#pragma unroll
            for (int m2 = 0; m2 < 8; m2++)
                a += sTP[(p * 8 + m2) * 16 + c] * S[m2 * 52 + g];
        }
        orow[64 + 5 * c + k] = a;
    }
}

// ---------------------------------------------------------------------------
extern "C" void kernel_launch(void* const* d_in, const int* in_sizes, int n_in,
                              void* d_out, int out_size)
{
    const float* pos    = (const float*)d_in[0];
    const int*   A      = (const int*)d_in[1];
    const int*   batch  = (const int*)d_in[2];
    const int*   esrc   = (const int*)d_in[3];
    const int*   edst   = (const int*)d_in[4];
    const float* eshift = (const float*)d_in[5];
    const float* cell   = (const float*)d_in[6];
    const float* embt   = (const float*)d_in[7];
    const float* mw1    = (const float*)d_in[8];
    const float* mb1    = (const float*)d_in[9];
    const float* mw2    = (const float*)d_in[10];
    const float* mb2    = (const float*)d_in[11];
    const float* fw1    = (const float*)d_in[12];
    const float* fb1    = (const float*)d_in[13];
    const float* fw2    = (const float*)d_in[14];
    const float* fb2    = (const float*)d_in[15];
    const float* fw3    = (const float*)d_in[16];
    const float* fb3    = (const float*)d_in[17];
    const float* tpw    = (const float*)d_in[18];
    float* out = (float*)d_out;

    int N = in_sizes[1];
    int E = in_sizes[3];
    float avg = (float)E / (float)N;
    float inv_avg = 1.0f / fmaxf(avg, 1e-8f);

    int nbNode = (N + 255) / 256;
    int megaBlocks = NB_CG + NB_TAB + nbNode + NB_ZERO;

    mega_init_kernel<<<megaBlocks, 256>>>(fw1, fb1, fw2, fb2, fw3, fb3, inv_avg,
                                          embt, A, mw1, mb1, mw2, mb2, N, nbNode);
    hist_kernel<<<(E + 255) / 256, 256>>>(edst, E);
    scan_kernel<<<1, SCAN_T>>>();
    scatter_kernel<<<(E + 255) / 256, 256>>>(esrc, edst, eshift, E);
    geo_kernel<<<(E + 255) / 256, 256>>>(pos, batch, cell, E);
    accum_finalize_kernel<<<(N + 7) / 8, 256>>>(tpw, out, N);
}

// round 10
// speedup vs baseline: 12.5877x; 1.1565x over previous
#include <cuda_runtime.h>
#include <cuda_fp16.h>
#include <math.h>

#define NPATHS 15
#define CG_TOTAL 615
#define MAXE 1000000
#define NPAD 53248            // 13 * 4096, >= N
#define TABN 16384            // gate table intervals over [0, 2]
#define NB_CG 15
#define NB_TAB 65             // covers TABN+1 = 16385 at 256/block
#define NB_ZERO 208           // NPAD / 256

// path tables: (l1,l2,l3) enumerated as in the reference (l1 outer, l2 mid, l3 inner)
__device__ constexpr int PL1[NPATHS]  = {0,0,0,1,1,1,1,1,1,2,2,2,2,2,2};
__device__ constexpr int PL2[NPATHS]  = {0,1,2,0,1,1,1,2,2,0,1,1,2,2,2};
__device__ constexpr int PL3[NPATHS]  = {0,1,2,1,0,1,2,1,2,2,1,2,0,1,2};
__device__ constexpr int CGO[NPATHS]  = {0,1,10,35,44,53,80,125,170,245,270,315,390,415,490};
__device__ constexpr int GEOO[NPATHS] = {0,1,4,9,12,13,16,21,24,29,34,37,42,43,46};
__device__ constexpr int LOFF[3] = {0,1,4};

__device__ float g_cg[CG_TOTAL];
__device__ __align__(16) float g_Ai[NPAD * 8];
__device__ __align__(16) __half g_AiH[(size_t)8 * MAXE];   // [m][slot], fp16
__device__ __align__(16) __half g_geoH[(size_t)52 * MAXE]; // [pj][slot], fp16; row 51 stays 0
__device__ __align__(16) float g_tab[(TABN + 1) * 16];     // gate table (alpha*inv_avg baked)
__device__ __align__(16) float4 g_edata[MAXE];             // {sx,sy,sz, bitcast(src)} per slot
__device__ int   g_dstS[MAXE];                             // dst per slot (sorted)
__device__ __align__(16) int g_count[NPAD];
__device__ __align__(16) int g_off[NPAD + 4];
__device__ __align__(16) int g_cursor[NPAD];

// ---------------------------------------------------------------------------
// CG math helpers (double precision, replicates the reference)
// ---------------------------------------------------------------------------
__device__ double dfact(int n) {
    double r = 1.0;
    for (int i = 2; i <= n; ++i) r *= (double)i;
    return r;
}

__device__ double cgc(int j1, int j2, int j3, int m1, int m2, int m3) {
    if (m1 + m2 != m3) return 0.0;
    double pre = sqrt((double)(2 * j3 + 1) * dfact(j3 + j1 - j2) * dfact(j3 - j1 + j2) *
                      dfact(j1 + j2 - j3) / dfact(j1 + j2 + j3 + 1));
    pre *= sqrt(dfact(j3 + m3) * dfact(j3 - m3) * dfact(j1 - m1) * dfact(j1 + m1) *
                dfact(j2 - m2) * dfact(j2 + m2));
    double s = 0.0;
    for (int k = 0; k <= j1 + j2 - j3; ++k) {
        int d1 = j1 + j2 - j3 - k, d2 = j1 - m1 - k, d3 = j2 + m2 - k;
        int d4 = j3 - j2 + m1 + k, d5 = j3 - j1 - m2 + k;
        if (d1 < 0 || d2 < 0 || d3 < 0 || d4 < 0 || d5 < 0) continue;
        double t = 1.0 / (dfact(k) * dfact(d1) * dfact(d2) * dfact(d3) * dfact(d4) * dfact(d5));
        s += (k & 1) ? -t : t;
    }
    return pre * s;
}

__device__ void buildq(int l, double qr[5][5], double qi[5][5]) {
    for (int a = 0; a < 5; a++)
        for (int b = 0; b < 5; b++) { qr[a][b] = 0.0; qi[a][b] = 0.0; }
    const double isq = sqrt(0.5);
    for (int m = -l; m < 0; m++) {
        qr[l + m][l - m] = isq;
        qi[l + m][l + m] = -isq;
    }
    qr[l][l] = 1.0;
    for (int m = 1; m <= l; m++) {
        double sg = (m & 1) ? -1.0 : 1.0;
        qr[l + m][l + m] = sg * isq;
        qi[l + m][l - m] = sg * isq;
    }
    if (l == 1) {
        for (int a = 0; a < 5; a++)
            for (int b = 0; b < 5; b++) {
                double r = qr[a][b], i0 = qi[a][b];
                qr[a][b] = i0;
                qi[a][b] = -r;
            }
    } else if (l == 2) {
        for (int a = 0; a < 5; a++)
            for (int b = 0; b < 5; b++) { qr[a][b] = -qr[a][b]; qi[a][b] = -qi[a][b]; }
    }
}

// ---------------------------------------------------------------------------
// Mega init kernel: CG init / gate table / node MLP / count zeroing.
// ---------------------------------------------------------------------------
__global__ void __launch_bounds__(256) mega_init_kernel(
    const float* __restrict__ fw1, const float* __restrict__ fb1,
    const float* __restrict__ fw2, const float* __restrict__ fb2,
    const float* __restrict__ fw3, const float* __restrict__ fb3,
    float inv_avg,
    const float* __restrict__ emb_table, const int* __restrict__ A,
    const float* __restrict__ mw1, const float* __restrict__ mb1,
    const float* __restrict__ mw2, const float* __restrict__ mb2,
    int N, int nbNode)
{
    __shared__ __align__(16) unsigned char sbuf[23040];
    int b = blockIdx.x;
    int tid = threadIdx.x;

    if (b < NB_CG) {
        double* q1r = (double*)(sbuf);
        double* q1i = q1r + 25;
        double* q2r = q1i + 25;
        double* q2i = q2r + 25;
        double* q3r = q2i + 25;
        double* q3i = q3r + 25;
        float* sAr = (float*)(q3i + 25);
        float* sAi = sAr + 128;
        int* sUseRe = (int*)(sAi + 128);

        int p = b;
        int l1 = PL1[p], l2 = PL2[p], l3 = PL3[p];
        int n1 = 2 * l1 + 1, n2 = 2 * l2 + 1, n3 = 2 * l3 + 1;
        int tot = n1 * n2 * n3;

        if (tid < 3) {
            double qr[5][5], qi[5][5];
            int l = (tid == 0) ? l1 : (tid == 1) ? l2 : l3;
            buildq(l, qr, qi);
            double* dr = (tid == 0) ? q1r : (tid == 1) ? q2r : q3r;
            double* di = (tid == 0) ? q1i : (tid == 1) ? q2i : q3i;
            for (int a = 0; a < 5; a++)
                for (int c = 0; c < 5; c++) { dr[a * 5 + c] = qr[a][c]; di[a * 5 + c] = qi[a][c]; }
        }
        __syncthreads();

        double ar = 0.0, ai = 0.0;
        if (tid < tot) {
            int i = tid / (n2 * n3);
            int rem = tid - i * (n2 * n3);
            int j = rem / n3;
            int k = rem - j * n3;
            for (int a = 0; a < n1; a++)
                for (int c = 0; c < n2; c++) {
                    double t12r = q1r[a * 5 + i] * q2r[c * 5 + j] - q1i[a * 5 + i] * q2i[c * 5 + j];
                    double t12i = q1r[a * 5 + i] * q2i[c * 5 + j] + q1i[a * 5 + i] * q2r[c * 5 + j];
                    if (t12r == 0.0 && t12i == 0.0) continue;
                    for (int cc = 0; cc < n3; cc++) {
                        double C = cgc(l1, l2, l3, a - l1, c - l2, cc - l3);
                        if (C == 0.0) continue;
                        double t3r = q3r[cc * 5 + k], t3i = -q3i[cc * 5 + k];
                        ar += (t12r * t3r - t12i * t3i) * C;
                        ai += (t12r * t3i + t12i * t3r) * C;
                    }
                }
        }
        if (tid < 128) {
            sAr[tid] = (tid < tot) ? (float)fabs(ar) : 0.0f;
            sAi[tid] = (tid < tot) ? (float)fabs(ai) : 0.0f;
        }
        __syncthreads();
        if (tid == 0) {
            float sr = 0.0f, si = 0.0f;
            for (int q = 0; q < tot; q++) { sr += sAr[q]; si += sAi[q]; }
            *sUseRe = (sr >= si) ? 1 : 0;
        }
        __syncthreads();
        if (tid < tot)
            g_cg[CGO[p] + tid] = (float)(*sUseRe ? ar : ai);
        return;
    }
    b -= NB_CG;

    if (b < NB_TAB) {
        float* F = (float*)sbuf;
        float* sW1 = F;
        float* sB1 = F + 512;
        float* sB2 = F + 576;
        float* sW2 = F + 640;
        float* sW3 = F + 4736;
        float* sB3 = F + 5696;

        for (int i = tid; i < 8 * 64; i += 256) sW1[i] = fw1[i];
        for (int i = tid; i < 64; i += 256) { sB1[i] = fb1[i]; sB2[i] = fb2[i]; }
        for (int i = tid; i < 64 * 64; i += 256) sW2[i] = fw2[i];
        for (int i = tid; i < 64 * NPATHS; i += 256) sW3[i] = fw3[i];
        for (int i = tid; i < NPATHS; i += 256) sB3[i] = fb3[i];
        __syncthreads();

        int idx = b * 256 + tid;
        if (idx > TABN) return;
        float len = (float)idx * (2.0f / (float)TABN);

        float emb[8];
        const float step = 2.0f / 9.0f;
        const float istep = 4.5f;
        const float cemb = 2.8284271247461903f / 1.12f;
#pragma unroll
        for (int i = 0; i < 8; i++) {
            float t = (len - (float)(i + 1) * step) * istep;
            emb[i] = __expf(-t * t) * cemb;
        }

        float h1[64];
#pragma unroll
        for (int j = 0; j < 64; j++) {
            float t = sB1[j];
#pragma unroll
            for (int i = 0; i < 8; i++) t += emb[i] * sW1[i * 64 + j];
            h1[j] = t / (1.0f + __expf(-t));
        }

        float gp[NPATHS];
#pragma unroll
        for (int p = 0; p < NPATHS; p++) gp[p] = sB3[p];
#pragma unroll 4
        for (int j = 0; j < 64; j++) {
            float t = sB2[j];
#pragma unroll
            for (int i = 0; i < 64; i++) t += h1[i] * sW2[i * 64 + j];
            float s = t / (1.0f + __expf(-t));
#pragma unroll
            for (int p = 0; p < NPATHS; p++) gp[p] += s * sW3[j * NPATHS + p];
        }

        const float ALP0 = 0.20412414523193154f;
        const float ALP1 = 0.14433756729740643f;
        float* row = g_tab + (size_t)idx * 16;
#pragma unroll
        for (int p = 0; p < NPATHS; p++) {
            float alpha = (PL3[p] == 0) ? ALP0 : ALP1;
            row[p] = gp[p] * alpha * inv_avg;
        }
        row[15] = 0.0f;
        return;
    }
    b -= NB_TAB;

    if (b < nbNode) {
        float* F = (float*)sbuf;
        float* sW1 = F;
        float* sB1 = F + 1024;
        float* sW2 = F + 1088;
        float* sB2 = F + 1600;
        float* sEmb = F + 1608;

        for (int i = tid; i < 16 * 64; i += 256) sW1[i] = mw1[i];
        for (int i = tid; i < 64; i += 256) sB1[i] = mb1[i];
        for (int i = tid; i < 64 * 8; i += 256) sW2[i] = mw2[i];
        for (int i = tid; i < 8; i += 256) sB2[i] = mb2[i];
        for (int i = tid; i < 10 * 16; i += 256) sEmb[i] = emb_table[i];
        __syncthreads();

        int n = b * 256 + tid;
        if (n >= N) return;
        int a = A[n];
        float x[16];
#pragma unroll
        for (int i = 0; i < 16; i++) x[i] = sEmb[a * 16 + i];
        float h[64];
#pragma unroll
        for (int j = 0; j < 64; j++) {
            float t = sB1[j];
#pragma unroll
            for (int i = 0; i < 16; i++) t += x[i] * sW1[i * 64 + j];
            h[j] = t / (1.0f + __expf(-t));
        }
#pragma unroll
        for (int o = 0; o < 8; o++) {
            float t = sB2[o];
#pragma unroll
            for (int j = 0; j < 64; j++) t += h[j] * sW2[j * 8 + o];
            g_Ai[n * 8 + o] = t;
        }
        return;
    }
    b -= nbNode;

    // ----- zero counts -----
    int i = b * 256 + tid;
    if (i < NPAD) g_count[i] = 0;
}

// ---------------------------------------------------------------------------
// Sorting: hist -> scan (coalesced tiled) -> scatter
// ---------------------------------------------------------------------------
__global__ void hist_kernel(const int* __restrict__ edst, int E) {
    int e = blockIdx.x * blockDim.x + threadIdx.x;
    if (e < E) atomicAdd(&g_count[edst[e]], 1);
}

// Coalesced exclusive scan: 1024 threads, int4 per thread per tile, 13 tiles.
__global__ void __launch_bounds__(1024) scan_kernel() {
    __shared__ int warpsums[32];
    __shared__ int sCarry;
    int t = threadIdx.x;
    int lane = t & 31, wid = t >> 5;
    if (t == 0) sCarry = 0;
    __syncthreads();

#pragma unroll 1
    for (int base = 0; base < NPAD; base += 4096) {
        int4 v = *(const int4*)(g_count + base + t * 4);
        int s = v.x + v.y + v.z + v.w;
        // inclusive warp scan of s
        int ss = s;
#pragma unroll
        for (int d = 1; d < 32; d <<= 1) {
            int o = __shfl_up_sync(0xffffffffu, ss, d);
            if (lane >= d) ss += o;
        }
        if (lane == 31) warpsums[wid] = ss;
        __syncthreads();
        if (wid == 0) {
            int w = warpsums[lane];
#pragma unroll
            for (int d = 1; d < 32; d <<= 1) {
                int o = __shfl_up_sync(0xffffffffu, w, d);
                if (lane >= d) w += o;
            }
            warpsums[lane] = w;
        }
        __syncthreads();
        int carry = sCarry;
        int excl = carry + (wid ? warpsums[wid - 1] : 0) + (ss - s);
        int4 o;
        o.x = excl;
        o.y = excl + v.x;
        o.z = o.y + v.y;
        o.w = o.z + v.z;
        *(int4*)(g_off + base + t * 4) = o;
        *(int4*)(g_cursor + base + t * 4) = o;
        int total = warpsums[31];
        __syncthreads();
        if (t == 0) sCarry = carry + total;
        __syncthreads();
    }
    if (t == 0) g_off[NPAD] = sCarry;
}

__global__ void scatter_kernel(const int* __restrict__ esrc,
                               const int* __restrict__ edst,
                               const float* __restrict__ eshift, int E) {
    int e = blockIdx.x * blockDim.x + threadIdx.x;
    if (e >= E) return;
    int d = edst[e];
    int s = esrc[e];
    float sx = eshift[e * 3 + 0], sy = eshift[e * 3 + 1], sz = eshift[e * 3 + 2];
    int p = atomicAdd(&g_cursor[d], 1);
    g_edata[p] = make_float4(sx, sy, sz, __int_as_float(s));
    g_dstS[p] = d;
}

// ---------------------------------------------------------------------------
// Geo kernel: 1 slot per thread, coalesced edge-record reads.
// Writes geoH[pj][slot] (fp16) and AiH[m][slot] (fp16), both coalesced.
// ---------------------------------------------------------------------------
__global__ void __launch_bounds__(256) geo_kernel(
    const float* __restrict__ pos, const int* __restrict__ batch,
    const float* __restrict__ cell, int E)
{
    __shared__ float sCG[CG_TOTAL];
    int tid = threadIdx.x;
    for (int i = tid; i < CG_TOTAL; i += 256) sCG[i] = g_cg[i];
    __syncthreads();

    int slot = blockIdx.x * 256 + tid;
    if (slot >= E) return;
    float4 rec = g_edata[slot];
    int s = __float_as_int(rec.w);
    int d = g_dstS[slot];

    // copy Ai of source into transposed slot-ordered stream [m][slot], fp16
    {
        const float4* ap = (const float4*)(g_Ai + (size_t)s * 8);
        float4 a0 = ap[0], a1 = ap[1];
        g_AiH[(size_t)0 * MAXE + slot] = __float2half_rn(a0.x);
        g_AiH[(size_t)1 * MAXE + slot] = __float2half_rn(a0.y);
        g_AiH[(size_t)2 * MAXE + slot] = __float2half_rn(a0.z);
        g_AiH[(size_t)3 * MAXE + slot] = __float2half_rn(a0.w);
        g_AiH[(size_t)4 * MAXE + slot] = __float2half_rn(a1.x);
        g_AiH[(size_t)5 * MAXE + slot] = __float2half_rn(a1.y);
        g_AiH[(size_t)6 * MAXE + slot] = __float2half_rn(a1.z);
        g_AiH[(size_t)7 * MAXE + slot] = __float2half_rn(a1.w);
    }

    int b = batch[s];
    const float* cl = cell + b * 9;
    float shx = rec.x * cl[0] + rec.y * cl[3] + rec.z * cl[6];
    float shy = rec.x * cl[1] + rec.y * cl[4] + rec.z * cl[7];
    float shz = rec.x * cl[2] + rec.y * cl[5] + rec.z * cl[8];
    float vx = pos[d * 3 + 0] - pos[s * 3 + 0] + shx;
    float vy = pos[d * 3 + 1] - pos[s * 3 + 1] + shy;
    float vz = pos[d * 3 + 2] - pos[s * 3 + 2] + shz;
    float L = sqrtf(vx * vx + vy * vy + vz * vz);
    float il = 1.0f / fmaxf(L, 1e-8f);
    float nx = vx * il, ny = vy * il, nz = vz * il;

    float Yv[9];
    const float s3 = 1.7320508075688772f;
    const float s15 = 3.872983346207417f;
    const float s5 = 2.23606797749979f;
    Yv[0] = 1.0f;
    Yv[1] = s3 * ny; Yv[2] = s3 * nz; Yv[3] = s3 * nx;
    Yv[4] = s15 * nx * ny;
    Yv[5] = s15 * ny * nz;
    Yv[6] = 0.5f * s5 * (3.0f * nz * nz - 1.0f);
    Yv[7] = s15 * nx * nz;
    Yv[8] = 0.5f * s15 * (nx * nx - ny * ny);

    // gates via table lerp (alpha * inv_avg already baked in)
    float gp[16];
    {
        float t = L * ((float)TABN / 2.0f);
        int i0 = (int)t;
        i0 = min(i0, TABN - 1);
        float f = t - (float)i0;
        const float4* t0 = (const float4*)(g_tab + (size_t)i0 * 16);
        const float4* t1 = (const float4*)(g_tab + (size_t)(i0 + 1) * 16);
#pragma unroll
        for (int q = 0; q < 4; q++) {
            float4 a = t0[q], c = t1[q];
            gp[q * 4 + 0] = a.x + f * (c.x - a.x);
            gp[q * 4 + 1] = a.y + f * (c.y - a.y);
            gp[q * 4 + 2] = a.z + f * (c.z - a.z);
            gp[q * 4 + 3] = a.w + f * (c.w - a.w);
        }
    }

    // geometry: stream scaled values out as fp16, coalesced (geoH[pj][slot])
#pragma unroll
    for (int p = 0; p < NPATHS; p++) {
        const int l1 = PL1[p], l2 = PL2[p], l3 = PL3[p];
        const int o1 = LOFF[l1], o2 = LOFF[l2];
        const int n2d = 2 * l2 + 1, n3d = 2 * l3 + 1;
#pragma unroll
        for (int k = 0; k < 2 * l3 + 1; k++) {
            float acc = 0.0f;
#pragma unroll
            for (int m = 0; m < 2 * l1 + 1; m++) {
#pragma unroll
                for (int n = 0; n < 2 * l2 + 1; n++) {
                    acc += Yv[o1 + m] * Yv[o2 + n] * sCG[CGO[p] + (m * n2d + n) * n3d + k];
                }
            }
            int j = GEOO[p] + k;
            g_geoH[(size_t)j * MAXE + slot] = __float2half_rn(acc * gp[p]);
        }
    }
}

// ---------------------------------------------------------------------------
// Accum+finalize fused: warp per node (8 nodes/block), warp-autonomous.
// fp16 inputs, fp32 accumulation; 8 edges per vector iteration.
// ---------------------------------------------------------------------------
__global__ void __launch_bounds__(256) accum_finalize_kernel(
    const float* __restrict__ tpw, float* __restrict__ out, int N)
{
    __shared__ float sS[8][416];
    __shared__ float sTP[NPATHS * 8 * 16];
    int tid = threadIdx.x;
    for (int i = tid; i < NPATHS * 8 * 16; i += 256) sTP[i] = tpw[i];
    __syncthreads();

    int warp = tid >> 5;
    int lane = tid & 31;
    int n = blockIdx.x * 8 + warp;
    int m = lane & 7;
    int q = lane >> 3;           // 0..3
    int base_pj = q * 13;        // pj 51 is a zero row (padding)
    if (n >= N) return;

    {
        int lo = g_off[n], hi = g_off[n + 1];
        const __half* aim = g_AiH + (size_t)m * MAXE;

        float acc[13];
#pragma unroll
        for (int r = 0; r < 13; r++) acc[r] = 0.0f;

        int i = lo;
        for (; i < hi && (i & 7); i++) {
            float ai0 = __half2float(aim[i]);
#pragma unroll
            for (int r = 0; r < 13; r++)
                acc[r] += ai0 * __half2float(g_geoH[(size_t)(base_pj + r) * MAXE + i]);
        }
        for (; i + 7 < hi; i += 8) {
            float4 av = *(const float4*)(aim + i);
            const __half2* ah = (const __half2*)&av;
            float af[8];
#pragma unroll
            for (int k = 0; k < 4; k++) {
                float2 f = __half22float2(ah[k]);
                af[2 * k] = f.x;
                af[2 * k + 1] = f.y;
            }
#pragma unroll
            for (int r = 0; r < 13; r++) {
                float4 gv = *(const float4*)(g_geoH + (size_t)(base_pj + r) * MAXE + i);
                const __half2* gh = (const __half2*)&gv;
#pragma unroll
                for (int k = 0; k < 4; k++) {
                    float2 gf = __half22float2(gh[k]);
                    acc[r] += af[2 * k] * gf.x + af[2 * k + 1] * gf.y;
                }
            }
        }
        for (; i < hi; i++) {
            float ai0 = __half2float(aim[i]);
#pragma unroll
            for (int r = 0; r < 13; r++)
                acc[r] += ai0 * __half2float(g_geoH[(size_t)(base_pj + r) * MAXE + i]);
        }

        float* srow = &sS[warp][m * 52 + base_pj];
#pragma unroll
        for (int r = 0; r < 13; r++) srow[r] = acc[r];
    }
    __syncwarp();

    if (lane >= 16) return;
    int c = lane;
    const float* S = sS[warp];
    float* orow = out + (size_t)n * 144;

    const int P0[3] = {0, 4, 12};
    const int G0[3] = {0, 12, 42};
    const int P1[6] = {1, 3, 5, 7, 10, 13};
    const int G1[6] = {1, 9, 13, 21, 34, 43};
    const int P2[6] = {2, 6, 8, 9, 11, 14};
    const int G2[6] = {4, 16, 24, 29, 37, 46};

    {
        float a = 0.0f;
#pragma unroll
        for (int i = 0; i < 3; i++) {
            int p = P0[i], g = G0[i];
#pragma unroll
            for (int m2 = 0; m2 < 8; m2++)
                a += sTP[(p * 8 + m2) * 16 + c] * S[m2 * 52 + g];
        }
        orow[c] = a;
    }
#pragma unroll
    for (int k = 0; k < 3; k++) {
        float a = 0.0f;
#pragma unroll
        for (int i = 0; i < 6; i++) {
            int p = P1[i], g = G1[i] + k;
#pragma unroll
            for (int m2 = 0; m2 < 8; m2++)
                a += sTP[(p * 8 + m2) * 16 + c] * S[m2 * 52 + g];
        }
        orow[16 + 3 * c + k] = a;
    }
#pragma unroll
    for (int k = 0; k < 5; k++) {
        float a = 0.0f;
#pragma unroll
        for (int i = 0; i < 6; i++) {
            int p = P2[i], g = G2[i] + k;
#pragma unroll
            for (int m2 = 0; m2 < 8; m2++)
                a += sTP[(p * 8 + m2) * 16 + c] * S[m2 * 52 + g];
        }
        orow[64 + 5 * c + k] = a;
    }
}

// ---------------------------------------------------------------------------
extern "C" void kernel_launch(void* const* d_in, const int* in_sizes, int n_in,
                              void* d_out, int out_size)
{
    const float* pos    = (const float*)d_in[0];
    const int*   A      = (const int*)d_in[1];
    const int*   batch  = (const int*)d_in[2];
    const int*   esrc   = (const int*)d_in[3];
    const int*   edst   = (const int*)d_in[4];
    const float* eshift = (const float*)d_in[5];
    const float* cell   = (const float*)d_in[6];
    const float* embt   = (const float*)d_in[7];
    const float* mw1    = (const float*)d_in[8];
    const float* mb1    = (const float*)d_in[9];
    const float* mw2    = (const float*)d_in[10];
    const float* mb2    = (const float*)d_in[11];
    const float* fw1    = (const float*)d_in[12];
    const float* fb1    = (const float*)d_in[13];
    const float* fw2    = (const float*)d_in[14];
    const float* fb2    = (const float*)d_in[15];
    const float* fw3    = (const float*)d_in[16];
    const float* fb3    = (const float*)d_in[17];
    const float* tpw    = (const float*)d_in[18];
    float* out = (float*)d_out;

    int N = in_sizes[1];
    int E = in_sizes[3];
    float avg = (float)E / (float)N;
    float inv_avg = 1.0f / fmaxf(avg, 1e-8f);

    int nbNode = (N + 255) / 256;
    int megaBlocks = NB_CG + NB_TAB + nbNode + NB_ZERO;

    mega_init_kernel<<<megaBlocks, 256>>>(fw1, fb1, fw2, fb2, fw3, fb3, inv_avg,
                                          embt, A, mw1, mb1, mw2, mb2, N, nbNode);
    hist_kernel<<<(E + 255) / 256, 256>>>(edst, E);
    scan_kernel<<<1, 1024>>>();
    scatter_kernel<<<(E + 255) / 256, 256>>>(esrc, edst, eshift, E);
    geo_kernel<<<(E + 255) / 256, 256>>>(pos, batch, cell, E);
    accum_finalize_kernel<<<(N + 7) / 8, 256>>>(tpw, out, N);
}

// round 11
// speedup vs baseline: 13.4989x; 1.0724x over previous
#include <cuda_runtime.h>
#include <cuda_fp16.h>
#include <math.h>

#define NPATHS 15
#define CG_TOTAL 615
#define MAXE 1000000
#define NPAD 53248            // 13 * 4096, >= N
#define TABN 16384            // gate table intervals over [0, 2]
#define NB_CG 15
#define NB_TAB 65             // covers TABN+1 = 16385 at 256/block

// path tables: (l1,l2,l3) enumerated as in the reference (l1 outer, l2 mid, l3 inner)
__device__ constexpr int PL1[NPATHS]  = {0,0,0,1,1,1,1,1,1,2,2,2,2,2,2};
__device__ constexpr int PL2[NPATHS]  = {0,1,2,0,1,1,1,2,2,0,1,1,2,2,2};
__device__ constexpr int PL3[NPATHS]  = {0,1,2,1,0,1,2,1,2,2,1,2,0,1,2};
__device__ constexpr int CGO[NPATHS]  = {0,1,10,35,44,53,80,125,170,245,270,315,390,415,490};
__device__ constexpr int GEOO[NPATHS] = {0,1,4,9,12,13,16,21,24,29,34,37,42,43,46};
__device__ constexpr int LOFF[3] = {0,1,4};

__device__ float g_cg[CG_TOTAL];
__device__ __align__(16) float g_Ai[NPAD * 8];
__device__ __align__(16) __half g_AiH[(size_t)8 * MAXE];   // [m][slot], fp16
__device__ __align__(16) __half g_geoH[(size_t)52 * MAXE]; // [pj][slot], fp16; row 51 stays 0
__device__ __align__(16) float g_tab[(TABN + 1) * 16];     // gate table (alpha*inv_avg baked)
__device__ __align__(16) float4 g_edata[MAXE];             // {sx,sy,sz, bitcast(src)} per slot
__device__ int   g_dstS[MAXE];                             // dst per slot (sorted)
__device__ __align__(16) int g_count[NPAD];                // zero at entry; re-zeroed by scan
__device__ __align__(16) int g_off[NPAD + 4];
__device__ __align__(16) int g_cursor[NPAD];

// ---------------------------------------------------------------------------
// CG math helpers (double precision, replicates the reference)
// ---------------------------------------------------------------------------
__device__ double dfact(int n) {
    double r = 1.0;
    for (int i = 2; i <= n; ++i) r *= (double)i;
    return r;
}

__device__ double cgc(int j1, int j2, int j3, int m1, int m2, int m3) {
    if (m1 + m2 != m3) return 0.0;
    double pre = sqrt((double)(2 * j3 + 1) * dfact(j3 + j1 - j2) * dfact(j3 - j1 + j2) *
                      dfact(j1 + j2 - j3) / dfact(j1 + j2 + j3 + 1));
    pre *= sqrt(dfact(j3 + m3) * dfact(j3 - m3) * dfact(j1 - m1) * dfact(j1 + m1) *
                dfact(j2 - m2) * dfact(j2 + m2));
    double s = 0.0;
    for (int k = 0; k <= j1 + j2 - j3; ++k) {
        int d1 = j1 + j2 - j3 - k, d2 = j1 - m1 - k, d3 = j2 + m2 - k;
        int d4 = j3 - j2 + m1 + k, d5 = j3 - j1 - m2 + k;
        if (d1 < 0 || d2 < 0 || d3 < 0 || d4 < 0 || d5 < 0) continue;
        double t = 1.0 / (dfact(k) * dfact(d1) * dfact(d2) * dfact(d3) * dfact(d4) * dfact(d5));
        s += (k & 1) ? -t : t;
    }
    return pre * s;
}

__device__ void buildq(int l, double qr[5][5], double qi[5][5]) {
    for (int a = 0; a < 5; a++)
        for (int b = 0; b < 5; b++) { qr[a][b] = 0.0; qi[a][b] = 0.0; }
    const double isq = sqrt(0.5);
    for (int m = -l; m < 0; m++) {
        qr[l + m][l - m] = isq;
        qi[l + m][l + m] = -isq;
    }
    qr[l][l] = 1.0;
    for (int m = 1; m <= l; m++) {
        double sg = (m & 1) ? -1.0 : 1.0;
        qr[l + m][l + m] = sg * isq;
        qi[l + m][l - m] = sg * isq;
    }
    if (l == 1) {
        for (int a = 0; a < 5; a++)
            for (int b = 0; b < 5; b++) {
                double r = qr[a][b], i0 = qi[a][b];
                qr[a][b] = i0;
                qi[a][b] = -r;
            }
    } else if (l == 2) {
        for (int a = 0; a < 5; a++)
            for (int b = 0; b < 5; b++) { qr[a][b] = -qr[a][b]; qi[a][b] = -qi[a][b]; }
    }
}

// ---------------------------------------------------------------------------
// Mega init kernel: CG init / gate table / node MLP / edge histogram.
// g_count enters zeroed (initial static zero-init; re-zeroed by scan_kernel).
// ---------------------------------------------------------------------------
__global__ void __launch_bounds__(256) mega_init_kernel(
    const float* __restrict__ fw1, const float* __restrict__ fb1,
    const float* __restrict__ fw2, const float* __restrict__ fb2,
    const float* __restrict__ fw3, const float* __restrict__ fb3,
    float inv_avg,
    const float* __restrict__ emb_table, const int* __restrict__ A,
    const float* __restrict__ mw1, const float* __restrict__ mb1,
    const float* __restrict__ mw2, const float* __restrict__ mb2,
    const int* __restrict__ edst,
    int N, int E, int nbNode)
{
    __shared__ __align__(16) unsigned char sbuf[23040];
    int b = blockIdx.x;
    int tid = threadIdx.x;

    if (b < NB_CG) {
        double* q1r = (double*)(sbuf);
        double* q1i = q1r + 25;
        double* q2r = q1i + 25;
        double* q2i = q2r + 25;
        double* q3r = q2i + 25;
        double* q3i = q3r + 25;
        float* sAr = (float*)(q3i + 25);
        float* sAi = sAr + 128;
        int* sUseRe = (int*)(sAi + 128);

        int p = b;
        int l1 = PL1[p], l2 = PL2[p], l3 = PL3[p];
        int n1 = 2 * l1 + 1, n2 = 2 * l2 + 1, n3 = 2 * l3 + 1;
        int tot = n1 * n2 * n3;

        if (tid < 3) {
            double qr[5][5], qi[5][5];
            int l = (tid == 0) ? l1 : (tid == 1) ? l2 : l3;
            buildq(l, qr, qi);
            double* dr = (tid == 0) ? q1r : (tid == 1) ? q2r : q3r;
            double* di = (tid == 0) ? q1i : (tid == 1) ? q2i : q3i;
            for (int a = 0; a < 5; a++)
                for (int c = 0; c < 5; c++) { dr[a * 5 + c] = qr[a][c]; di[a * 5 + c] = qi[a][c]; }
        }
        __syncthreads();

        double ar = 0.0, ai = 0.0;
        if (tid < tot) {
            int i = tid / (n2 * n3);
            int rem = tid - i * (n2 * n3);
            int j = rem / n3;
            int k = rem - j * n3;
            for (int a = 0; a < n1; a++)
                for (int c = 0; c < n2; c++) {
                    double t12r = q1r[a * 5 + i] * q2r[c * 5 + j] - q1i[a * 5 + i] * q2i[c * 5 + j];
                    double t12i = q1r[a * 5 + i] * q2i[c * 5 + j] + q1i[a * 5 + i] * q2r[c * 5 + j];
                    if (t12r == 0.0 && t12i == 0.0) continue;
                    for (int cc = 0; cc < n3; cc++) {
                        double C = cgc(l1, l2, l3, a - l1, c - l2, cc - l3);
                        if (C == 0.0) continue;
                        double t3r = q3r[cc * 5 + k], t3i = -q3i[cc * 5 + k];
                        ar += (t12r * t3r - t12i * t3i) * C;
                        ai += (t12r * t3i + t12i * t3r) * C;
                    }
                }
        }
        if (tid < 128) {
            sAr[tid] = (tid < tot) ? (float)fabs(ar) : 0.0f;
            sAi[tid] = (tid < tot) ? (float)fabs(ai) : 0.0f;
        }
        __syncthreads();
        if (tid == 0) {
            float sr = 0.0f, si = 0.0f;
            for (int q = 0; q < tot; q++) { sr += sAr[q]; si += sAi[q]; }
            *sUseRe = (sr >= si) ? 1 : 0;
        }
        __syncthreads();
        if (tid < tot)
            g_cg[CGO[p] + tid] = (float)(*sUseRe ? ar : ai);
        return;
    }
    b -= NB_CG;

    if (b < NB_TAB) {
        float* F = (float*)sbuf;
        float* sW1 = F;
        float* sB1 = F + 512;
        float* sB2 = F + 576;
        float* sW2 = F + 640;
        float* sW3 = F + 4736;
        float* sB3 = F + 5696;

        for (int i = tid; i < 8 * 64; i += 256) sW1[i] = fw1[i];
        for (int i = tid; i < 64; i += 256) { sB1[i] = fb1[i]; sB2[i] = fb2[i]; }
        for (int i = tid; i < 64 * 64; i += 256) sW2[i] = fw2[i];
        for (int i = tid; i < 64 * NPATHS; i += 256) sW3[i] = fw3[i];
        for (int i = tid; i < NPATHS; i += 256) sB3[i] = fb3[i];
        __syncthreads();

        int idx = b * 256 + tid;
        if (idx > TABN) return;
        float len = (float)idx * (2.0f / (float)TABN);

        float emb[8];
        const float step = 2.0f / 9.0f;
        const float istep = 4.5f;
        const float cemb = 2.8284271247461903f / 1.12f;
#pragma unroll
        for (int i = 0; i < 8; i++) {
            float t = (len - (float)(i + 1) * step) * istep;
            emb[i] = __expf(-t * t) * cemb;
        }

        float h1[64];
#pragma unroll
        for (int j = 0; j < 64; j++) {
            float t = sB1[j];
#pragma unroll
            for (int i = 0; i < 8; i++) t += emb[i] * sW1[i * 64 + j];
            h1[j] = t / (1.0f + __expf(-t));
        }

        float gp[NPATHS];
#pragma unroll
        for (int p = 0; p < NPATHS; p++) gp[p] = sB3[p];
#pragma unroll 4
        for (int j = 0; j < 64; j++) {
            float t = sB2[j];
#pragma unroll
            for (int i = 0; i < 64; i++) t += h1[i] * sW2[i * 64 + j];
            float s = t / (1.0f + __expf(-t));
#pragma unroll
            for (int p = 0; p < NPATHS; p++) gp[p] += s * sW3[j * NPATHS + p];
        }

        const float ALP0 = 0.20412414523193154f;
        const float ALP1 = 0.14433756729740643f;
        float* row = g_tab + (size_t)idx * 16;
#pragma unroll
        for (int p = 0; p < NPATHS; p++) {
            float alpha = (PL3[p] == 0) ? ALP0 : ALP1;
            row[p] = gp[p] * alpha * inv_avg;
        }
        row[15] = 0.0f;
        return;
    }
    b -= NB_TAB;

    if (b < nbNode) {
        float* F = (float*)sbuf;
        float* sW1 = F;
        float* sB1 = F + 1024;
        float* sW2 = F + 1088;
        float* sB2 = F + 1600;
        float* sEmb = F + 1608;

        for (int i = tid; i < 16 * 64; i += 256) sW1[i] = mw1[i];
        for (int i = tid; i < 64; i += 256) sB1[i] = mb1[i];
        for (int i = tid; i < 64 * 8; i += 256) sW2[i] = mw2[i];
        for (int i = tid; i < 8; i += 256) sB2[i] = mb2[i];
        for (int i = tid; i < 10 * 16; i += 256) sEmb[i] = emb_table[i];
        __syncthreads();

        int n = b * 256 + tid;
        if (n >= N) return;
        int a = A[n];
        float x[16];
#pragma unroll
        for (int i = 0; i < 16; i++) x[i] = sEmb[a * 16 + i];
        float h[64];
#pragma unroll
        for (int j = 0; j < 64; j++) {
            float t = sB1[j];
#pragma unroll
            for (int i = 0; i < 16; i++) t += x[i] * sW1[i * 64 + j];
            h[j] = t / (1.0f + __expf(-t));
        }
#pragma unroll
        for (int o = 0; o < 8; o++) {
            float t = sB2[o];
#pragma unroll
            for (int j = 0; j < 64; j++) t += h[j] * sW2[j * 8 + o];
            g_Ai[n * 8 + o] = t;
        }
        return;
    }
    b -= nbNode;

    // ----- edge histogram (counts pre-zeroed) -----
    int e = b * 256 + tid;
    if (e < E) atomicAdd(&g_count[edst[e]], 1);
}

// ---------------------------------------------------------------------------
// Coalesced exclusive scan: 1024 threads, int4 per thread per tile, 13 tiles.
// Also re-zeros g_count for the next graph replay.
// ---------------------------------------------------------------------------
__global__ void __launch_bounds__(1024) scan_kernel() {
    __shared__ int warpsums[32];
    __shared__ int sCarry;
    int t = threadIdx.x;
    int lane = t & 31, wid = t >> 5;
    if (t == 0) sCarry = 0;
    __syncthreads();

#pragma unroll 1
    for (int base = 0; base < NPAD; base += 4096) {
        int4 v = *(const int4*)(g_count + base + t * 4);
        *(int4*)(g_count + base + t * 4) = make_int4(0, 0, 0, 0);  // re-zero for next replay
        int s = v.x + v.y + v.z + v.w;
        int ss = s;
#pragma unroll
        for (int d = 1; d < 32; d <<= 1) {
            int o = __shfl_up_sync(0xffffffffu, ss, d);
            if (lane >= d) ss += o;
        }
        if (lane == 31) warpsums[wid] = ss;
        __syncthreads();
        if (wid == 0) {
            int w = warpsums[lane];
#pragma unroll
            for (int d = 1; d < 32; d <<= 1) {
                int o = __shfl_up_sync(0xffffffffu, w, d);
                if (lane >= d) w += o;
            }
            warpsums[lane] = w;
        }
        __syncthreads();
        int carry = sCarry;
        int excl = carry + (wid ? warpsums[wid - 1] : 0) + (ss - s);
        int4 o;
        o.x = excl;
        o.y = excl + v.x;
        o.z = o.y + v.y;
        o.w = o.z + v.z;
        *(int4*)(g_off + base + t * 4) = o;
        *(int4*)(g_cursor + base + t * 4) = o;
        int total = warpsums[31];
        __syncthreads();
        if (t == 0) sCarry = carry + total;
        __syncthreads();
    }
    if (t == 0) g_off[NPAD] = sCarry;
}

__global__ void scatter_kernel(const int* __restrict__ esrc,
                               const int* __restrict__ edst,
                               const float* __restrict__ eshift, int E) {
    int e = blockIdx.x * blockDim.x + threadIdx.x;
    if (e >= E) return;
    int d = edst[e];
    int s = esrc[e];
    float sx = eshift[e * 3 + 0], sy = eshift[e * 3 + 1], sz = eshift[e * 3 + 2];
    int p = atomicAdd(&g_cursor[d], 1);
    g_edata[p] = make_float4(sx, sy, sz, __int_as_float(s));
    g_dstS[p] = d;
}

// ---------------------------------------------------------------------------
// Geo kernel: 1 slot per thread. Yv products hoisted out of the k-loop.
// Writes geoH[pj][slot] (fp16) and AiH[m][slot] (fp16), both coalesced.
// ---------------------------------------------------------------------------
__global__ void __launch_bounds__(256) geo_kernel(
    const float* __restrict__ pos, const int* __restrict__ batch,
    const float* __restrict__ cell, int E)
{
    __shared__ float sCG[CG_TOTAL];
    int tid = threadIdx.x;
    for (int i = tid; i < CG_TOTAL; i += 256) sCG[i] = g_cg[i];
    __syncthreads();

    int slot = blockIdx.x * 256 + tid;
    if (slot >= E) return;
    float4 rec = g_edata[slot];
    int s = __float_as_int(rec.w);
    int d = g_dstS[slot];

    {
        const float4* ap = (const float4*)(g_Ai + (size_t)s * 8);
        float4 a0 = ap[0], a1 = ap[1];
        g_AiH[(size_t)0 * MAXE + slot] = __float2half_rn(a0.x);
        g_AiH[(size_t)1 * MAXE + slot] = __float2half_rn(a0.y);
        g_AiH[(size_t)2 * MAXE + slot] = __float2half_rn(a0.z);
        g_AiH[(size_t)3 * MAXE + slot] = __float2half_rn(a0.w);
        g_AiH[(size_t)4 * MAXE + slot] = __float2half_rn(a1.x);
        g_AiH[(size_t)5 * MAXE + slot] = __float2half_rn(a1.y);
        g_AiH[(size_t)6 * MAXE + slot] = __float2half_rn(a1.z);
        g_AiH[(size_t)7 * MAXE + slot] = __float2half_rn(a1.w);
    }

    int b = batch[s];
    const float* cl = cell + b * 9;
    float shx = rec.x * cl[0] + rec.y * cl[3] + rec.z * cl[6];
    float shy = rec.x * cl[1] + rec.y * cl[4] + rec.z * cl[7];
    float shz = rec.x * cl[2] + rec.y * cl[5] + rec.z * cl[8];
    float vx = pos[d * 3 + 0] - pos[s * 3 + 0] + shx;
    float vy = pos[d * 3 + 1] - pos[s * 3 + 1] + shy;
    float vz = pos[d * 3 + 2] - pos[s * 3 + 2] + shz;
    float L = sqrtf(vx * vx + vy * vy + vz * vz);
    float il = 1.0f / fmaxf(L, 1e-8f);
    float nx = vx * il, ny = vy * il, nz = vz * il;

    float Yv[9];
    const float s3 = 1.7320508075688772f;
    const float s15 = 3.872983346207417f;
    const float s5 = 2.23606797749979f;
    Yv[0] = 1.0f;
    Yv[1] = s3 * ny; Yv[2] = s3 * nz; Yv[3] = s3 * nx;
    Yv[4] = s15 * nx * ny;
    Yv[5] = s15 * ny * nz;
    Yv[6] = 0.5f * s5 * (3.0f * nz * nz - 1.0f);
    Yv[7] = s15 * nx * nz;
    Yv[8] = 0.5f * s15 * (nx * nx - ny * ny);

    // gates via table lerp (alpha * inv_avg already baked in)
    float gp[16];
    {
        float t = L * ((float)TABN / 2.0f);
        int i0 = (int)t;
        i0 = min(i0, TABN - 1);
        float f = t - (float)i0;
        const float4* t0 = (const float4*)(g_tab + (size_t)i0 * 16);
        const float4* t1 = (const float4*)(g_tab + (size_t)(i0 + 1) * 16);
#pragma unroll
        for (int q = 0; q < 4; q++) {
            float4 a = t0[q], c = t1[q];
            gp[q * 4 + 0] = a.x + f * (c.x - a.x);
            gp[q * 4 + 1] = a.y + f * (c.y - a.y);
            gp[q * 4 + 2] = a.z + f * (c.z - a.z);
            gp[q * 4 + 3] = a.w + f * (c.w - a.w);
        }
    }

    // geometry: per path, m/n outer with hoisted Yv product, k inner.
#pragma unroll
    for (int p = 0; p < NPATHS; p++) {
        const int l1 = PL1[p], l2 = PL2[p], l3 = PL3[p];
        const int o1 = LOFF[l1], o2 = LOFF[l2];
        const int n2d = 2 * l2 + 1, n3d = 2 * l3 + 1;
        float acc[5];
#pragma unroll
        for (int k = 0; k < 5; k++) acc[k] = 0.0f;
#pragma unroll
        for (int m = 0; m < 2 * l1 + 1; m++) {
#pragma unroll
            for (int n = 0; n < 2 * l2 + 1; n++) {
                float t = Yv[o1 + m] * Yv[o2 + n];
#pragma unroll
                for (int k = 0; k < 2 * l3 + 1; k++)
                    acc[k] += t * sCG[CGO[p] + (m * n2d + n) * n3d + k];
            }
        }
#pragma unroll
        for (int k = 0; k < 2 * l3 + 1; k++)
            g_geoH[(size_t)(GEOO[p] + k) * MAXE + slot] = __float2half_rn(acc[k] * gp[p]);
    }
}

// ---------------------------------------------------------------------------
// Accum+finalize fused: warp per node (8 nodes/block), warp-autonomous.
// fp16 inputs, fp32 accumulation; 8 edges per vector iteration.
// ---------------------------------------------------------------------------
__global__ void __launch_bounds__(256) accum_finalize_kernel(
    const float* __restrict__ tpw, float* __restrict__ out, int N)
{
    __shared__ float sS[8][416];
    __shared__ float sTP[NPATHS * 8 * 16];
    int tid = threadIdx.x;
    for (int i = tid; i < NPATHS * 8 * 16; i += 256) sTP[i] = tpw[i];
    __syncthreads();

    int warp = tid >> 5;
    int lane = tid & 31;
    int n = blockIdx.x * 8 + warp;
    int m = lane & 7;
    int q = lane >> 3;           // 0..3
    int base_pj = q * 13;        // pj 51 is a zero row (padding)
    if (n >= N) return;

    {
        int lo = g_off[n], hi = g_off[n + 1];
        const __half* aim = g_AiH + (size_t)m * MAXE;

        float acc[13];
#pragma unroll
        for (int r = 0; r < 13; r++) acc[r] = 0.0f;

        int i = lo;
        for (; i < hi && (i & 7); i++) {
            float ai0 = __half2float(aim[i]);
#pragma unroll
            for (int r = 0; r < 13; r++)
                acc[r] += ai0 * __half2float(g_geoH[(size_t)(base_pj + r) * MAXE + i]);
        }
        for (; i + 7 < hi; i += 8) {
            float4 av = *(const float4*)(aim + i);
            const __half2* ah = (const __half2*)&av;
            float af[8];
#pragma unroll
            for (int k = 0; k < 4; k++) {
                float2 f = __half22float2(ah[k]);
                af[2 * k] = f.x;
                af[2 * k + 1] = f.y;
            }
#pragma unroll
            for (int r = 0; r < 13; r++) {
                float4 gv = *(const float4*)(g_geoH + (size_t)(base_pj + r) * MAXE + i);
                const __half2* gh = (const __half2*)&gv;
#pragma unroll
                for (int k = 0; k < 4; k++) {
                    float2 gf = __half22float2(gh[k]);
                    acc[r] += af[2 * k] * gf.x + af[2 * k + 1] * gf.y;
                }
            }
        }
        for (; i < hi; i++) {
            float ai0 = __half2float(aim[i]);
#pragma unroll
            for (int r = 0; r < 13; r++)
                acc[r] += ai0 * __half2float(g_geoH[(size_t)(base_pj + r) * MAXE + i]);
        }

        float* srow = &sS[warp][m * 52 + base_pj];
#pragma unroll
        for (int r = 0; r < 13; r++) srow[r] = acc[r];
    }
    __syncwarp();

    if (lane >= 16) return;
    int c = lane;
    const float* S = sS[warp];
    float* orow = out + (size_t)n * 144;

    const int P0[3] = {0, 4, 12};
    const int G0[3] = {0, 12, 42};
    const int P1[6] = {1, 3, 5, 7, 10, 13};
    const int G1[6] = {1, 9, 13, 21, 34, 43};
    const int P2[6] = {2, 6, 8, 9, 11, 14};
    const int G2[6] = {4, 16, 24, 29, 37, 46};

    {
        float a = 0.0f;
#pragma unroll
        for (int i = 0; i < 3; i++) {
            int p = P0[i], g = G0[i];
#pragma unroll
            for (int m2 = 0; m2 < 8; m2++)
                a += sTP[(p * 8 + m2) * 16 + c] * S[m2 * 52 + g];
        }
        orow[c] = a;
    }
#pragma unroll
    for (int k = 0; k < 3; k++) {
        float a = 0.0f;
#pragma unroll
        for (int i = 0; i < 6; i++) {
            int p = P1[i], g = G1[i] + k;
#pragma unroll
            for (int m2 = 0; m2 < 8; m2++)
                a += sTP[(p * 8 + m2) * 16 + c] * S[m2 * 52 + g];
        }
        orow[16 + 3 * c + k] = a;
    }
#pragma unroll
    for (int k = 0; k < 5; k++) {
        float a = 0.0f;
#pragma unroll
        for (int i = 0; i < 6; i++) {
            int p = P2[i], g = G2[i] + k;
#pragma unroll
            for (int m2 = 0; m2 < 8; m2++)
                a += sTP[(p * 8 + m2) * 16 + c] * S[m2 * 52 + g];
        }
        orow[64 + 5 * c + k] = a;
    }
}

// ---------------------------------------------------------------------------
extern "C" void kernel_launch(void* const* d_in, const int* in_sizes, int n_in,
                              void* d_out, int out_size)
{
    const float* pos    = (const float*)d_in[0];
    const int*   A      = (const int*)d_in[1];
    const int*   batch  = (const int*)d_in[2];
    const int*   esrc   = (const int*)d_in[3];
    const int*   edst   = (const int*)d_in[4];
    const float* eshift = (const float*)d_in[5];
    const float* cell   = (const float*)d_in[6];
    const float* embt   = (const float*)d_in[7];
    const float* mw1    = (const float*)d_in[8];
    const float* mb1    = (const float*)d_in[9];
    const float* mw2    = (const float*)d_in[10];
    const float* mb2    = (const float*)d_in[11];
    const float* fw1    = (const float*)d_in[12];
    const float* fb1    = (const float*)d_in[13];
    const float* fw2    = (const float*)d_in[14];
    const float* fb2    = (const float*)d_in[15];
    const float* fw3    = (const float*)d_in[16];
    const float* fb3    = (const float*)d_in[17];
    const float* tpw    = (const float*)d_in[18];
    float* out = (float*)d_out;

    int N = in_sizes[1];
    int E = in_sizes[3];
    float avg = (float)E / (float)N;
    float inv_avg = 1.0f / fmaxf(avg, 1e-8f);

    int nbNode = (N + 255) / 256;
    int nbHist = (E + 255) / 256;
    int megaBlocks = NB_CG + NB_TAB + nbNode + nbHist;

    mega_init_kernel<<<megaBlocks, 256>>>(fw1, fb1, fw2, fb2, fw3, fb3, inv_avg,
                                          embt, A, mw1, mb1, mw2, mb2, edst,
                                          N, E, nbNode);
    scan_kernel<<<1, 1024>>>();
    scatter_kernel<<<(E + 255) / 256, 256>>>(esrc, edst, eshift, E);
    geo_kernel<<<(E + 255) / 256, 256>>>(pos, batch, cell, E);
    accum_finalize_kernel<<<(N + 7) / 8, 256>>>(tpw, out, N);
}